// round 3
// baseline (speedup 1.0000x reference)
#include <cuda_runtime.h>
#include <math.h>

#define B_ 2
#define S_ 2048
#define D_ 1024
#define H_ 16
#define DH_ 64
#define DR_ 64
#define DL_ 512
#define DHID_ 512
#define NR_ 8
#define NS_ 2
#define T_ (B_*S_)          // 4096 tokens
#define QDIM_ (DH_+DR_)     // 128

// ---------------- scratch (device globals; no allocation allowed) ----------
__device__ float g_h  [T_*D_];          // rmsnorm(x)
__device__ float g_q  [T_*H_*QDIM_];    // q (B,S,H,128), rope applied in-place
__device__ float g_lat[T_*DL_];
__device__ float g_kc [T_*H_*DH_];
__device__ float g_v  [T_*H_*DH_];
__device__ float g_kr [T_*DR_];
__device__ float g_ctx[T_*H_*DH_];
__device__ float g_h2 [T_*D_];
__device__ float g_gb [T_*DHID_];
__device__ float g_ub [T_*DHID_];
__device__ int   g_cnt[NR_];
__device__ int   g_elist[NR_*T_];
__device__ float g_ew  [NR_*T_];

// ---------------- rmsnorm --------------------------------------------------
__global__ void rmsnorm_k(const float* __restrict__ x, const float* __restrict__ w,
                          float* __restrict__ o) {
    int row = blockIdx.x;
    const float* xr = x + (size_t)row * D_;
    float ss = 0.f;
    float vloc[4];
#pragma unroll
    for (int i = 0; i < 4; i++) { vloc[i] = xr[threadIdx.x + i*256]; ss += vloc[i]*vloc[i]; }
#pragma unroll
    for (int off = 16; off; off >>= 1) ss += __shfl_xor_sync(0xffffffffu, ss, off);
    __shared__ float sm[8];
    __shared__ float invs;
    if ((threadIdx.x & 31) == 0) sm[threadIdx.x >> 5] = ss;
    __syncthreads();
    if (threadIdx.x == 0) {
        float t = 0.f;
#pragma unroll
        for (int i = 0; i < 8; i++) t += sm[i];
        invs = 1.0f / sqrtf(t / (float)D_ + 1e-6f);
    }
    __syncthreads();
    float inv = invs;
    float* orow = o + (size_t)row * D_;
#pragma unroll
    for (int i = 0; i < 4; i++) {
        int d = threadIdx.x + i*256;
        orow[d] = vloc[i] * inv * w[d];
    }
}

// ---------------- generic tiled SGEMM (row-major, full 64/16 tiles) --------
template<bool ACC>
__global__ void sgemm64(const float* __restrict__ A, const float* __restrict__ Bm,
                        float* __restrict__ C, int N, int K) {
    __shared__ float As[16][64];
    __shared__ float Bs[16][64];
    int tid = threadIdx.x;
    int bx = blockIdx.x, by = blockIdx.y;
    int tx = tid & 15, ty = tid >> 4;
    float acc[4][4];
#pragma unroll
    for (int i = 0; i < 4; i++)
#pragma unroll
        for (int j = 0; j < 4; j++) acc[i][j] = 0.f;

    int aRow = tid >> 2;          // 0..63
    int aCol = (tid & 3) * 4;     // 0,4,8,12
    const float* Aptr = A + (size_t)(by*64 + aRow) * K + aCol;
    int bRow = tid >> 4;          // 0..15
    int bCol = (tid & 15) * 4;
    const float* Bptr = Bm + (size_t)bRow * N + bx*64 + bCol;

    for (int k0 = 0; k0 < K; k0 += 16) {
        float4 av = *(const float4*)Aptr;
        float4 bv = *(const float4*)Bptr;
        As[aCol+0][aRow] = av.x; As[aCol+1][aRow] = av.y;
        As[aCol+2][aRow] = av.z; As[aCol+3][aRow] = av.w;
        *(float4*)&Bs[bRow][bCol] = bv;
        __syncthreads();
#pragma unroll
        for (int k = 0; k < 16; k++) {
            float4 a4 = *(const float4*)&As[k][ty*4];
            float4 b4 = *(const float4*)&Bs[k][tx*4];
            float ar[4] = {a4.x, a4.y, a4.z, a4.w};
            float br[4] = {b4.x, b4.y, b4.z, b4.w};
#pragma unroll
            for (int i = 0; i < 4; i++)
#pragma unroll
                for (int j = 0; j < 4; j++) acc[i][j] += ar[i]*br[j];
        }
        __syncthreads();
        Aptr += 16;
        Bptr += (size_t)16 * N;
    }
#pragma unroll
    for (int i = 0; i < 4; i++) {
        float* cp = C + (size_t)(by*64 + ty*4 + i) * N + bx*64 + tx*4;
#pragma unroll
        for (int j = 0; j < 4; j++) {
            if (ACC) cp[j] += acc[i][j]; else cp[j] = acc[i][j];
        }
    }
}

// ------- expert GEMM: optional row-gather on A, optional scatter+scale out --
template<bool GATHER, bool SCATTER>
__global__ void egemm64(const float* __restrict__ A, const float* __restrict__ Bm,
                        float* __restrict__ C, const int* __restrict__ idx,
                        const float* __restrict__ wts, const int* __restrict__ cntPtr,
                        int N, int K) {
    int cnt = *cntPtr;
    int by = blockIdx.y;
    if (by*64 >= cnt) return;
    __shared__ float As[16][64];
    __shared__ float Bs[16][64];
    int tid = threadIdx.x;
    int bx = blockIdx.x;
    int tx = tid & 15, ty = tid >> 4;
    float acc[4][4];
#pragma unroll
    for (int i = 0; i < 4; i++)
#pragma unroll
        for (int j = 0; j < 4; j++) acc[i][j] = 0.f;

    int aRow = tid >> 2;
    int aCol = (tid & 3) * 4;
    int r = by*64 + aRow;
    int rs = (r < cnt) ? r : (cnt - 1);
    int asrc = GATHER ? idx[rs] : rs;
    const float* Aptr = A + (size_t)asrc * K + aCol;
    int bRow = tid >> 4;
    int bCol = (tid & 15) * 4;
    const float* Bptr = Bm + (size_t)bRow * N + bx*64 + bCol;

    for (int k0 = 0; k0 < K; k0 += 16) {
        float4 av = *(const float4*)Aptr;
        float4 bv = *(const float4*)Bptr;
        As[aCol+0][aRow] = av.x; As[aCol+1][aRow] = av.y;
        As[aCol+2][aRow] = av.z; As[aCol+3][aRow] = av.w;
        *(float4*)&Bs[bRow][bCol] = bv;
        __syncthreads();
#pragma unroll
        for (int k = 0; k < 16; k++) {
            float4 a4 = *(const float4*)&As[k][ty*4];
            float4 b4 = *(const float4*)&Bs[k][tx*4];
            float ar[4] = {a4.x, a4.y, a4.z, a4.w};
            float br[4] = {b4.x, b4.y, b4.z, b4.w};
#pragma unroll
            for (int i = 0; i < 4; i++)
#pragma unroll
                for (int j = 0; j < 4; j++) acc[i][j] += ar[i]*br[j];
        }
        __syncthreads();
        Aptr += 16;
        Bptr += (size_t)16 * N;
    }
#pragma unroll
    for (int i = 0; i < 4; i++) {
        int rr = by*64 + ty*4 + i;
        if (rr >= cnt) continue;
        if (SCATTER) {
            float w = wts[rr];
            int orow = idx[rr];
            float* cp = C + (size_t)orow * N + bx*64 + tx*4;
#pragma unroll
            for (int j = 0; j < 4; j++) cp[j] += w * acc[i][j];
        } else {
            float* cp = C + (size_t)rr * N + bx*64 + tx*4;
#pragma unroll
            for (int j = 0; j < 4; j++) cp[j] = acc[i][j];
        }
    }
}

// ---------------- RoPE (in-place on q tail + k_r) --------------------------
__global__ void rope_k(float* __restrict__ q, float* __restrict__ kr) {
    int p = blockIdx.x * blockDim.x + threadIdx.x;
    const int NQ = T_ * H_ * 32;
    const int NK = T_ * 32;
    if (p < NQ) {
        int i = p & 31;
        int h = (p >> 5) & (H_ - 1);
        int t = p >> 9;
        int s = t & (S_ - 1);
        float inv = powf(10000.0f, -(float)i / 32.0f);
        float sn, c;
        sincosf((float)s * inv, &sn, &c);
        float* base = q + (size_t)t * (H_*QDIM_) + h * QDIM_ + DH_;
        float t1 = base[i], t2 = base[32 + i];
        base[i]      = t1 * c - t2 * sn;
        base[32 + i] = t2 * c + t1 * sn;
    } else if (p < NQ + NK) {
        int p2 = p - NQ;
        int i = p2 & 31;
        int t = p2 >> 5;
        int s = t & (S_ - 1);
        float inv = powf(10000.0f, -(float)i / 32.0f);
        float sn, c;
        sincosf((float)s * inv, &sn, &c);
        float* base = kr + (size_t)t * DR_;
        float t1 = base[i], t2 = base[32 + i];
        base[i]      = t1 * c - t2 * sn;
        base[32 + i] = t2 * c + t1 * sn;
    }
}

// ---------------- flash attention (causal, d=128, dv=64) -------------------
// grid: (S/32, B*H), 128 threads. Thread t: q-row = t/4, col-group = t%4.
__global__ __launch_bounds__(128) void flash_attn_k(
        const float* __restrict__ q, const float* __restrict__ kc,
        const float* __restrict__ kr, const float* __restrict__ v,
        float* __restrict__ ctx) {
    __shared__ float qs[32][129];
    __shared__ float ks[64][33];
    __shared__ float vs[64][65];
    int qb = blockIdx.x;
    int bh = blockIdx.y;
    int b = bh / H_, h = bh % H_;
    int tid = threadIdx.x;
    int row = tid >> 2;
    int qi = tid & 3;
    int qrow_g = qb*32 + row;
    size_t tq = (size_t)b*S_ + qb*32;

#pragma unroll
    for (int i = 0; i < 32; i++) {
        int e = i*128 + tid;
        int r = e >> 7, d = e & 127;
        qs[r][d] = q[(tq + r) * (H_*QDIM_) + h*QDIM_ + d];
    }

    float m = -1e30f, l = 0.f;
    float o[64];
#pragma unroll
    for (int dv = 0; dv < 64; dv++) o[dv] = 0.f;

    int nkb = (qb*32 + 31) / 64 + 1;
    for (int kb = 0; kb < nkb; kb++) {
        size_t tk = (size_t)b*S_ + kb*64;
        float s[16];
#pragma unroll
        for (int j = 0; j < 16; j++) s[j] = 0.f;

        for (int c = 0; c < 4; c++) {
            __syncthreads();
#pragma unroll
            for (int i = 0; i < 16; i++) {          // K chunk 64x32
                int e = i*128 + tid;
                int r = e >> 5, dd = e & 31;
                float kv;
                if (c < 2) kv = kc[(tk + r) * (H_*DH_) + h*DH_ + c*32 + dd];
                else       kv = kr[(tk + r) * DR_ + (c-2)*32 + dd];
                ks[r][dd] = kv;
            }
#pragma unroll
            for (int i = 0; i < 8; i++) {           // V quarter
                int e = c*1024 + i*128 + tid;
                int r = e >> 6, dv = e & 63;
                vs[r][dv] = v[(tk + r) * (H_*DH_) + h*DH_ + dv];
            }
            __syncthreads();
#pragma unroll 8
            for (int dd = 0; dd < 32; dd++) {
                float qv = qs[row][c*32 + dd];
#pragma unroll
                for (int j = 0; j < 16; j++) s[j] += qv * ks[qi + 4*j][dd];
            }
        }

        const float scale = 0.088388347648318447f;  // 1/sqrt(128)
        bool last = (kb == nkb - 1);
#pragma unroll
        for (int j = 0; j < 16; j++) {
            s[j] *= scale;
            if (last) {
                int key_g = kb*64 + qi + 4*j;
                if (key_g > qrow_g) s[j] = -1e9f;
            }
        }
        float mt = s[0];
#pragma unroll
        for (int j = 1; j < 16; j++) mt = fmaxf(mt, s[j]);
        mt = fmaxf(mt, __shfl_xor_sync(0xffffffffu, mt, 1));
        mt = fmaxf(mt, __shfl_xor_sync(0xffffffffu, mt, 2));
        float mnew = fmaxf(m, mt);
        float alpha = __expf(m - mnew);
        float p[16];
        float psum = 0.f;
#pragma unroll
        for (int j = 0; j < 16; j++) { p[j] = __expf(s[j] - mnew); psum += p[j]; }
        psum += __shfl_xor_sync(0xffffffffu, psum, 1);
        psum += __shfl_xor_sync(0xffffffffu, psum, 2);
        l = l * alpha + psum;
        m = mnew;
#pragma unroll
        for (int dv = 0; dv < 64; dv++) o[dv] *= alpha;
#pragma unroll
        for (int j = 0; j < 16; j++) {
            float pj = p[j];
            int col = qi + 4*j;
#pragma unroll
            for (int dv = 0; dv < 64; dv++) o[dv] += pj * vs[col][dv];
        }
    }

#pragma unroll
    for (int dv = 0; dv < 64; dv++) {
        o[dv] += __shfl_xor_sync(0xffffffffu, o[dv], 1);
        o[dv] += __shfl_xor_sync(0xffffffffu, o[dv], 2);
    }
    float invl = 1.f / l;
    size_t ob = (tq + row) * (size_t)(H_*DH_) + h*DH_;
#pragma unroll
    for (int d2 = 0; d2 < 16; d2++)
        ctx[ob + qi*16 + d2] = o[qi*16 + d2] * invl;
}

// ---------------- misc elementwise ----------------------------------------
__global__ void copy_k(const float4* __restrict__ src, float4* __restrict__ dst, int n4) {
    int i = blockIdx.x * blockDim.x + threadIdx.x;
    if (i < n4) dst[i] = src[i];
}

__global__ void zero_cnt_k(int* c) {
    if (threadIdx.x < NR_) c[threadIdx.x] = 0;
}

__global__ void silu_mul_k(const float* __restrict__ g, const float* __restrict__ u,
                           float* __restrict__ o, const int* __restrict__ cntPtr,
                           int fixedCnt) {
    int cnt = cntPtr ? *cntPtr : fixedCnt;
    long total = (long)cnt * DHID_;
    long i = (long)blockIdx.x * blockDim.x + threadIdx.x;
    if (i >= total) return;
    float gv = g[i], uv = u[i];
    o[i] = (gv / (1.f + __expf(-gv))) * uv;
}

// ---------------- gating: logits + softmax + top2 + routing lists ----------
__global__ void gate_topk_k(const float* __restrict__ h2, const float* __restrict__ gw,
                            int* __restrict__ cnt, int* __restrict__ elist,
                            float* __restrict__ ew) {
    int t = blockIdx.x * 8 + (threadIdx.x >> 5);
    int lane = threadIdx.x & 31;
    if (t >= T_) return;
    float acc[NR_];
#pragma unroll
    for (int e = 0; e < NR_; e++) acc[e] = 0.f;
    const float* hr = h2 + (size_t)t * D_;
    for (int d = lane; d < D_; d += 32) {
        float xv = hr[d];
        const float* g = gw + (size_t)d * NR_;
#pragma unroll
        for (int e = 0; e < NR_; e++) acc[e] += xv * g[e];
    }
#pragma unroll
    for (int e = 0; e < NR_; e++)
#pragma unroll
        for (int off = 16; off; off >>= 1)
            acc[e] += __shfl_xor_sync(0xffffffffu, acc[e], off);
    if (lane == 0) {
        int i1 = 0;
#pragma unroll
        for (int e = 1; e < NR_; e++) if (acc[e] > acc[i1]) i1 = e;
        int i2 = (i1 == 0) ? 1 : 0;
#pragma unroll
        for (int e = 0; e < NR_; e++) {
            if (e == i1 || e == i2) continue;
            if (acc[e] > acc[i2]) i2 = e;
        }
        float p2 = __expf(acc[i2] - acc[i1]);   // p1 = 1
        float inv = 1.f / (1.f + p2);
        float w1 = inv, w2 = p2 * inv;
        int pos = atomicAdd(&cnt[i1], 1);
        elist[i1*T_ + pos] = t; ew[i1*T_ + pos] = w1;
        pos = atomicAdd(&cnt[i2], 1);
        elist[i2*T_ + pos] = t; ew[i2*T_ + pos] = w2;
    }
}

// ---------------- launch ---------------------------------------------------
extern "C" void kernel_launch(void* const* d_in, const int* in_sizes, int n_in,
                              void* d_out, int out_size) {
    const float* x         = (const float*)d_in[0];
    // d_in[1] = mask (known: causal tril) — unused
    const float* w_q       = (const float*)d_in[2];
    const float* w_dkv     = (const float*)d_in[3];
    const float* w_uk      = (const float*)d_in[4];
    const float* w_uv      = (const float*)d_in[5];
    const float* w_kr      = (const float*)d_in[6];
    const float* w_o       = (const float*)d_in[7];
    const float* attn_nw   = (const float*)d_in[8];
    const float* mlp_nw    = (const float*)d_in[9];
    const float* gate_w    = (const float*)d_in[10];
    const float* wr_gate   = (const float*)d_in[11];
    const float* wr_up     = (const float*)d_in[12];
    const float* wr_down   = (const float*)d_in[13];
    const float* ws_gate   = (const float*)d_in[14];
    const float* ws_up     = (const float*)d_in[15];
    const float* ws_down   = (const float*)d_in[16];
    float* out = (float*)d_out;

    float *ph, *pq, *plat, *pkc, *pv, *pkr, *pctx, *ph2, *pgb, *pub, *pew;
    int *pcnt, *pel;
    cudaGetSymbolAddress((void**)&ph,   g_h);
    cudaGetSymbolAddress((void**)&pq,   g_q);
    cudaGetSymbolAddress((void**)&plat, g_lat);
    cudaGetSymbolAddress((void**)&pkc,  g_kc);
    cudaGetSymbolAddress((void**)&pv,   g_v);
    cudaGetSymbolAddress((void**)&pkr,  g_kr);
    cudaGetSymbolAddress((void**)&pctx, g_ctx);
    cudaGetSymbolAddress((void**)&ph2,  g_h2);
    cudaGetSymbolAddress((void**)&pgb,  g_gb);
    cudaGetSymbolAddress((void**)&pub,  g_ub);
    cudaGetSymbolAddress((void**)&pcnt, g_cnt);
    cudaGetSymbolAddress((void**)&pel,  g_elist);
    cudaGetSymbolAddress((void**)&pew,  g_ew);

    // 1) h = rmsnorm(x)
    rmsnorm_k<<<T_, 256>>>(x, attn_nw, ph);

    // 2) projections
    sgemm64<false><<<dim3((H_*QDIM_)/64, T_/64), 256>>>(ph, w_q,   pq,   H_*QDIM_, D_);
    sgemm64<false><<<dim3(DL_/64,       T_/64), 256>>>(ph, w_dkv, plat, DL_,      D_);
    sgemm64<false><<<dim3((H_*DH_)/64,  T_/64), 256>>>(plat, w_uk, pkc, H_*DH_,   DL_);
    sgemm64<false><<<dim3((H_*DH_)/64,  T_/64), 256>>>(plat, w_uv, pv,  H_*DH_,   DL_);
    sgemm64<false><<<dim3(DR_/64,       T_/64), 256>>>(ph, w_kr,  pkr,  DR_,      D_);

    // 3) RoPE on q tail + k_r
    {
        int n = T_*H_*32 + T_*32;
        rope_k<<<(n + 255)/256, 256>>>(pq, pkr);
    }

    // 4) attention -> ctx
    flash_attn_k<<<dim3(S_/32, B_*H_), 128>>>(pq, pkc, pkr, pv, pctx);

    // 5) out = x; out += ctx @ w_o
    copy_k<<<(T_*D_/4 + 255)/256, 256>>>((const float4*)x, (float4*)out, T_*D_/4);
    sgemm64<true><<<dim3(D_/64, T_/64), 256>>>(pctx, w_o, out, D_, D_);

    // 6) h2 = rmsnorm(out)
    rmsnorm_k<<<T_, 256>>>(out, mlp_nw, ph2);

    // 7) routing
    zero_cnt_k<<<1, 32>>>(pcnt);
    gate_topk_k<<<T_/8, 256>>>(ph2, gate_w, pcnt, pel, pew);

    // 8) shared experts (dense): out += down( silu(h2@g) * (h2@u) )
    for (int s = 0; s < NS_; s++) {
        const float* wg = ws_gate + (size_t)s * D_ * DHID_;
        const float* wu = ws_up   + (size_t)s * D_ * DHID_;
        const float* wd = ws_down + (size_t)s * DHID_ * D_;
        sgemm64<false><<<dim3(DHID_/64, T_/64), 256>>>(ph2, wg, pgb, DHID_, D_);
        sgemm64<false><<<dim3(DHID_/64, T_/64), 256>>>(ph2, wu, pub, DHID_, D_);
        silu_mul_k<<<(T_*DHID_ + 255)/256, 256>>>(pgb, pub, pgb, nullptr, T_);
        sgemm64<true><<<dim3(D_/64, T_/64), 256>>>(pgb, wd, out, D_, DHID_);
    }

    // 9) routed experts (sparse top-2, gather/scatter)
    for (int e = 0; e < NR_; e++) {
        const float* wg = wr_gate + (size_t)e * D_ * DHID_;
        const float* wu = wr_up   + (size_t)e * D_ * DHID_;
        const float* wd = wr_down + (size_t)e * DHID_ * D_;
        const int*   idx = pel + e * T_;
        const float* wts = pew + e * T_;
        const int*   cp  = pcnt + e;
        egemm64<true,  false><<<dim3(DHID_/64, T_/64), 256>>>(ph2, wg, pgb, idx, nullptr, cp, DHID_, D_);
        egemm64<true,  false><<<dim3(DHID_/64, T_/64), 256>>>(ph2, wu, pub, idx, nullptr, cp, DHID_, D_);
        silu_mul_k<<<(T_*DHID_ + 255)/256, 256>>>(pgb, pub, pgb, cp, 0);
        egemm64<false, true ><<<dim3(D_/64, T_/64), 256>>>(pgb, wd, out, idx, wts, cp, D_, DHID_);
    }
}

// round 5
// speedup vs baseline: 1.0429x; 1.0429x over previous
#include <cuda_runtime.h>
#include <math.h>

#define B_ 2
#define S_ 2048
#define D_ 1024
#define H_ 16
#define DH_ 64
#define DR_ 64
#define DL_ 512
#define DHID_ 512
#define NR_ 8
#define NS_ 2
#define T_ (B_*S_)          // 4096 tokens
#define QDIM_ (DH_+DR_)     // 128

// ---------------- scratch (device globals; no allocation allowed) ----------
__device__ float g_h  [T_*D_];          // rmsnorm(x)
__device__ float g_q  [T_*H_*QDIM_];    // q (B,S,H,128), rope applied in-place
__device__ float g_lat[T_*DL_];
__device__ float g_kc [T_*H_*DH_];
__device__ float g_v  [T_*H_*DH_];
__device__ float g_kr [T_*DR_];
__device__ float g_ctx[T_*H_*DH_];
__device__ float g_h2 [T_*D_];
__device__ float g_gb [T_*DHID_];
__device__ float g_ub [T_*DHID_];
__device__ int   g_cnt[NR_];
__device__ int   g_elist[NR_*T_];
__device__ float g_ew  [NR_*T_];

// ---------------- rmsnorm --------------------------------------------------
__global__ void rmsnorm_k(const float* __restrict__ x, const float* __restrict__ w,
                          float* __restrict__ o) {
    int row = blockIdx.x;
    const float* xr = x + (size_t)row * D_;
    float ss = 0.f;
    float vloc[4];
#pragma unroll
    for (int i = 0; i < 4; i++) { vloc[i] = xr[threadIdx.x + i*256]; ss += vloc[i]*vloc[i]; }
#pragma unroll
    for (int off = 16; off; off >>= 1) ss += __shfl_xor_sync(0xffffffffu, ss, off);
    __shared__ float sm[8];
    __shared__ float invs;
    if ((threadIdx.x & 31) == 0) sm[threadIdx.x >> 5] = ss;
    __syncthreads();
    if (threadIdx.x == 0) {
        float t = 0.f;
#pragma unroll
        for (int i = 0; i < 8; i++) t += sm[i];
        invs = 1.0f / sqrtf(t / (float)D_ + 1e-6f);
    }
    __syncthreads();
    float inv = invs;
    float* orow = o + (size_t)row * D_;
#pragma unroll
    for (int i = 0; i < 4; i++) {
        int d = threadIdx.x + i*256;
        orow[d] = vloc[i] * inv * w[d];
    }
}

// ---------------- small SGEMM for N=64 (w_kr only) -------------------------
template<bool ACC>
__global__ void sgemm64(const float* __restrict__ A, const float* __restrict__ Bm,
                        float* __restrict__ C, int N, int K) {
    __shared__ float As[16][64];
    __shared__ float Bs[16][64];
    int tid = threadIdx.x;
    int bx = blockIdx.x, by = blockIdx.y;
    int tx = tid & 15, ty = tid >> 4;
    float acc[4][4];
#pragma unroll
    for (int i = 0; i < 4; i++)
#pragma unroll
        for (int j = 0; j < 4; j++) acc[i][j] = 0.f;

    int aRow = tid >> 2;
    int aCol = (tid & 3) * 4;
    const float* Aptr = A + (size_t)(by*64 + aRow) * K + aCol;
    int bRow = tid >> 4;
    int bCol = (tid & 15) * 4;
    const float* Bptr = Bm + (size_t)bRow * N + bx*64 + bCol;

    for (int k0 = 0; k0 < K; k0 += 16) {
        float4 av = *(const float4*)Aptr;
        float4 bv = *(const float4*)Bptr;
        As[aCol+0][aRow] = av.x; As[aCol+1][aRow] = av.y;
        As[aCol+2][aRow] = av.z; As[aCol+3][aRow] = av.w;
        *(float4*)&Bs[bRow][bCol] = bv;
        __syncthreads();
#pragma unroll
        for (int k = 0; k < 16; k++) {
            float4 a4 = *(const float4*)&As[k][ty*4];
            float4 b4 = *(const float4*)&Bs[k][tx*4];
            float ar[4] = {a4.x, a4.y, a4.z, a4.w};
            float br[4] = {b4.x, b4.y, b4.z, b4.w};
#pragma unroll
            for (int i = 0; i < 4; i++)
#pragma unroll
                for (int j = 0; j < 4; j++) acc[i][j] += ar[i]*br[j];
        }
        __syncthreads();
        Aptr += 16;
        Bptr += (size_t)16 * N;
    }
#pragma unroll
    for (int i = 0; i < 4; i++) {
        float* cp = C + (size_t)(by*64 + ty*4 + i) * N + bx*64 + tx*4;
#pragma unroll
        for (int j = 0; j < 4; j++) {
            if (ACC) cp[j] += acc[i][j]; else cp[j] = acc[i][j];
        }
    }
}

// ---------------- main SGEMM: 128x128 tile, 8x8/thread, dbl-buffered -------
// GATHER: A rows gathered via idx (expert input), compact C rows, bound = *cntPtr
// SCATTER: A compact rows, C rows scattered via idx with per-row weight (+=)
template<bool ACC, bool GATHER, bool SCATTER>
__global__ __launch_bounds__(256, 2) void sgemm128(
        const float* __restrict__ A, const float* __restrict__ Bm,
        float* __restrict__ C, int N, int K,
        const int* __restrict__ idx, const float* __restrict__ wts,
        const int* __restrict__ cntPtr) {
    constexpr bool EXPERT = GATHER || SCATTER;
    int cnt = 0;
    if (EXPERT) {
        cnt = *cntPtr;
        if ((int)blockIdx.y * 128 >= cnt) return;
    }
    __shared__ float As[16][132];   // [k][m], padded
    __shared__ float Bs[16][128];   // [k][n]

    int tid = threadIdx.x;
    int bx = blockIdx.x, by = blockIdx.y;
    int tx = tid & 15, ty = tid >> 4;

    float acc[8][8];
#pragma unroll
    for (int i = 0; i < 8; i++)
#pragma unroll
        for (int j = 0; j < 8; j++) acc[i][j] = 0.f;

    // A: thread loads 2 float4 covering row ar, k-offsets ac..ac+7
    int ar = tid >> 1;
    int ac = (tid & 1) * 8;
    int gRowA = by*128 + ar;
    int rowA;
    if (GATHER) {
        int rs = (gRowA < cnt) ? gRowA : (cnt - 1);
        rowA = idx[rs];
    } else if (SCATTER) {
        rowA = (gRowA < cnt) ? gRowA : (cnt - 1);
    } else {
        rowA = gRowA;
    }
    const float* Ap = A + (size_t)rowA * K + ac;

    // B: thread loads 2 float4 at row br, cols bc..bc+7
    int br = tid >> 4;
    int bc = (tid & 15) * 8;
    const float* Bp = Bm + (size_t)br * N + bx*128 + bc;

    int ntiles = K >> 4;
    float4 pa0 = *(const float4*)Ap;
    float4 pa1 = *(const float4*)(Ap + 4);
    float4 pb0 = *(const float4*)Bp;
    float4 pb1 = *(const float4*)(Bp + 4);

    for (int kt = 0; kt < ntiles; kt++) {
        As[ac+0][ar] = pa0.x; As[ac+1][ar] = pa0.y;
        As[ac+2][ar] = pa0.z; As[ac+3][ar] = pa0.w;
        As[ac+4][ar] = pa1.x; As[ac+5][ar] = pa1.y;
        As[ac+6][ar] = pa1.z; As[ac+7][ar] = pa1.w;
        *(float4*)&Bs[br][bc]   = pb0;
        *(float4*)&Bs[br][bc+4] = pb1;
        __syncthreads();

        if (kt + 1 < ntiles) {
            Ap += 16;
            Bp += (size_t)16 * N;
            pa0 = *(const float4*)Ap;
            pa1 = *(const float4*)(Ap + 4);
            pb0 = *(const float4*)Bp;
            pb1 = *(const float4*)(Bp + 4);
        }

#pragma unroll
        for (int k = 0; k < 16; k++) {
            float4 a0 = *(const float4*)&As[k][ty*4];
            float4 a1 = *(const float4*)&As[k][64 + ty*4];
            float4 b0 = *(const float4*)&Bs[k][tx*4];
            float4 b1 = *(const float4*)&Bs[k][64 + tx*4];
            float av[8] = {a0.x, a0.y, a0.z, a0.w, a1.x, a1.y, a1.z, a1.w};
            float bv[8] = {b0.x, b0.y, b0.z, b0.w, b1.x, b1.y, b1.z, b1.w};
#pragma unroll
            for (int i = 0; i < 8; i++)
#pragma unroll
                for (int j = 0; j < 8; j++) acc[i][j] += av[i]*bv[j];
        }
        __syncthreads();
    }

    // epilogue
#pragma unroll
    for (int i = 0; i < 8; i++) {
        int ml = (i < 4) ? (ty*4 + i) : (64 + ty*4 + (i - 4));
        int gr = by*128 + ml;
        if (EXPERT && gr >= cnt) continue;
        if (SCATTER) {
            float w = wts[gr];
            float* cp = C + (size_t)idx[gr] * N + bx*128;
#pragma unroll
            for (int j = 0; j < 8; j++) {
                int nl = (j < 4) ? (tx*4 + j) : (64 + tx*4 + (j - 4));
                cp[nl] += w * acc[i][j];
            }
        } else {
            float* cp = C + (size_t)gr * N + bx*128;
#pragma unroll
            for (int j = 0; j < 8; j++) {
                int nl = (j < 4) ? (tx*4 + j) : (64 + tx*4 + (j - 4));
                if (ACC) cp[nl] += acc[i][j]; else cp[nl] = acc[i][j];
            }
        }
    }
}

// ---------------- RoPE (in-place on q tail + k_r) --------------------------
__global__ void rope_k(float* __restrict__ q, float* __restrict__ kr) {
    int p = blockIdx.x * blockDim.x + threadIdx.x;
    const int NQ = T_ * H_ * 32;
    const int NK = T_ * 32;
    if (p < NQ) {
        int i = p & 31;
        int h = (p >> 5) & (H_ - 1);
        int t = p >> 9;
        int s = t & (S_ - 1);
        float inv = powf(10000.0f, -(float)i / 32.0f);
        float sn, c;
        sincosf((float)s * inv, &sn, &c);
        float* base = q + (size_t)t * (H_*QDIM_) + h * QDIM_ + DH_;
        float t1 = base[i], t2 = base[32 + i];
        base[i]      = t1 * c - t2 * sn;
        base[32 + i] = t2 * c + t1 * sn;
    } else if (p < NQ + NK) {
        int p2 = p - NQ;
        int i = p2 & 31;
        int t = p2 >> 5;
        int s = t & (S_ - 1);
        float inv = powf(10000.0f, -(float)i / 32.0f);
        float sn, c;
        sincosf((float)s * inv, &sn, &c);
        float* base = kr + (size_t)t * DR_;
        float t1 = base[i], t2 = base[32 + i];
        base[i]      = t1 * c - t2 * sn;
        base[32 + i] = t2 * c + t1 * sn;
    }
}

// ---------------- flash attention (causal, d=128, dv=64) -------------------
__global__ __launch_bounds__(128) void flash_attn_k(
        const float* __restrict__ q, const float* __restrict__ kc,
        const float* __restrict__ kr, const float* __restrict__ v,
        float* __restrict__ ctx) {
    __shared__ float qs[32][129];
    __shared__ float ks[64][33];
    __shared__ float vs[64][65];
    int qb = blockIdx.x;
    int bh = blockIdx.y;
    int b = bh / H_, h = bh % H_;
    int tid = threadIdx.x;
    int row = tid >> 2;
    int qi = tid & 3;
    int qrow_g = qb*32 + row;
    size_t tq = (size_t)b*S_ + qb*32;

#pragma unroll
    for (int i = 0; i < 32; i++) {
        int e = i*128 + tid;
        int r = e >> 7, d = e & 127;
        qs[r][d] = q[(tq + r) * (H_*QDIM_) + h*QDIM_ + d];
    }

    float m = -1e30f, l = 0.f;
    float o[64];
#pragma unroll
    for (int dv = 0; dv < 64; dv++) o[dv] = 0.f;

    int nkb = (qb*32 + 31) / 64 + 1;
    for (int kb = 0; kb < nkb; kb++) {
        size_t tk = (size_t)b*S_ + kb*64;
        float s[16];
#pragma unroll
        for (int j = 0; j < 16; j++) s[j] = 0.f;

        for (int c = 0; c < 4; c++) {
            __syncthreads();
#pragma unroll
            for (int i = 0; i < 16; i++) {
                int e = i*128 + tid;
                int r = e >> 5, dd = e & 31;
                float kv;
                if (c < 2) kv = kc[(tk + r) * (H_*DH_) + h*DH_ + c*32 + dd];
                else       kv = kr[(tk + r) * DR_ + (c-2)*32 + dd];
                ks[r][dd] = kv;
            }
#pragma unroll
            for (int i = 0; i < 8; i++) {
                int e = c*1024 + i*128 + tid;
                int r = e >> 6, dv = e & 63;
                vs[r][dv] = v[(tk + r) * (H_*DH_) + h*DH_ + dv];
            }
            __syncthreads();
#pragma unroll 8
            for (int dd = 0; dd < 32; dd++) {
                float qv = qs[row][c*32 + dd];
#pragma unroll
                for (int j = 0; j < 16; j++) s[j] += qv * ks[qi + 4*j][dd];
            }
        }

        const float scale = 0.088388347648318447f;  // 1/sqrt(128)
        bool last = (kb == nkb - 1);
#pragma unroll
        for (int j = 0; j < 16; j++) {
            s[j] *= scale;
            if (last) {
                int key_g = kb*64 + qi + 4*j;
                if (key_g > qrow_g) s[j] = -1e9f;
            }
        }
        float mt = s[0];
#pragma unroll
        for (int j = 1; j < 16; j++) mt = fmaxf(mt, s[j]);
        mt = fmaxf(mt, __shfl_xor_sync(0xffffffffu, mt, 1));
        mt = fmaxf(mt, __shfl_xor_sync(0xffffffffu, mt, 2));
        float mnew = fmaxf(m, mt);
        float alpha = __expf(m - mnew);
        float p[16];
        float psum = 0.f;
#pragma unroll
        for (int j = 0; j < 16; j++) { p[j] = __expf(s[j] - mnew); psum += p[j]; }
        psum += __shfl_xor_sync(0xffffffffu, psum, 1);
        psum += __shfl_xor_sync(0xffffffffu, psum, 2);
        l = l * alpha + psum;
        m = mnew;
#pragma unroll
        for (int dv = 0; dv < 64; dv++) o[dv] *= alpha;
#pragma unroll
        for (int j = 0; j < 16; j++) {
            float pj = p[j];
            int col = qi + 4*j;
#pragma unroll
            for (int dv = 0; dv < 64; dv++) o[dv] += pj * vs[col][dv];
        }
    }

#pragma unroll
    for (int dv = 0; dv < 64; dv++) {
        o[dv] += __shfl_xor_sync(0xffffffffu, o[dv], 1);
        o[dv] += __shfl_xor_sync(0xffffffffu, o[dv], 2);
    }
    float invl = 1.f / l;
    size_t ob = (tq + row) * (size_t)(H_*DH_) + h*DH_;
#pragma unroll
    for (int d2 = 0; d2 < 16; d2++)
        ctx[ob + qi*16 + d2] = o[qi*16 + d2] * invl;
}

// ---------------- misc elementwise ----------------------------------------
__global__ void copy_k(const float4* __restrict__ src, float4* __restrict__ dst, int n4) {
    int i = blockIdx.x * blockDim.x + threadIdx.x;
    if (i < n4) dst[i] = src[i];
}

__global__ void zero_cnt_k(int* c) {
    if (threadIdx.x < NR_) c[threadIdx.x] = 0;
}

__global__ void silu_mul_k(const float* __restrict__ g, const float* __restrict__ u,
                           float* __restrict__ o, const int* __restrict__ cntPtr,
                           int fixedCnt) {
    int cnt = cntPtr ? *cntPtr : fixedCnt;
    long total = (long)cnt * DHID_;
    long i = (long)blockIdx.x * blockDim.x + threadIdx.x;
    if (i >= total) return;
    float gv = g[i], uv = u[i];
    o[i] = (gv / (1.f + __expf(-gv))) * uv;
}

// ---------------- gating: logits + softmax + top2 + routing lists ----------
__global__ void gate_topk_k(const float* __restrict__ h2, const float* __restrict__ gw,
                            int* __restrict__ cnt, int* __restrict__ elist,
                            float* __restrict__ ew) {
    int t = blockIdx.x * 8 + (threadIdx.x >> 5);
    int lane = threadIdx.x & 31;
    if (t >= T_) return;
    float acc[NR_];
#pragma unroll
    for (int e = 0; e < NR_; e++) acc[e] = 0.f;
    const float* hr = h2 + (size_t)t * D_;
    for (int d = lane; d < D_; d += 32) {
        float xv = hr[d];
        const float* g = gw + (size_t)d * NR_;
#pragma unroll
        for (int e = 0; e < NR_; e++) acc[e] += xv * g[e];
    }
#pragma unroll
    for (int e = 0; e < NR_; e++)
#pragma unroll
        for (int off = 16; off; off >>= 1)
            acc[e] += __shfl_xor_sync(0xffffffffu, acc[e], off);
    if (lane == 0) {
        int i1 = 0;
#pragma unroll
        for (int e = 1; e < NR_; e++) if (acc[e] > acc[i1]) i1 = e;
        int i2 = (i1 == 0) ? 1 : 0;
#pragma unroll
        for (int e = 0; e < NR_; e++) {
            if (e == i1 || e == i2) continue;
            if (acc[e] > acc[i2]) i2 = e;
        }
        float p2 = __expf(acc[i2] - acc[i1]);
        float inv = 1.f / (1.f + p2);
        float w1 = inv, w2 = p2 * inv;
        int pos = atomicAdd(&cnt[i1], 1);
        elist[i1*T_ + pos] = t; ew[i1*T_ + pos] = w1;
        pos = atomicAdd(&cnt[i2], 1);
        elist[i2*T_ + pos] = t; ew[i2*T_ + pos] = w2;
    }
}

// ---------------- launch ---------------------------------------------------
extern "C" void kernel_launch(void* const* d_in, const int* in_sizes, int n_in,
                              void* d_out, int out_size) {
    const float* x         = (const float*)d_in[0];
    const float* w_q       = (const float*)d_in[2];
    const float* w_dkv     = (const float*)d_in[3];
    const float* w_uk      = (const float*)d_in[4];
    const float* w_uv      = (const float*)d_in[5];
    const float* w_kr      = (const float*)d_in[6];
    const float* w_o       = (const float*)d_in[7];
    const float* attn_nw   = (const float*)d_in[8];
    const float* mlp_nw    = (const float*)d_in[9];
    const float* gate_w    = (const float*)d_in[10];
    const float* wr_gate   = (const float*)d_in[11];
    const float* wr_up     = (const float*)d_in[12];
    const float* wr_down   = (const float*)d_in[13];
    const float* ws_gate   = (const float*)d_in[14];
    const float* ws_up     = (const float*)d_in[15];
    const float* ws_down   = (const float*)d_in[16];
    float* out = (float*)d_out;

    float *ph, *pq, *plat, *pkc, *pv, *pkr, *pctx, *ph2, *pgb, *pub, *pew;
    int *pcnt, *pel;
    cudaGetSymbolAddress((void**)&ph,   g_h);
    cudaGetSymbolAddress((void**)&pq,   g_q);
    cudaGetSymbolAddress((void**)&plat, g_lat);
    cudaGetSymbolAddress((void**)&pkc,  g_kc);
    cudaGetSymbolAddress((void**)&pv,   g_v);
    cudaGetSymbolAddress((void**)&pkr,  g_kr);
    cudaGetSymbolAddress((void**)&pctx, g_ctx);
    cudaGetSymbolAddress((void**)&ph2,  g_h2);
    cudaGetSymbolAddress((void**)&pgb,  g_gb);
    cudaGetSymbolAddress((void**)&pub,  g_ub);
    cudaGetSymbolAddress((void**)&pcnt, g_cnt);
    cudaGetSymbolAddress((void**)&pel,  g_elist);
    cudaGetSymbolAddress((void**)&pew,  g_ew);

    // 1) h = rmsnorm(x)
    rmsnorm_k<<<T_, 256>>>(x, attn_nw, ph);

    // 2) projections (128x128 tiled)
    sgemm128<false,false,false><<<dim3((H_*QDIM_)/128, T_/128), 256>>>(ph,   w_q,   pq,  H_*QDIM_, D_,  nullptr, nullptr, nullptr);
    sgemm128<false,false,false><<<dim3(DL_/128,        T_/128), 256>>>(ph,   w_dkv, plat, DL_,     D_,  nullptr, nullptr, nullptr);
    sgemm128<false,false,false><<<dim3((H_*DH_)/128,   T_/128), 256>>>(plat, w_uk,  pkc, H_*DH_,   DL_, nullptr, nullptr, nullptr);
    sgemm128<false,false,false><<<dim3((H_*DH_)/128,   T_/128), 256>>>(plat, w_uv,  pv,  H_*DH_,   DL_, nullptr, nullptr, nullptr);
    sgemm64<false><<<dim3(DR_/64, T_/64), 256>>>(ph, w_kr, pkr, DR_, D_);

    // 3) RoPE on q tail + k_r
    {
        int n = T_*H_*32 + T_*32;
        rope_k<<<(n + 255)/256, 256>>>(pq, pkr);
    }

    // 4) attention -> ctx
    flash_attn_k<<<dim3(S_/32, B_*H_), 128>>>(pq, pkc, pkr, pv, pctx);

    // 5) out = x; out += ctx @ w_o
    copy_k<<<(T_*D_/4 + 255)/256, 256>>>((const float4*)x, (float4*)out, T_*D_/4);
    sgemm128<true,false,false><<<dim3(D_/128, T_/128), 256>>>(pctx, w_o, out, D_, D_, nullptr, nullptr, nullptr);

    // 6) h2 = rmsnorm(out)
    rmsnorm_k<<<T_, 256>>>(out, mlp_nw, ph2);

    // 7) routing
    zero_cnt_k<<<1, 32>>>(pcnt);
    gate_topk_k<<<T_/8, 256>>>(ph2, gate_w, pcnt, pel, pew);

    // 8) shared experts (dense)
    for (int s = 0; s < NS_; s++) {
        const float* wg = ws_gate + (size_t)s * D_ * DHID_;
        const float* wu = ws_up   + (size_t)s * D_ * DHID_;
        const float* wd = ws_down + (size_t)s * DHID_ * D_;
        sgemm128<false,false,false><<<dim3(DHID_/128, T_/128), 256>>>(ph2, wg, pgb, DHID_, D_, nullptr, nullptr, nullptr);
        sgemm128<false,false,false><<<dim3(DHID_/128, T_/128), 256>>>(ph2, wu, pub, DHID_, D_, nullptr, nullptr, nullptr);
        silu_mul_k<<<(T_*DHID_ + 255)/256, 256>>>(pgb, pub, pgb, nullptr, T_);
        sgemm128<true,false,false><<<dim3(D_/128, T_/128), 256>>>(pgb, wd, out, D_, DHID_, nullptr, nullptr, nullptr);
    }

    // 9) routed experts (sparse top-2, gather/scatter)
    for (int e = 0; e < NR_; e++) {
        const float* wg = wr_gate + (size_t)e * D_ * DHID_;
        const float* wu = wr_up   + (size_t)e * D_ * DHID_;
        const float* wd = wr_down + (size_t)e * DHID_ * D_;
        const int*   idx = pel + e * T_;
        const float* wts = pew + e * T_;
        const int*   cp  = pcnt + e;
        sgemm128<false,true, false><<<dim3(DHID_/128, T_/128), 256>>>(ph2, wg, pgb, DHID_, D_, idx, nullptr, cp);
        sgemm128<false,true, false><<<dim3(DHID_/128, T_/128), 256>>>(ph2, wu, pub, DHID_, D_, idx, nullptr, cp);
        silu_mul_k<<<(T_*DHID_ + 255)/256, 256>>>(pgb, pub, pgb, cp, 0);
        sgemm128<false,false,true ><<<dim3(D_/128, T_/128), 256>>>(pgb, wd, out, D_, DHID_, idx, wts, cp);
    }
}

// round 6
// speedup vs baseline: 1.4482x; 1.3886x over previous
#include <cuda_runtime.h>
#include <math.h>

#define B_ 2
#define S_ 2048
#define D_ 1024
#define H_ 16
#define DH_ 64
#define DR_ 64
#define DL_ 512
#define DHID_ 512
#define NR_ 8
#define NS_ 2
#define T_ (B_*S_)          // 4096 tokens
#define QDIM_ (DH_+DR_)     // 128

// ---------------- scratch (device globals; no allocation allowed) ----------
__device__ float g_h  [T_*D_];
__device__ float g_q  [T_*H_*QDIM_];
__device__ float g_lat[T_*DL_];
__device__ float g_kc [T_*H_*DH_];
__device__ float g_v  [T_*H_*DH_];
__device__ float g_kr [T_*DR_];
__device__ float g_ctx[T_*H_*DH_];
__device__ float g_h2 [T_*D_];
__device__ float g_gb [T_*DHID_];
__device__ float g_ub [T_*DHID_];
__device__ int   g_cnt[NR_];
__device__ int   g_elist[NR_*T_];
__device__ float g_ew  [NR_*T_];

// ---------------- rmsnorm --------------------------------------------------
__global__ void rmsnorm_k(const float* __restrict__ x, const float* __restrict__ w,
                          float* __restrict__ o) {
    int row = blockIdx.x;
    const float* xr = x + (size_t)row * D_;
    float ss = 0.f;
    float vloc[4];
#pragma unroll
    for (int i = 0; i < 4; i++) { vloc[i] = xr[threadIdx.x + i*256]; ss += vloc[i]*vloc[i]; }
#pragma unroll
    for (int off = 16; off; off >>= 1) ss += __shfl_xor_sync(0xffffffffu, ss, off);
    __shared__ float sm[8];
    __shared__ float invs;
    if ((threadIdx.x & 31) == 0) sm[threadIdx.x >> 5] = ss;
    __syncthreads();
    if (threadIdx.x == 0) {
        float t = 0.f;
#pragma unroll
        for (int i = 0; i < 8; i++) t += sm[i];
        invs = 1.0f / sqrtf(t / (float)D_ + 1e-6f);
    }
    __syncthreads();
    float inv = invs;
    float* orow = o + (size_t)row * D_;
#pragma unroll
    for (int i = 0; i < 4; i++) {
        int d = threadIdx.x + i*256;
        orow[d] = vloc[i] * inv * w[d];
    }
}

// ---------------- small fp32 SGEMM for N=64 (w_kr only) --------------------
template<bool ACC>
__global__ void sgemm64(const float* __restrict__ A, const float* __restrict__ Bm,
                        float* __restrict__ C, int N, int K) {
    __shared__ float As[16][64];
    __shared__ float Bs[16][64];
    int tid = threadIdx.x;
    int bx = blockIdx.x, by = blockIdx.y;
    int tx = tid & 15, ty = tid >> 4;
    float acc[4][4];
#pragma unroll
    for (int i = 0; i < 4; i++)
#pragma unroll
        for (int j = 0; j < 4; j++) acc[i][j] = 0.f;

    int aRow = tid >> 2;
    int aCol = (tid & 3) * 4;
    const float* Aptr = A + (size_t)(by*64 + aRow) * K + aCol;
    int bRow = tid >> 4;
    int bCol = (tid & 15) * 4;
    const float* Bptr = Bm + (size_t)bRow * N + bx*64 + bCol;

    for (int k0 = 0; k0 < K; k0 += 16) {
        float4 av = *(const float4*)Aptr;
        float4 bv = *(const float4*)Bptr;
        As[aCol+0][aRow] = av.x; As[aCol+1][aRow] = av.y;
        As[aCol+2][aRow] = av.z; As[aCol+3][aRow] = av.w;
        *(float4*)&Bs[bRow][bCol] = bv;
        __syncthreads();
#pragma unroll
        for (int k = 0; k < 16; k++) {
            float4 a4 = *(const float4*)&As[k][ty*4];
            float4 b4 = *(const float4*)&Bs[k][tx*4];
            float ar[4] = {a4.x, a4.y, a4.z, a4.w};
            float br[4] = {b4.x, b4.y, b4.z, b4.w};
#pragma unroll
            for (int i = 0; i < 4; i++)
#pragma unroll
                for (int j = 0; j < 4; j++) acc[i][j] += ar[i]*br[j];
        }
        __syncthreads();
        Aptr += 16;
        Bptr += (size_t)16 * N;
    }
#pragma unroll
    for (int i = 0; i < 4; i++) {
        float* cp = C + (size_t)(by*64 + ty*4 + i) * N + bx*64 + tx*4;
#pragma unroll
        for (int j = 0; j < 4; j++) {
            if (ACC) cp[j] += acc[i][j]; else cp[j] = acc[i][j];
        }
    }
}

// ---------------- tf32 tensor-core GEMM: 128x128x16, mma.m16n8k8 -----------
__device__ __forceinline__ unsigned f2tf(float x) {
    unsigned r;
    asm("cvt.rna.tf32.f32 %0, %1;" : "=r"(r) : "f"(x));
    return r;
}

template<bool ACC, bool GATHER, bool SCATTER>
__global__ __launch_bounds__(256, 2) void mma128(
        const float* __restrict__ A, const float* __restrict__ Bm,
        float* __restrict__ C, int N, int K,
        const int* __restrict__ idx, const float* __restrict__ wts,
        const int* __restrict__ cntPtr) {
    constexpr bool EXPERT = GATHER || SCATTER;
    int cnt = 0;
    if (EXPERT) {
        cnt = *cntPtr;
        if ((int)blockIdx.y * 128 >= cnt) return;
    }
    __shared__ unsigned As[16][136];   // [k][m], bank = (8k + m) % 32
    __shared__ unsigned Bs[16][136];   // [k][n]

    int tid = threadIdx.x;
    int bx = blockIdx.x, by = blockIdx.y;
    int warp = tid >> 5, lane = tid & 31;
    int wm = warp & 3;        // m-warp: 0..3, offset wm*32
    int wn = warp >> 2;       // n-warp: 0..1, offset wn*64
    int r  = lane >> 2;       // 0..7
    int cq = lane & 3;        // 0..3

    float acc[2][8][4];
#pragma unroll
    for (int i = 0; i < 2; i++)
#pragma unroll
        for (int j = 0; j < 8; j++)
#pragma unroll
            for (int k = 0; k < 4; k++) acc[i][j][k] = 0.f;

    // A loader: thread -> row ar, k-offsets ac..ac+7
    int ar = tid >> 1;
    int ac = (tid & 1) * 8;
    int gRowA = by*128 + ar;
    int rowA;
    if (GATHER) {
        int rs = (gRowA < cnt) ? gRowA : (cnt - 1);
        rowA = idx[rs];
    } else if (SCATTER) {
        rowA = (gRowA < cnt) ? gRowA : (cnt - 1);
    } else {
        rowA = gRowA;
    }
    const float* Ap = A + (size_t)rowA * K + ac;

    // B loader: thread -> k-row br, n-offsets bc..bc+7
    int br = tid >> 4;
    int bc = (tid & 15) * 8;
    const float* Bp = Bm + (size_t)br * N + bx*128 + bc;

    int ntiles = K >> 4;
    float4 pa0 = *(const float4*)Ap;
    float4 pa1 = *(const float4*)(Ap + 4);
    float4 pb0 = *(const float4*)Bp;
    float4 pb1 = *(const float4*)(Bp + 4);

    for (int kt = 0; kt < ntiles; kt++) {
        As[ac+0][ar] = f2tf(pa0.x); As[ac+1][ar] = f2tf(pa0.y);
        As[ac+2][ar] = f2tf(pa0.z); As[ac+3][ar] = f2tf(pa0.w);
        As[ac+4][ar] = f2tf(pa1.x); As[ac+5][ar] = f2tf(pa1.y);
        As[ac+6][ar] = f2tf(pa1.z); As[ac+7][ar] = f2tf(pa1.w);
        {
            uint4 u0 = {f2tf(pb0.x), f2tf(pb0.y), f2tf(pb0.z), f2tf(pb0.w)};
            uint4 u1 = {f2tf(pb1.x), f2tf(pb1.y), f2tf(pb1.z), f2tf(pb1.w)};
            *(uint4*)&Bs[br][bc]     = u0;
            *(uint4*)&Bs[br][bc + 4] = u1;
        }
        __syncthreads();

        if (kt + 1 < ntiles) {
            Ap += 16;
            Bp += (size_t)16 * N;
            pa0 = *(const float4*)Ap;
            pa1 = *(const float4*)(Ap + 4);
            pb0 = *(const float4*)Bp;
            pb1 = *(const float4*)(Bp + 4);
        }

#pragma unroll
        for (int kk = 0; kk < 16; kk += 8) {
            unsigned a[2][4];
#pragma unroll
            for (int i = 0; i < 2; i++) {
                int m0 = wm*32 + i*16 + r;
                a[i][0] = As[kk+cq  ][m0];
                a[i][1] = As[kk+cq  ][m0 + 8];
                a[i][2] = As[kk+cq+4][m0];
                a[i][3] = As[kk+cq+4][m0 + 8];
            }
#pragma unroll
            for (int j = 0; j < 8; j++) {
                int n0 = wn*64 + j*8 + r;
                unsigned b0 = Bs[kk+cq  ][n0];
                unsigned b1 = Bs[kk+cq+4][n0];
#pragma unroll
                for (int i = 0; i < 2; i++) {
                    asm volatile(
                        "mma.sync.aligned.m16n8k8.row.col.f32.tf32.tf32.f32 "
                        "{%0,%1,%2,%3},{%4,%5,%6,%7},{%8,%9},{%0,%1,%2,%3};"
                        : "+f"(acc[i][j][0]), "+f"(acc[i][j][1]),
                          "+f"(acc[i][j][2]), "+f"(acc[i][j][3])
                        : "r"(a[i][0]), "r"(a[i][1]), "r"(a[i][2]), "r"(a[i][3]),
                          "r"(b0), "r"(b1));
                }
            }
        }
        __syncthreads();
    }

    // epilogue: c0,c1 -> (row, col), (row, col+1); c2,c3 -> row+8
#pragma unroll
    for (int i = 0; i < 2; i++) {
        int lrow = wm*32 + i*16 + r;
        int gr0 = by*128 + lrow;       // compact row index
        int gr1 = gr0 + 8;
#pragma unroll
        for (int half = 0; half < 2; half++) {
            int gr = half ? gr1 : gr0;
            if (EXPERT && gr >= cnt) continue;
            int crow;
            float wscale = 1.f;
            if (SCATTER) { crow = idx[gr]; wscale = wts[gr]; }
            else         { crow = gr; }
            float* cbase = C + (size_t)crow * N + bx*128 + wn*64;
#pragma unroll
            for (int j = 0; j < 8; j++) {
                float v0 = acc[i][j][half*2 + 0];
                float v1 = acc[i][j][half*2 + 1];
                float2* p = (float2*)(cbase + j*8 + cq*2);
                if (SCATTER) {
                    float2 old = *p;
                    old.x += wscale * v0;
                    old.y += wscale * v1;
                    *p = old;
                } else if (ACC) {
                    float2 old = *p;
                    old.x += v0; old.y += v1;
                    *p = old;
                } else {
                    float2 nv; nv.x = v0; nv.y = v1;
                    *p = nv;
                }
            }
        }
    }
}

// ---------------- RoPE (in-place on q tail + k_r) --------------------------
__global__ void rope_k(float* __restrict__ q, float* __restrict__ kr) {
    int p = blockIdx.x * blockDim.x + threadIdx.x;
    const int NQ = T_ * H_ * 32;
    const int NK = T_ * 32;
    if (p < NQ) {
        int i = p & 31;
        int h = (p >> 5) & (H_ - 1);
        int t = p >> 9;
        int s = t & (S_ - 1);
        float inv = powf(10000.0f, -(float)i / 32.0f);
        float sn, c;
        sincosf((float)s * inv, &sn, &c);
        float* base = q + (size_t)t * (H_*QDIM_) + h * QDIM_ + DH_;
        float t1 = base[i], t2 = base[32 + i];
        base[i]      = t1 * c - t2 * sn;
        base[32 + i] = t2 * c + t1 * sn;
    } else if (p < NQ + NK) {
        int p2 = p - NQ;
        int i = p2 & 31;
        int t = p2 >> 5;
        int s = t & (S_ - 1);
        float inv = powf(10000.0f, -(float)i / 32.0f);
        float sn, c;
        sincosf((float)s * inv, &sn, &c);
        float* base = kr + (size_t)t * DR_;
        float t1 = base[i], t2 = base[32 + i];
        base[i]      = t1 * c - t2 * sn;
        base[32 + i] = t2 * c + t1 * sn;
    }
}

// ---------------- flash attention (causal, d=128, dv=64) -------------------
__global__ __launch_bounds__(128) void flash_attn_k(
        const float* __restrict__ q, const float* __restrict__ kc,
        const float* __restrict__ kr, const float* __restrict__ v,
        float* __restrict__ ctx) {
    __shared__ float qs[32][129];
    __shared__ float ks[64][33];
    __shared__ float vs[64][65];
    int qb = blockIdx.x;
    int bh = blockIdx.y;
    int b = bh / H_, h = bh % H_;
    int tid = threadIdx.x;
    int row = tid >> 2;
    int qi = tid & 3;
    int qrow_g = qb*32 + row;
    size_t tq = (size_t)b*S_ + qb*32;

#pragma unroll
    for (int i = 0; i < 32; i++) {
        int e = i*128 + tid;
        int r = e >> 7, d = e & 127;
        qs[r][d] = q[(tq + r) * (H_*QDIM_) + h*QDIM_ + d];
    }

    float m = -1e30f, l = 0.f;
    float o[64];
#pragma unroll
    for (int dv = 0; dv < 64; dv++) o[dv] = 0.f;

    int nkb = (qb*32 + 31) / 64 + 1;
    for (int kb = 0; kb < nkb; kb++) {
        size_t tk = (size_t)b*S_ + kb*64;
        float s[16];
#pragma unroll
        for (int j = 0; j < 16; j++) s[j] = 0.f;

        for (int c = 0; c < 4; c++) {
            __syncthreads();
#pragma unroll
            for (int i = 0; i < 16; i++) {
                int e = i*128 + tid;
                int r = e >> 5, dd = e & 31;
                float kv;
                if (c < 2) kv = kc[(tk + r) * (H_*DH_) + h*DH_ + c*32 + dd];
                else       kv = kr[(tk + r) * DR_ + (c-2)*32 + dd];
                ks[r][dd] = kv;
            }
#pragma unroll
            for (int i = 0; i < 8; i++) {
                int e = c*1024 + i*128 + tid;
                int r = e >> 6, dv = e & 63;
                vs[r][dv] = v[(tk + r) * (H_*DH_) + h*DH_ + dv];
            }
            __syncthreads();
#pragma unroll 8
            for (int dd = 0; dd < 32; dd++) {
                float qv = qs[row][c*32 + dd];
#pragma unroll
                for (int j = 0; j < 16; j++) s[j] += qv * ks[qi + 4*j][dd];
            }
        }

        const float scale = 0.088388347648318447f;  // 1/sqrt(128)
        bool last = (kb == nkb - 1);
#pragma unroll
        for (int j = 0; j < 16; j++) {
            s[j] *= scale;
            if (last) {
                int key_g = kb*64 + qi + 4*j;
                if (key_g > qrow_g) s[j] = -1e9f;
            }
        }
        float mt = s[0];
#pragma unroll
        for (int j = 1; j < 16; j++) mt = fmaxf(mt, s[j]);
        mt = fmaxf(mt, __shfl_xor_sync(0xffffffffu, mt, 1));
        mt = fmaxf(mt, __shfl_xor_sync(0xffffffffu, mt, 2));
        float mnew = fmaxf(m, mt);
        float alpha = __expf(m - mnew);
        float p[16];
        float psum = 0.f;
#pragma unroll
        for (int j = 0; j < 16; j++) { p[j] = __expf(s[j] - mnew); psum += p[j]; }
        psum += __shfl_xor_sync(0xffffffffu, psum, 1);
        psum += __shfl_xor_sync(0xffffffffu, psum, 2);
        l = l * alpha + psum;
        m = mnew;
#pragma unroll
        for (int dv = 0; dv < 64; dv++) o[dv] *= alpha;
#pragma unroll
        for (int j = 0; j < 16; j++) {
            float pj = p[j];
            int col = qi + 4*j;
#pragma unroll
            for (int dv = 0; dv < 64; dv++) o[dv] += pj * vs[col][dv];
        }
    }

#pragma unroll
    for (int dv = 0; dv < 64; dv++) {
        o[dv] += __shfl_xor_sync(0xffffffffu, o[dv], 1);
        o[dv] += __shfl_xor_sync(0xffffffffu, o[dv], 2);
    }
    float invl = 1.f / l;
    size_t ob = (tq + row) * (size_t)(H_*DH_) + h*DH_;
#pragma unroll
    for (int d2 = 0; d2 < 16; d2++)
        ctx[ob + qi*16 + d2] = o[qi*16 + d2] * invl;
}

// ---------------- misc elementwise ----------------------------------------
__global__ void copy_k(const float4* __restrict__ src, float4* __restrict__ dst, int n4) {
    int i = blockIdx.x * blockDim.x + threadIdx.x;
    if (i < n4) dst[i] = src[i];
}

__global__ void zero_cnt_k(int* c) {
    if (threadIdx.x < NR_) c[threadIdx.x] = 0;
}

__global__ void silu_mul_k(const float* __restrict__ g, const float* __restrict__ u,
                           float* __restrict__ o, const int* __restrict__ cntPtr,
                           int fixedCnt) {
    int cnt = cntPtr ? *cntPtr : fixedCnt;
    long total = (long)cnt * DHID_;
    long i = (long)blockIdx.x * blockDim.x + threadIdx.x;
    if (i >= total) return;
    float gv = g[i], uv = u[i];
    o[i] = (gv / (1.f + __expf(-gv))) * uv;
}

// ---------------- gating: logits + softmax + top2 + routing lists ----------
__global__ void gate_topk_k(const float* __restrict__ h2, const float* __restrict__ gw,
                            int* __restrict__ cnt, int* __restrict__ elist,
                            float* __restrict__ ew) {
    int t = blockIdx.x * 8 + (threadIdx.x >> 5);
    int lane = threadIdx.x & 31;
    if (t >= T_) return;
    float acc[NR_];
#pragma unroll
    for (int e = 0; e < NR_; e++) acc[e] = 0.f;
    const float* hr = h2 + (size_t)t * D_;
    for (int d = lane; d < D_; d += 32) {
        float xv = hr[d];
        const float* g = gw + (size_t)d * NR_;
#pragma unroll
        for (int e = 0; e < NR_; e++) acc[e] += xv * g[e];
    }
#pragma unroll
    for (int e = 0; e < NR_; e++)
#pragma unroll
        for (int off = 16; off; off >>= 1)
            acc[e] += __shfl_xor_sync(0xffffffffu, acc[e], off);
    if (lane == 0) {
        int i1 = 0;
#pragma unroll
        for (int e = 1; e < NR_; e++) if (acc[e] > acc[i1]) i1 = e;
        int i2 = (i1 == 0) ? 1 : 0;
#pragma unroll
        for (int e = 0; e < NR_; e++) {
            if (e == i1 || e == i2) continue;
            if (acc[e] > acc[i2]) i2 = e;
        }
        float p2 = __expf(acc[i2] - acc[i1]);
        float inv = 1.f / (1.f + p2);
        float w1 = inv, w2 = p2 * inv;
        int pos = atomicAdd(&cnt[i1], 1);
        elist[i1*T_ + pos] = t; ew[i1*T_ + pos] = w1;
        pos = atomicAdd(&cnt[i2], 1);
        elist[i2*T_ + pos] = t; ew[i2*T_ + pos] = w2;
    }
}

// ---------------- launch ---------------------------------------------------
extern "C" void kernel_launch(void* const* d_in, const int* in_sizes, int n_in,
                              void* d_out, int out_size) {
    const float* x         = (const float*)d_in[0];
    const float* w_q       = (const float*)d_in[2];
    const float* w_dkv     = (const float*)d_in[3];
    const float* w_uk      = (const float*)d_in[4];
    const float* w_uv      = (const float*)d_in[5];
    const float* w_kr      = (const float*)d_in[6];
    const float* w_o       = (const float*)d_in[7];
    const float* attn_nw   = (const float*)d_in[8];
    const float* mlp_nw    = (const float*)d_in[9];
    const float* gate_w    = (const float*)d_in[10];
    const float* wr_gate   = (const float*)d_in[11];
    const float* wr_up     = (const float*)d_in[12];
    const float* wr_down   = (const float*)d_in[13];
    const float* ws_gate   = (const float*)d_in[14];
    const float* ws_up     = (const float*)d_in[15];
    const float* ws_down   = (const float*)d_in[16];
    float* out = (float*)d_out;

    float *ph, *pq, *plat, *pkc, *pv, *pkr, *pctx, *ph2, *pgb, *pub, *pew;
    int *pcnt, *pel;
    cudaGetSymbolAddress((void**)&ph,   g_h);
    cudaGetSymbolAddress((void**)&pq,   g_q);
    cudaGetSymbolAddress((void**)&plat, g_lat);
    cudaGetSymbolAddress((void**)&pkc,  g_kc);
    cudaGetSymbolAddress((void**)&pv,   g_v);
    cudaGetSymbolAddress((void**)&pkr,  g_kr);
    cudaGetSymbolAddress((void**)&pctx, g_ctx);
    cudaGetSymbolAddress((void**)&ph2,  g_h2);
    cudaGetSymbolAddress((void**)&pgb,  g_gb);
    cudaGetSymbolAddress((void**)&pub,  g_ub);
    cudaGetSymbolAddress((void**)&pcnt, g_cnt);
    cudaGetSymbolAddress((void**)&pel,  g_elist);
    cudaGetSymbolAddress((void**)&pew,  g_ew);

    // 1) h = rmsnorm(x)
    rmsnorm_k<<<T_, 256>>>(x, attn_nw, ph);

    // 2) projections (tf32 tensor cores)
    mma128<false,false,false><<<dim3((H_*QDIM_)/128, T_/128), 256>>>(ph,   w_q,   pq,  H_*QDIM_, D_,  nullptr, nullptr, nullptr);
    mma128<false,false,false><<<dim3(DL_/128,        T_/128), 256>>>(ph,   w_dkv, plat, DL_,     D_,  nullptr, nullptr, nullptr);
    mma128<false,false,false><<<dim3((H_*DH_)/128,   T_/128), 256>>>(plat, w_uk,  pkc, H_*DH_,   DL_, nullptr, nullptr, nullptr);
    mma128<false,false,false><<<dim3((H_*DH_)/128,   T_/128), 256>>>(plat, w_uv,  pv,  H_*DH_,   DL_, nullptr, nullptr, nullptr);
    sgemm64<false><<<dim3(DR_/64, T_/64), 256>>>(ph, w_kr, pkr, DR_, D_);

    // 3) RoPE on q tail + k_r
    {
        int n = T_*H_*32 + T_*32;
        rope_k<<<(n + 255)/256, 256>>>(pq, pkr);
    }

    // 4) attention -> ctx
    flash_attn_k<<<dim3(S_/32, B_*H_), 128>>>(pq, pkc, pkr, pv, pctx);

    // 5) out = x; out += ctx @ w_o
    copy_k<<<(T_*D_/4 + 255)/256, 256>>>((const float4*)x, (float4*)out, T_*D_/4);
    mma128<true,false,false><<<dim3(D_/128, T_/128), 256>>>(pctx, w_o, out, D_, D_, nullptr, nullptr, nullptr);

    // 6) h2 = rmsnorm(out)
    rmsnorm_k<<<T_, 256>>>(out, mlp_nw, ph2);

    // 7) routing
    zero_cnt_k<<<1, 32>>>(pcnt);
    gate_topk_k<<<T_/8, 256>>>(ph2, gate_w, pcnt, pel, pew);

    // 8) shared experts (dense)
    for (int s = 0; s < NS_; s++) {
        const float* wg = ws_gate + (size_t)s * D_ * DHID_;
        const float* wu = ws_up   + (size_t)s * D_ * DHID_;
        const float* wd = ws_down + (size_t)s * DHID_ * D_;
        mma128<false,false,false><<<dim3(DHID_/128, T_/128), 256>>>(ph2, wg, pgb, DHID_, D_, nullptr, nullptr, nullptr);
        mma128<false,false,false><<<dim3(DHID_/128, T_/128), 256>>>(ph2, wu, pub, DHID_, D_, nullptr, nullptr, nullptr);
        silu_mul_k<<<(T_*DHID_ + 255)/256, 256>>>(pgb, pub, pgb, nullptr, T_);
        mma128<true,false,false><<<dim3(D_/128, T_/128), 256>>>(pgb, wd, out, D_, DHID_, nullptr, nullptr, nullptr);
    }

    // 9) routed experts (sparse top-2, gather/scatter)
    for (int e = 0; e < NR_; e++) {
        const float* wg = wr_gate + (size_t)e * D_ * DHID_;
        const float* wu = wr_up   + (size_t)e * D_ * DHID_;
        const float* wd = wr_down + (size_t)e * DHID_ * D_;
        const int*   idx = pel + e * T_;
        const float* wts = pew + e * T_;
        const int*   cp  = pcnt + e;
        mma128<false,true, false><<<dim3(DHID_/128, T_/128), 256>>>(ph2, wg, pgb, DHID_, D_, idx, nullptr, cp);
        mma128<false,true, false><<<dim3(DHID_/128, T_/128), 256>>>(ph2, wu, pub, DHID_, D_, idx, nullptr, cp);
        silu_mul_k<<<(T_*DHID_ + 255)/256, 256>>>(pgb, pub, pgb, cp, 0);
        mma128<false,false,true ><<<dim3(D_/128, T_/128), 256>>>(pgb, wd, out, D_, DHID_, idx, wts, cp);
    }
}

// round 7
// speedup vs baseline: 1.5850x; 1.0945x over previous
#include <cuda_runtime.h>
#include <math.h>

#define B_ 2
#define S_ 2048
#define D_ 1024
#define H_ 16
#define DH_ 64
#define DR_ 64
#define DL_ 512
#define DHID_ 512
#define NR_ 8
#define NS_ 2
#define T_ (B_*S_)          // 4096 tokens
#define QDIM_ (DH_+DR_)     // 128

// ---------------- scratch (device globals; no allocation allowed) ----------
__device__ float g_h  [T_*D_];
__device__ float g_q  [T_*H_*QDIM_];
__device__ float g_lat[T_*DL_];
__device__ float g_kc [T_*H_*DH_];
__device__ float g_v  [T_*H_*DH_];
__device__ float g_kr [T_*DR_];
__device__ float g_ctx[T_*H_*DH_];
__device__ float g_h2 [T_*D_];
__device__ float g_gb [T_*DHID_];
__device__ float g_ub [T_*DHID_];
__device__ int   g_cnt[NR_];
__device__ int   g_elist[NR_*T_];
__device__ float g_ew  [NR_*T_];

__device__ __forceinline__ unsigned f2tf(float x) {
    unsigned r;
    asm("cvt.rna.tf32.f32 %0, %1;" : "=r"(r) : "f"(x));
    return r;
}

// ---------------- rmsnorm --------------------------------------------------
__global__ void rmsnorm_k(const float* __restrict__ x, const float* __restrict__ w,
                          float* __restrict__ o) {
    int row = blockIdx.x;
    const float* xr = x + (size_t)row * D_;
    float ss = 0.f;
    float vloc[4];
#pragma unroll
    for (int i = 0; i < 4; i++) { vloc[i] = xr[threadIdx.x + i*256]; ss += vloc[i]*vloc[i]; }
#pragma unroll
    for (int off = 16; off; off >>= 1) ss += __shfl_xor_sync(0xffffffffu, ss, off);
    __shared__ float sm[8];
    __shared__ float invs;
    if ((threadIdx.x & 31) == 0) sm[threadIdx.x >> 5] = ss;
    __syncthreads();
    if (threadIdx.x == 0) {
        float t = 0.f;
#pragma unroll
        for (int i = 0; i < 8; i++) t += sm[i];
        invs = 1.0f / sqrtf(t / (float)D_ + 1e-6f);
    }
    __syncthreads();
    float inv = invs;
    float* orow = o + (size_t)row * D_;
#pragma unroll
    for (int i = 0; i < 4; i++) {
        int d = threadIdx.x + i*256;
        orow[d] = vloc[i] * inv * w[d];
    }
}

// ---------------- small fp32 SGEMM for N=64 (w_kr only) --------------------
template<bool ACC>
__global__ void sgemm64(const float* __restrict__ A, const float* __restrict__ Bm,
                        float* __restrict__ C, int N, int K) {
    __shared__ float As[16][64];
    __shared__ float Bs[16][64];
    int tid = threadIdx.x;
    int bx = blockIdx.x, by = blockIdx.y;
    int tx = tid & 15, ty = tid >> 4;
    float acc[4][4];
#pragma unroll
    for (int i = 0; i < 4; i++)
#pragma unroll
        for (int j = 0; j < 4; j++) acc[i][j] = 0.f;

    int aRow = tid >> 2;
    int aCol = (tid & 3) * 4;
    const float* Aptr = A + (size_t)(by*64 + aRow) * K + aCol;
    int bRow = tid >> 4;
    int bCol = (tid & 15) * 4;
    const float* Bptr = Bm + (size_t)bRow * N + bx*64 + bCol;

    for (int k0 = 0; k0 < K; k0 += 16) {
        float4 av = *(const float4*)Aptr;
        float4 bv = *(const float4*)Bptr;
        As[aCol+0][aRow] = av.x; As[aCol+1][aRow] = av.y;
        As[aCol+2][aRow] = av.z; As[aCol+3][aRow] = av.w;
        *(float4*)&Bs[bRow][bCol] = bv;
        __syncthreads();
#pragma unroll
        for (int k = 0; k < 16; k++) {
            float4 a4 = *(const float4*)&As[k][ty*4];
            float4 b4 = *(const float4*)&Bs[k][tx*4];
            float ar[4] = {a4.x, a4.y, a4.z, a4.w};
            float br[4] = {b4.x, b4.y, b4.z, b4.w};
#pragma unroll
            for (int i = 0; i < 4; i++)
#pragma unroll
                for (int j = 0; j < 4; j++) acc[i][j] += ar[i]*br[j];
        }
        __syncthreads();
        Aptr += 16;
        Bptr += (size_t)16 * N;
    }
#pragma unroll
    for (int i = 0; i < 4; i++) {
        float* cp = C + (size_t)(by*64 + ty*4 + i) * N + bx*64 + tx*4;
#pragma unroll
        for (int j = 0; j < 4; j++) {
            if (ACC) cp[j] += acc[i][j]; else cp[j] = acc[i][j];
        }
    }
}

// ---------------- tf32 tensor-core GEMM: 128x128x16, mma.m16n8k8 -----------
template<bool ACC, bool GATHER, bool SCATTER>
__global__ __launch_bounds__(256, 2) void mma128(
        const float* __restrict__ A, const float* __restrict__ Bm,
        float* __restrict__ C, int N, int K,
        const int* __restrict__ idx, const float* __restrict__ wts,
        const int* __restrict__ cntPtr) {
    constexpr bool EXPERT = GATHER || SCATTER;
    int cnt = 0;
    if (EXPERT) {
        cnt = *cntPtr;
        if ((int)blockIdx.y * 128 >= cnt) return;
    }
    __shared__ unsigned As[16][136];
    __shared__ unsigned Bs[16][136];

    int tid = threadIdx.x;
    int bx = blockIdx.x, by = blockIdx.y;
    int warp = tid >> 5, lane = tid & 31;
    int wm = warp & 3;
    int wn = warp >> 2;
    int r  = lane >> 2;
    int cq = lane & 3;

    float acc[2][8][4];
#pragma unroll
    for (int i = 0; i < 2; i++)
#pragma unroll
        for (int j = 0; j < 8; j++)
#pragma unroll
            for (int k = 0; k < 4; k++) acc[i][j][k] = 0.f;

    int ar = tid >> 1;
    int ac = (tid & 1) * 8;
    int gRowA = by*128 + ar;
    int rowA;
    if (GATHER) {
        int rs = (gRowA < cnt) ? gRowA : (cnt - 1);
        rowA = idx[rs];
    } else if (SCATTER) {
        rowA = (gRowA < cnt) ? gRowA : (cnt - 1);
    } else {
        rowA = gRowA;
    }
    const float* Ap = A + (size_t)rowA * K + ac;

    int br = tid >> 4;
    int bc = (tid & 15) * 8;
    const float* Bp = Bm + (size_t)br * N + bx*128 + bc;

    int ntiles = K >> 4;
    float4 pa0 = *(const float4*)Ap;
    float4 pa1 = *(const float4*)(Ap + 4);
    float4 pb0 = *(const float4*)Bp;
    float4 pb1 = *(const float4*)(Bp + 4);

    for (int kt = 0; kt < ntiles; kt++) {
        As[ac+0][ar] = f2tf(pa0.x); As[ac+1][ar] = f2tf(pa0.y);
        As[ac+2][ar] = f2tf(pa0.z); As[ac+3][ar] = f2tf(pa0.w);
        As[ac+4][ar] = f2tf(pa1.x); As[ac+5][ar] = f2tf(pa1.y);
        As[ac+6][ar] = f2tf(pa1.z); As[ac+7][ar] = f2tf(pa1.w);
        {
            uint4 u0 = {f2tf(pb0.x), f2tf(pb0.y), f2tf(pb0.z), f2tf(pb0.w)};
            uint4 u1 = {f2tf(pb1.x), f2tf(pb1.y), f2tf(pb1.z), f2tf(pb1.w)};
            *(uint4*)&Bs[br][bc]     = u0;
            *(uint4*)&Bs[br][bc + 4] = u1;
        }
        __syncthreads();

        if (kt + 1 < ntiles) {
            Ap += 16;
            Bp += (size_t)16 * N;
            pa0 = *(const float4*)Ap;
            pa1 = *(const float4*)(Ap + 4);
            pb0 = *(const float4*)Bp;
            pb1 = *(const float4*)(Bp + 4);
        }

#pragma unroll
        for (int kk = 0; kk < 16; kk += 8) {
            unsigned a[2][4];
#pragma unroll
            for (int i = 0; i < 2; i++) {
                int m0 = wm*32 + i*16 + r;
                a[i][0] = As[kk+cq  ][m0];
                a[i][1] = As[kk+cq  ][m0 + 8];
                a[i][2] = As[kk+cq+4][m0];
                a[i][3] = As[kk+cq+4][m0 + 8];
            }
#pragma unroll
            for (int j = 0; j < 8; j++) {
                int n0 = wn*64 + j*8 + r;
                unsigned b0 = Bs[kk+cq  ][n0];
                unsigned b1 = Bs[kk+cq+4][n0];
#pragma unroll
                for (int i = 0; i < 2; i++) {
                    asm volatile(
                        "mma.sync.aligned.m16n8k8.row.col.f32.tf32.tf32.f32 "
                        "{%0,%1,%2,%3},{%4,%5,%6,%7},{%8,%9},{%0,%1,%2,%3};"
                        : "+f"(acc[i][j][0]), "+f"(acc[i][j][1]),
                          "+f"(acc[i][j][2]), "+f"(acc[i][j][3])
                        : "r"(a[i][0]), "r"(a[i][1]), "r"(a[i][2]), "r"(a[i][3]),
                          "r"(b0), "r"(b1));
                }
            }
        }
        __syncthreads();
    }

#pragma unroll
    for (int i = 0; i < 2; i++) {
        int lrow = wm*32 + i*16 + r;
        int gr0 = by*128 + lrow;
        int gr1 = gr0 + 8;
#pragma unroll
        for (int half = 0; half < 2; half++) {
            int gr = half ? gr1 : gr0;
            if (EXPERT && gr >= cnt) continue;
            int crow;
            float wscale = 1.f;
            if (SCATTER) { crow = idx[gr]; wscale = wts[gr]; }
            else         { crow = gr; }
            float* cbase = C + (size_t)crow * N + bx*128 + wn*64;
#pragma unroll
            for (int j = 0; j < 8; j++) {
                float v0 = acc[i][j][half*2 + 0];
                float v1 = acc[i][j][half*2 + 1];
                float2* p = (float2*)(cbase + j*8 + cq*2);
                if (SCATTER) {
                    float2 old = *p;
                    old.x += wscale * v0;
                    old.y += wscale * v1;
                    *p = old;
                } else if (ACC) {
                    float2 old = *p;
                    old.x += v0; old.y += v1;
                    *p = old;
                } else {
                    float2 nv; nv.x = v0; nv.y = v1;
                    *p = nv;
                }
            }
        }
    }
}

// ---------------- RoPE (in-place on q tail + k_r) --------------------------
__global__ void rope_k(float* __restrict__ q, float* __restrict__ kr) {
    int p = blockIdx.x * blockDim.x + threadIdx.x;
    const int NQ = T_ * H_ * 32;
    const int NK = T_ * 32;
    if (p < NQ) {
        int i = p & 31;
        int h = (p >> 5) & (H_ - 1);
        int t = p >> 9;
        int s = t & (S_ - 1);
        float inv = powf(10000.0f, -(float)i / 32.0f);
        float sn, c;
        sincosf((float)s * inv, &sn, &c);
        float* base = q + (size_t)t * (H_*QDIM_) + h * QDIM_ + DH_;
        float t1 = base[i], t2 = base[32 + i];
        base[i]      = t1 * c - t2 * sn;
        base[32 + i] = t2 * c + t1 * sn;
    } else if (p < NQ + NK) {
        int p2 = p - NQ;
        int i = p2 & 31;
        int t = p2 >> 5;
        int s = t & (S_ - 1);
        float inv = powf(10000.0f, -(float)i / 32.0f);
        float sn, c;
        sincosf((float)s * inv, &sn, &c);
        float* base = kr + (size_t)t * DR_;
        float t1 = base[i], t2 = base[32 + i];
        base[i]      = t1 * c - t2 * sn;
        base[32 + i] = t2 * c + t1 * sn;
    }
}

// ---------------- tensor-core flash attention (causal, d=128, dv=64) -------
// 64 q-rows/CTA, 4 warps * 16 rows. S and P@V via mma.m16n8k8.tf32.
// smem strides: Q/K 132, V/P 68  -> fragment banks (4r+cq)%32 all distinct.
#define FA_SMEM_FLOATS (64*132 + 64*132 + 64*68 + 4*16*68)
#define FA_SMEM_BYTES  (FA_SMEM_FLOATS*4)

__global__ __launch_bounds__(128) void flash_mma_k(
        const float* __restrict__ q, const float* __restrict__ kc,
        const float* __restrict__ kr, const float* __restrict__ v,
        float* __restrict__ ctx) {
    extern __shared__ unsigned smbuf[];
    unsigned* Qs = smbuf;                 // [64][132]
    unsigned* Ks = Qs + 64*132;           // [64][132]
    unsigned* Vs = Ks + 64*132;           // [64][68]
    unsigned* Ps = Vs + 64*68;            // [4][16][68]

    int qb = blockIdx.x;
    int bh = blockIdx.y;
    int b = bh >> 4, h = bh & 15;
    int tid = threadIdx.x;
    int warp = tid >> 5, lane = tid & 31;
    int r = lane >> 2, cq = lane & 3;
    size_t tq = (size_t)b*S_ + qb*64;
    unsigned* Pw = Ps + warp*16*68;

    // load Q tile (64 x 128) as tf32
#pragma unroll
    for (int i = 0; i < 16; i++) {
        int e = i*128 + tid;
        int row = e >> 5, c4 = (e & 31) * 4;
        float4 qv = *(const float4*)&q[(tq+row)*(size_t)(H_*QDIM_) + h*QDIM_ + c4];
        unsigned* dst = &Qs[row*132 + c4];
        dst[0]=f2tf(qv.x); dst[1]=f2tf(qv.y); dst[2]=f2tf(qv.z); dst[3]=f2tf(qv.w);
    }

    float m0 = -1e30f, m1 = -1e30f;
    float l0 = 0.f,  l1 = 0.f;
    float o[8][4];
#pragma unroll
    for (int j = 0; j < 8; j++)
#pragma unroll
        for (int k = 0; k < 4; k++) o[j][k] = 0.f;

    const float scale = 0.088388347648318447f;   // 1/sqrt(128)
    int nkb = qb + 1;

    for (int kb = 0; kb < nkb; kb++) {
        size_t tk = (size_t)b*S_ + kb*64;
        __syncthreads();
        // K tile: kc (cols 0..63) + kr (cols 64..127)
#pragma unroll
        for (int i = 0; i < 8; i++) {
            int e = i*128 + tid;
            int row = e >> 4, c4 = (e & 15) * 4;
            float4 kv = *(const float4*)&kc[(tk+row)*(size_t)(H_*DH_) + h*DH_ + c4];
            unsigned* dst = &Ks[row*132 + c4];
            dst[0]=f2tf(kv.x); dst[1]=f2tf(kv.y); dst[2]=f2tf(kv.z); dst[3]=f2tf(kv.w);
        }
#pragma unroll
        for (int i = 0; i < 8; i++) {
            int e = i*128 + tid;
            int row = e >> 4, c4 = (e & 15) * 4;
            float4 kv = *(const float4*)&kr[(tk+row)*(size_t)DR_ + c4];
            unsigned* dst = &Ks[row*132 + 64 + c4];
            dst[0]=f2tf(kv.x); dst[1]=f2tf(kv.y); dst[2]=f2tf(kv.z); dst[3]=f2tf(kv.w);
        }
#pragma unroll
        for (int i = 0; i < 8; i++) {
            int e = i*128 + tid;
            int row = e >> 4, c4 = (e & 15) * 4;
            float4 vv = *(const float4*)&v[(tk+row)*(size_t)(H_*DH_) + h*DH_ + c4];
            unsigned* dst = &Vs[row*68 + c4];
            dst[0]=f2tf(vv.x); dst[1]=f2tf(vv.y); dst[2]=f2tf(vv.z); dst[3]=f2tf(vv.w);
        }
        __syncthreads();

        // S = Q @ K^T  (per warp: 16 x 64)
        float s[8][4];
#pragma unroll
        for (int j = 0; j < 8; j++)
#pragma unroll
            for (int k = 0; k < 4; k++) s[j][k] = 0.f;

#pragma unroll
        for (int kk = 0; kk < 128; kk += 8) {
            int m0r = (warp*16 + r)*132;
            unsigned a0 = Qs[m0r + kk + cq];
            unsigned a1 = Qs[m0r + 8*132 + kk + cq];
            unsigned a2 = Qs[m0r + kk + cq + 4];
            unsigned a3 = Qs[m0r + 8*132 + kk + cq + 4];
#pragma unroll
            for (int j = 0; j < 8; j++) {
                unsigned b0 = Ks[(j*8 + r)*132 + kk + cq];
                unsigned b1 = Ks[(j*8 + r)*132 + kk + cq + 4];
                asm volatile(
                    "mma.sync.aligned.m16n8k8.row.col.f32.tf32.tf32.f32 "
                    "{%0,%1,%2,%3},{%4,%5,%6,%7},{%8,%9},{%0,%1,%2,%3};"
                    : "+f"(s[j][0]), "+f"(s[j][1]), "+f"(s[j][2]), "+f"(s[j][3])
                    : "r"(a0), "r"(a1), "r"(a2), "r"(a3), "r"(b0), "r"(b1));
            }
        }

        // scale + causal mask (diagonal block only)
        bool diag = (kb == qb);
        int lq0 = warp*16 + r;       // local q row for c0,c1
        int lq1 = lq0 + 8;
#pragma unroll
        for (int j = 0; j < 8; j++) {
            int c0 = j*8 + cq*2, c1 = c0 + 1;
            s[j][0] *= scale; s[j][1] *= scale;
            s[j][2] *= scale; s[j][3] *= scale;
            if (diag) {
                if (c0 > lq0) s[j][0] = -1e9f;
                if (c1 > lq0) s[j][1] = -1e9f;
                if (c0 > lq1) s[j][2] = -1e9f;
                if (c1 > lq1) s[j][3] = -1e9f;
            }
        }

        // row maxes
        float mt0 = -1e30f, mt1 = -1e30f;
#pragma unroll
        for (int j = 0; j < 8; j++) {
            mt0 = fmaxf(mt0, fmaxf(s[j][0], s[j][1]));
            mt1 = fmaxf(mt1, fmaxf(s[j][2], s[j][3]));
        }
        mt0 = fmaxf(mt0, __shfl_xor_sync(0xffffffffu, mt0, 1));
        mt0 = fmaxf(mt0, __shfl_xor_sync(0xffffffffu, mt0, 2));
        mt1 = fmaxf(mt1, __shfl_xor_sync(0xffffffffu, mt1, 1));
        mt1 = fmaxf(mt1, __shfl_xor_sync(0xffffffffu, mt1, 2));

        float mn0 = fmaxf(m0, mt0), mn1 = fmaxf(m1, mt1);
        float al0 = __expf(m0 - mn0), al1 = __expf(m1 - mn1);
        m0 = mn0; m1 = mn1;

        float ps0 = 0.f, ps1 = 0.f;
#pragma unroll
        for (int j = 0; j < 8; j++) {
            s[j][0] = __expf(s[j][0] - mn0);
            s[j][1] = __expf(s[j][1] - mn0);
            s[j][2] = __expf(s[j][2] - mn1);
            s[j][3] = __expf(s[j][3] - mn1);
            ps0 += s[j][0] + s[j][1];
            ps1 += s[j][2] + s[j][3];
        }
        ps0 += __shfl_xor_sync(0xffffffffu, ps0, 1);
        ps0 += __shfl_xor_sync(0xffffffffu, ps0, 2);
        ps1 += __shfl_xor_sync(0xffffffffu, ps1, 1);
        ps1 += __shfl_xor_sync(0xffffffffu, ps1, 2);
        l0 = l0 * al0 + ps0;
        l1 = l1 * al1 + ps1;

#pragma unroll
        for (int j = 0; j < 8; j++) {
            o[j][0] *= al0; o[j][1] *= al0;
            o[j][2] *= al1; o[j][3] *= al1;
        }

        // P -> smem (tf32), warp-local
#pragma unroll
        for (int j = 0; j < 8; j++) {
            int c0 = j*8 + cq*2;
            Pw[r*68 + c0]       = f2tf(s[j][0]);
            Pw[r*68 + c0 + 1]   = f2tf(s[j][1]);
            Pw[(r+8)*68 + c0]     = f2tf(s[j][2]);
            Pw[(r+8)*68 + c0 + 1] = f2tf(s[j][3]);
        }
        __syncwarp();

        // O += P @ V  (16 x 64 += 16x64 @ 64x64)
#pragma unroll
        for (int kk = 0; kk < 64; kk += 8) {
            unsigned a0 = Pw[r*68 + kk + cq];
            unsigned a1 = Pw[(r+8)*68 + kk + cq];
            unsigned a2 = Pw[r*68 + kk + cq + 4];
            unsigned a3 = Pw[(r+8)*68 + kk + cq + 4];
#pragma unroll
            for (int j = 0; j < 8; j++) {
                unsigned b0 = Vs[(kk+cq)*68 + j*8 + r];
                unsigned b1 = Vs[(kk+cq+4)*68 + j*8 + r];
                asm volatile(
                    "mma.sync.aligned.m16n8k8.row.col.f32.tf32.tf32.f32 "
                    "{%0,%1,%2,%3},{%4,%5,%6,%7},{%8,%9},{%0,%1,%2,%3};"
                    : "+f"(o[j][0]), "+f"(o[j][1]), "+f"(o[j][2]), "+f"(o[j][3])
                    : "r"(a0), "r"(a1), "r"(a2), "r"(a3), "r"(b0), "r"(b1));
            }
        }
        __syncwarp();
    }

    // epilogue: divide by l, write ctx[token][h*64 + dv]
    float inv0 = 1.f / l0, inv1 = 1.f / l1;
    size_t row0 = (tq + warp*16 + r) * (size_t)(H_*DH_) + h*DH_;
    size_t row1 = row0 + (size_t)8 * (H_*DH_);
#pragma unroll
    for (int j = 0; j < 8; j++) {
        int c0 = j*8 + cq*2;
        float2 v0; v0.x = o[j][0]*inv0; v0.y = o[j][1]*inv0;
        float2 v1; v1.x = o[j][2]*inv1; v1.y = o[j][3]*inv1;
        *(float2*)&ctx[row0 + c0] = v0;
        *(float2*)&ctx[row1 + c0] = v1;
    }
}

// ---------------- misc elementwise ----------------------------------------
__global__ void copy_k(const float4* __restrict__ src, float4* __restrict__ dst, int n4) {
    int i = blockIdx.x * blockDim.x + threadIdx.x;
    if (i < n4) dst[i] = src[i];
}

__global__ void zero_cnt_k(int* c) {
    if (threadIdx.x < NR_) c[threadIdx.x] = 0;
}

__global__ void silu_mul_k(const float* __restrict__ g, const float* __restrict__ u,
                           float* __restrict__ o, const int* __restrict__ cntPtr,
                           int fixedCnt) {
    int cnt = cntPtr ? *cntPtr : fixedCnt;
    long total = (long)cnt * DHID_;
    long i = (long)blockIdx.x * blockDim.x + threadIdx.x;
    if (i >= total) return;
    float gv = g[i], uv = u[i];
    o[i] = (gv / (1.f + __expf(-gv))) * uv;
}

// ---------------- gating: logits + softmax + top2 + routing lists ----------
__global__ void gate_topk_k(const float* __restrict__ h2, const float* __restrict__ gw,
                            int* __restrict__ cnt, int* __restrict__ elist,
                            float* __restrict__ ew) {
    int t = blockIdx.x * 8 + (threadIdx.x >> 5);
    int lane = threadIdx.x & 31;
    if (t >= T_) return;
    float acc[NR_];
#pragma unroll
    for (int e = 0; e < NR_; e++) acc[e] = 0.f;
    const float* hr = h2 + (size_t)t * D_;
    for (int d = lane; d < D_; d += 32) {
        float xv = hr[d];
        const float* g = gw + (size_t)d * NR_;
#pragma unroll
        for (int e = 0; e < NR_; e++) acc[e] += xv * g[e];
    }
#pragma unroll
    for (int e = 0; e < NR_; e++)
#pragma unroll
        for (int off = 16; off; off >>= 1)
            acc[e] += __shfl_xor_sync(0xffffffffu, acc[e], off);
    if (lane == 0) {
        int i1 = 0;
#pragma unroll
        for (int e = 1; e < NR_; e++) if (acc[e] > acc[i1]) i1 = e;
        int i2 = (i1 == 0) ? 1 : 0;
#pragma unroll
        for (int e = 0; e < NR_; e++) {
            if (e == i1 || e == i2) continue;
            if (acc[e] > acc[i2]) i2 = e;
        }
        float p2 = __expf(acc[i2] - acc[i1]);
        float inv = 1.f / (1.f + p2);
        float w1 = inv, w2 = p2 * inv;
        int pos = atomicAdd(&cnt[i1], 1);
        elist[i1*T_ + pos] = t; ew[i1*T_ + pos] = w1;
        pos = atomicAdd(&cnt[i2], 1);
        elist[i2*T_ + pos] = t; ew[i2*T_ + pos] = w2;
    }
}

// ---------------- launch ---------------------------------------------------
extern "C" void kernel_launch(void* const* d_in, const int* in_sizes, int n_in,
                              void* d_out, int out_size) {
    const float* x         = (const float*)d_in[0];
    const float* w_q       = (const float*)d_in[2];
    const float* w_dkv     = (const float*)d_in[3];
    const float* w_uk      = (const float*)d_in[4];
    const float* w_uv      = (const float*)d_in[5];
    const float* w_kr      = (const float*)d_in[6];
    const float* w_o       = (const float*)d_in[7];
    const float* attn_nw   = (const float*)d_in[8];
    const float* mlp_nw    = (const float*)d_in[9];
    const float* gate_w    = (const float*)d_in[10];
    const float* wr_gate   = (const float*)d_in[11];
    const float* wr_up     = (const float*)d_in[12];
    const float* wr_down   = (const float*)d_in[13];
    const float* ws_gate   = (const float*)d_in[14];
    const float* ws_up     = (const float*)d_in[15];
    const float* ws_down   = (const float*)d_in[16];
    float* out = (float*)d_out;

    float *ph, *pq, *plat, *pkc, *pv, *pkr, *pctx, *ph2, *pgb, *pub, *pew;
    int *pcnt, *pel;
    cudaGetSymbolAddress((void**)&ph,   g_h);
    cudaGetSymbolAddress((void**)&pq,   g_q);
    cudaGetSymbolAddress((void**)&plat, g_lat);
    cudaGetSymbolAddress((void**)&pkc,  g_kc);
    cudaGetSymbolAddress((void**)&pv,   g_v);
    cudaGetSymbolAddress((void**)&pkr,  g_kr);
    cudaGetSymbolAddress((void**)&pctx, g_ctx);
    cudaGetSymbolAddress((void**)&ph2,  g_h2);
    cudaGetSymbolAddress((void**)&pgb,  g_gb);
    cudaGetSymbolAddress((void**)&pub,  g_ub);
    cudaGetSymbolAddress((void**)&pcnt, g_cnt);
    cudaGetSymbolAddress((void**)&pel,  g_elist);
    cudaGetSymbolAddress((void**)&pew,  g_ew);

    cudaFuncSetAttribute(flash_mma_k,
                         cudaFuncAttributeMaxDynamicSharedMemorySize, FA_SMEM_BYTES);

    // 1) h = rmsnorm(x)
    rmsnorm_k<<<T_, 256>>>(x, attn_nw, ph);

    // 2) projections (tf32 tensor cores)
    mma128<false,false,false><<<dim3((H_*QDIM_)/128, T_/128), 256>>>(ph,   w_q,   pq,  H_*QDIM_, D_,  nullptr, nullptr, nullptr);
    mma128<false,false,false><<<dim3(DL_/128,        T_/128), 256>>>(ph,   w_dkv, plat, DL_,     D_,  nullptr, nullptr, nullptr);
    mma128<false,false,false><<<dim3((H_*DH_)/128,   T_/128), 256>>>(plat, w_uk,  pkc, H_*DH_,   DL_, nullptr, nullptr, nullptr);
    mma128<false,false,false><<<dim3((H_*DH_)/128,   T_/128), 256>>>(plat, w_uv,  pv,  H_*DH_,   DL_, nullptr, nullptr, nullptr);
    sgemm64<false><<<dim3(DR_/64, T_/64), 256>>>(ph, w_kr, pkr, DR_, D_);

    // 3) RoPE on q tail + k_r
    {
        int n = T_*H_*32 + T_*32;
        rope_k<<<(n + 255)/256, 256>>>(pq, pkr);
    }

    // 4) attention -> ctx (tensor-core flash)
    flash_mma_k<<<dim3(S_/64, B_*H_), 128, FA_SMEM_BYTES>>>(pq, pkc, pkr, pv, pctx);

    // 5) out = x; out += ctx @ w_o
    copy_k<<<(T_*D_/4 + 255)/256, 256>>>((const float4*)x, (float4*)out, T_*D_/4);
    mma128<true,false,false><<<dim3(D_/128, T_/128), 256>>>(pctx, w_o, out, D_, D_, nullptr, nullptr, nullptr);

    // 6) h2 = rmsnorm(out)
    rmsnorm_k<<<T_, 256>>>(out, mlp_nw, ph2);

    // 7) routing
    zero_cnt_k<<<1, 32>>>(pcnt);
    gate_topk_k<<<T_/8, 256>>>(ph2, gate_w, pcnt, pel, pew);

    // 8) shared experts (dense)
    for (int s = 0; s < NS_; s++) {
        const float* wg = ws_gate + (size_t)s * D_ * DHID_;
        const float* wu = ws_up   + (size_t)s * D_ * DHID_;
        const float* wd = ws_down + (size_t)s * DHID_ * D_;
        mma128<false,false,false><<<dim3(DHID_/128, T_/128), 256>>>(ph2, wg, pgb, DHID_, D_, nullptr, nullptr, nullptr);
        mma128<false,false,false><<<dim3(DHID_/128, T_/128), 256>>>(ph2, wu, pub, DHID_, D_, nullptr, nullptr, nullptr);
        silu_mul_k<<<(T_*DHID_ + 255)/256, 256>>>(pgb, pub, pgb, nullptr, T_);
        mma128<true,false,false><<<dim3(D_/128, T_/128), 256>>>(pgb, wd, out, D_, DHID_, nullptr, nullptr, nullptr);
    }

    // 9) routed experts (sparse top-2, gather/scatter)
    for (int e = 0; e < NR_; e++) {
        const float* wg = wr_gate + (size_t)e * D_ * DHID_;
        const float* wu = wr_up   + (size_t)e * D_ * DHID_;
        const float* wd = wr_down + (size_t)e * DHID_ * D_;
        const int*   idx = pel + e * T_;
        const float* wts = pew + e * T_;
        const int*   cp  = pcnt + e;
        mma128<false,true, false><<<dim3(DHID_/128, T_/128), 256>>>(ph2, wg, pgb, DHID_, D_, idx, nullptr, cp);
        mma128<false,true, false><<<dim3(DHID_/128, T_/128), 256>>>(ph2, wu, pub, DHID_, D_, idx, nullptr, cp);
        silu_mul_k<<<(T_*DHID_ + 255)/256, 256>>>(pgb, pub, pgb, cp, 0);
        mma128<false,false,true ><<<dim3(D_/128, T_/128), 256>>>(pgb, wd, out, D_, DHID_, idx, wts, cp);
    }
}

// round 8
// speedup vs baseline: 2.5344x; 1.5990x over previous
#include <cuda_runtime.h>
#include <math.h>

#define B_ 2
#define S_ 2048
#define D_ 1024
#define H_ 16
#define DH_ 64
#define DR_ 64
#define DL_ 512
#define DHID_ 512
#define NR_ 8
#define NS_ 2
#define T_ (B_*S_)          // 4096 tokens
#define QDIM_ (DH_+DR_)     // 128

// ---------------- scratch (device globals; no allocation allowed) ----------
__device__ float g_h  [T_*D_];
__device__ float g_q  [T_*H_*QDIM_];
__device__ float g_lat[T_*DL_];
__device__ float g_kc [T_*H_*DH_];
__device__ float g_v  [T_*H_*DH_];
__device__ float g_kr [T_*DR_];
__device__ float g_ctx[T_*H_*DH_];
__device__ float g_h2 [T_*D_];
__device__ float g_gb [T_*DHID_];
__device__ float g_ub [T_*DHID_];
__device__ int   g_cnt[NR_];
__device__ int   g_elist[NR_*T_];
__device__ float g_ew  [NR_*T_];

__device__ __forceinline__ unsigned f2tf(float x) {
    unsigned r;
    asm("cvt.rna.tf32.f32 %0, %1;" : "=r"(r) : "f"(x));
    return r;
}

// ---------------- rmsnorm --------------------------------------------------
__global__ void rmsnorm_k(const float* __restrict__ x, const float* __restrict__ w,
                          float* __restrict__ o) {
    int row = blockIdx.x;
    const float* xr = x + (size_t)row * D_;
    float ss = 0.f;
    float vloc[4];
#pragma unroll
    for (int i = 0; i < 4; i++) { vloc[i] = xr[threadIdx.x + i*256]; ss += vloc[i]*vloc[i]; }
#pragma unroll
    for (int off = 16; off; off >>= 1) ss += __shfl_xor_sync(0xffffffffu, ss, off);
    __shared__ float sm[8];
    __shared__ float invs;
    if ((threadIdx.x & 31) == 0) sm[threadIdx.x >> 5] = ss;
    __syncthreads();
    if (threadIdx.x == 0) {
        float t = 0.f;
#pragma unroll
        for (int i = 0; i < 8; i++) t += sm[i];
        invs = 1.0f / sqrtf(t / (float)D_ + 1e-6f);
    }
    __syncthreads();
    float inv = invs;
    float* orow = o + (size_t)row * D_;
#pragma unroll
    for (int i = 0; i < 4; i++) {
        int d = threadIdx.x + i*256;
        orow[d] = vloc[i] * inv * w[d];
    }
}

// ---------------- small fp32 SGEMM for N=64 (w_kr only) --------------------
template<bool ACC>
__global__ void sgemm64(const float* __restrict__ A, const float* __restrict__ Bm,
                        float* __restrict__ C, int N, int K) {
    __shared__ float As[16][64];
    __shared__ float Bs[16][64];
    int tid = threadIdx.x;
    int bx = blockIdx.x, by = blockIdx.y;
    int tx = tid & 15, ty = tid >> 4;
    float acc[4][4];
#pragma unroll
    for (int i = 0; i < 4; i++)
#pragma unroll
        for (int j = 0; j < 4; j++) acc[i][j] = 0.f;

    int aRow = tid >> 2;
    int aCol = (tid & 3) * 4;
    const float* Aptr = A + (size_t)(by*64 + aRow) * K + aCol;
    int bRow = tid >> 4;
    int bCol = (tid & 15) * 4;
    const float* Bptr = Bm + (size_t)bRow * N + bx*64 + bCol;

    for (int k0 = 0; k0 < K; k0 += 16) {
        float4 av = *(const float4*)Aptr;
        float4 bv = *(const float4*)Bptr;
        As[aCol+0][aRow] = av.x; As[aCol+1][aRow] = av.y;
        As[aCol+2][aRow] = av.z; As[aCol+3][aRow] = av.w;
        *(float4*)&Bs[bRow][bCol] = bv;
        __syncthreads();
#pragma unroll
        for (int k = 0; k < 16; k++) {
            float4 a4 = *(const float4*)&As[k][ty*4];
            float4 b4 = *(const float4*)&Bs[k][tx*4];
            float ar[4] = {a4.x, a4.y, a4.z, a4.w};
            float br[4] = {b4.x, b4.y, b4.z, b4.w};
#pragma unroll
            for (int i = 0; i < 4; i++)
#pragma unroll
                for (int j = 0; j < 4; j++) acc[i][j] += ar[i]*br[j];
        }
        __syncthreads();
        Aptr += 16;
        Bptr += (size_t)16 * N;
    }
#pragma unroll
    for (int i = 0; i < 4; i++) {
        float* cp = C + (size_t)(by*64 + ty*4 + i) * N + bx*64 + tx*4;
#pragma unroll
        for (int j = 0; j < 4; j++) {
            if (ACC) cp[j] += acc[i][j]; else cp[j] = acc[i][j];
        }
    }
}

// ------ tf32 tensor-core GEMM: 128x128x16, double-buffered smem ------------
// Dadd (runtime, non-expert only): C = Dadd + acc (fused residual).
template<bool ACC, bool GATHER, bool SCATTER>
__global__ __launch_bounds__(256, 2) void mma128(
        const float* __restrict__ A, const float* __restrict__ Bm,
        float* __restrict__ C, int N, int K,
        const int* __restrict__ idx, const float* __restrict__ wts,
        const int* __restrict__ cntPtr, const float* __restrict__ Dadd) {
    constexpr bool EXPERT = GATHER || SCATTER;
    int cnt = 0;
    if (EXPERT) {
        cnt = *cntPtr;
        if ((int)blockIdx.y * 128 >= cnt) return;
    }
    __shared__ unsigned As[2][16][136];
    __shared__ unsigned Bs[2][16][136];

    int tid = threadIdx.x;
    int bx = blockIdx.x, by = blockIdx.y;
    int warp = tid >> 5, lane = tid & 31;
    int wm = warp & 3;
    int wn = warp >> 2;
    int r  = lane >> 2;
    int cq = lane & 3;

    float acc[2][8][4];
#pragma unroll
    for (int i = 0; i < 2; i++)
#pragma unroll
        for (int j = 0; j < 8; j++)
#pragma unroll
            for (int k = 0; k < 4; k++) acc[i][j][k] = 0.f;

    int ar = tid >> 1;
    int ac = (tid & 1) * 8;
    int gRowA = by*128 + ar;
    int rowA;
    if (GATHER) {
        int rs = (gRowA < cnt) ? gRowA : (cnt - 1);
        rowA = idx[rs];
    } else if (SCATTER) {
        rowA = (gRowA < cnt) ? gRowA : (cnt - 1);
    } else {
        rowA = gRowA;
    }
    const float* Ap = A + (size_t)rowA * K + ac;

    int br = tid >> 4;
    int bc = (tid & 15) * 8;
    const float* Bp = Bm + (size_t)br * N + bx*128 + bc;

    int ntiles = K >> 4;

    // prologue: load + store tile 0 into stage 0
    float4 pa0 = *(const float4*)Ap;
    float4 pa1 = *(const float4*)(Ap + 4);
    float4 pb0 = *(const float4*)Bp;
    float4 pb1 = *(const float4*)(Bp + 4);
    As[0][ac+0][ar] = f2tf(pa0.x); As[0][ac+1][ar] = f2tf(pa0.y);
    As[0][ac+2][ar] = f2tf(pa0.z); As[0][ac+3][ar] = f2tf(pa0.w);
    As[0][ac+4][ar] = f2tf(pa1.x); As[0][ac+5][ar] = f2tf(pa1.y);
    As[0][ac+6][ar] = f2tf(pa1.z); As[0][ac+7][ar] = f2tf(pa1.w);
    {
        uint4 u0 = {f2tf(pb0.x), f2tf(pb0.y), f2tf(pb0.z), f2tf(pb0.w)};
        uint4 u1 = {f2tf(pb1.x), f2tf(pb1.y), f2tf(pb1.z), f2tf(pb1.w)};
        *(uint4*)&Bs[0][br][bc]     = u0;
        *(uint4*)&Bs[0][br][bc + 4] = u1;
    }

    for (int kt = 0; kt < ntiles; kt++) {
        int st = kt & 1;
        __syncthreads();   // stage st fully stored; stage st^1's last readers done

        bool more = (kt + 1 < ntiles);
        if (more) {        // LDG for next tile, latency hidden under compute
            Ap += 16;
            Bp += (size_t)16 * N;
            pa0 = *(const float4*)Ap;
            pa1 = *(const float4*)(Ap + 4);
            pb0 = *(const float4*)Bp;
            pb1 = *(const float4*)(Bp + 4);
        }

#pragma unroll
        for (int kk = 0; kk < 16; kk += 8) {
            unsigned a[2][4];
#pragma unroll
            for (int i = 0; i < 2; i++) {
                int m0 = wm*32 + i*16 + r;
                a[i][0] = As[st][kk+cq  ][m0];
                a[i][1] = As[st][kk+cq  ][m0 + 8];
                a[i][2] = As[st][kk+cq+4][m0];
                a[i][3] = As[st][kk+cq+4][m0 + 8];
            }
#pragma unroll
            for (int j = 0; j < 8; j++) {
                int n0 = wn*64 + j*8 + r;
                unsigned b0 = Bs[st][kk+cq  ][n0];
                unsigned b1 = Bs[st][kk+cq+4][n0];
#pragma unroll
                for (int i = 0; i < 2; i++) {
                    asm volatile(
                        "mma.sync.aligned.m16n8k8.row.col.f32.tf32.tf32.f32 "
                        "{%0,%1,%2,%3},{%4,%5,%6,%7},{%8,%9},{%0,%1,%2,%3};"
                        : "+f"(acc[i][j][0]), "+f"(acc[i][j][1]),
                          "+f"(acc[i][j][2]), "+f"(acc[i][j][3])
                        : "r"(a[i][0]), "r"(a[i][1]), "r"(a[i][2]), "r"(a[i][3]),
                          "r"(b0), "r"(b1));
                }
            }
        }

        if (more) {        // store next tile into the other stage (safe: its
            int ns = st ^ 1;   // last readers passed the barrier above)
            As[ns][ac+0][ar] = f2tf(pa0.x); As[ns][ac+1][ar] = f2tf(pa0.y);
            As[ns][ac+2][ar] = f2tf(pa0.z); As[ns][ac+3][ar] = f2tf(pa0.w);
            As[ns][ac+4][ar] = f2tf(pa1.x); As[ns][ac+5][ar] = f2tf(pa1.y);
            As[ns][ac+6][ar] = f2tf(pa1.z); As[ns][ac+7][ar] = f2tf(pa1.w);
            uint4 u0 = {f2tf(pb0.x), f2tf(pb0.y), f2tf(pb0.z), f2tf(pb0.w)};
            uint4 u1 = {f2tf(pb1.x), f2tf(pb1.y), f2tf(pb1.z), f2tf(pb1.w)};
            *(uint4*)&Bs[ns][br][bc]     = u0;
            *(uint4*)&Bs[ns][br][bc + 4] = u1;
        }
    }

#pragma unroll
    for (int i = 0; i < 2; i++) {
        int lrow = wm*32 + i*16 + r;
        int gr0 = by*128 + lrow;
        int gr1 = gr0 + 8;
#pragma unroll
        for (int half = 0; half < 2; half++) {
            int gr = half ? gr1 : gr0;
            if (EXPERT && gr >= cnt) continue;
            int crow;
            float wscale = 1.f;
            if (SCATTER) { crow = idx[gr]; wscale = wts[gr]; }
            else         { crow = gr; }
            float* cbase = C + (size_t)crow * N + bx*128 + wn*64;
            const float* dbase = Dadd ? (Dadd + (size_t)crow * N + bx*128 + wn*64)
                                      : nullptr;
#pragma unroll
            for (int j = 0; j < 8; j++) {
                float v0 = acc[i][j][half*2 + 0];
                float v1 = acc[i][j][half*2 + 1];
                float2* p = (float2*)(cbase + j*8 + cq*2);
                if (SCATTER) {
                    float2 old = *p;
                    old.x += wscale * v0;
                    old.y += wscale * v1;
                    *p = old;
                } else if (ACC) {
                    float2 old = *p;
                    old.x += v0; old.y += v1;
                    *p = old;
                } else if (dbase) {
                    float2 dv = *(const float2*)(dbase + j*8 + cq*2);
                    float2 nv; nv.x = dv.x + v0; nv.y = dv.y + v1;
                    *p = nv;
                } else {
                    float2 nv; nv.x = v0; nv.y = v1;
                    *p = nv;
                }
            }
        }
    }
}

// ---------------- RoPE (in-place on q tail + k_r) --------------------------
__global__ void rope_k(float* __restrict__ q, float* __restrict__ kr) {
    int p = blockIdx.x * blockDim.x + threadIdx.x;
    const int NQ = T_ * H_ * 32;
    const int NK = T_ * 32;
    if (p < NQ) {
        int i = p & 31;
        int h = (p >> 5) & (H_ - 1);
        int t = p >> 9;
        int s = t & (S_ - 1);
        float inv = powf(10000.0f, -(float)i / 32.0f);
        float sn, c;
        sincosf((float)s * inv, &sn, &c);
        float* base = q + (size_t)t * (H_*QDIM_) + h * QDIM_ + DH_;
        float t1 = base[i], t2 = base[32 + i];
        base[i]      = t1 * c - t2 * sn;
        base[32 + i] = t2 * c + t1 * sn;
    } else if (p < NQ + NK) {
        int p2 = p - NQ;
        int i = p2 & 31;
        int t = p2 >> 5;
        int s = t & (S_ - 1);
        float inv = powf(10000.0f, -(float)i / 32.0f);
        float sn, c;
        sincosf((float)s * inv, &sn, &c);
        float* base = kr + (size_t)t * DR_;
        float t1 = base[i], t2 = base[32 + i];
        base[i]      = t1 * c - t2 * sn;
        base[32 + i] = t2 * c + t1 * sn;
    }
}

// ---------------- tensor-core flash attention (causal, d=128, dv=64) -------
#define FA_SMEM_FLOATS (64*132 + 64*132 + 64*68 + 4*16*68)
#define FA_SMEM_BYTES  (FA_SMEM_FLOATS*4)

__global__ __launch_bounds__(128) void flash_mma_k(
        const float* __restrict__ q, const float* __restrict__ kc,
        const float* __restrict__ kr, const float* __restrict__ v,
        float* __restrict__ ctx) {
    extern __shared__ unsigned smbuf[];
    unsigned* Qs = smbuf;                 // [64][132]
    unsigned* Ks = Qs + 64*132;           // [64][132]
    unsigned* Vs = Ks + 64*132;           // [64][68]
    unsigned* Ps = Vs + 64*68;            // [4][16][68]

    int qb = blockIdx.x;
    int bh = blockIdx.y;
    int b = bh >> 4, h = bh & 15;
    int tid = threadIdx.x;
    int warp = tid >> 5, lane = tid & 31;
    int r = lane >> 2, cq = lane & 3;
    size_t tq = (size_t)b*S_ + qb*64;
    unsigned* Pw = Ps + warp*16*68;

#pragma unroll
    for (int i = 0; i < 16; i++) {
        int e = i*128 + tid;
        int row = e >> 5, c4 = (e & 31) * 4;
        float4 qv = *(const float4*)&q[(tq+row)*(size_t)(H_*QDIM_) + h*QDIM_ + c4];
        unsigned* dst = &Qs[row*132 + c4];
        dst[0]=f2tf(qv.x); dst[1]=f2tf(qv.y); dst[2]=f2tf(qv.z); dst[3]=f2tf(qv.w);
    }

    float m0 = -1e30f, m1 = -1e30f;
    float l0 = 0.f,  l1 = 0.f;
    float o[8][4];
#pragma unroll
    for (int j = 0; j < 8; j++)
#pragma unroll
        for (int k = 0; k < 4; k++) o[j][k] = 0.f;

    const float scale = 0.088388347648318447f;   // 1/sqrt(128)
    int nkb = qb + 1;

    for (int kb = 0; kb < nkb; kb++) {
        size_t tk = (size_t)b*S_ + kb*64;
        __syncthreads();
#pragma unroll
        for (int i = 0; i < 8; i++) {
            int e = i*128 + tid;
            int row = e >> 4, c4 = (e & 15) * 4;
            float4 kv = *(const float4*)&kc[(tk+row)*(size_t)(H_*DH_) + h*DH_ + c4];
            unsigned* dst = &Ks[row*132 + c4];
            dst[0]=f2tf(kv.x); dst[1]=f2tf(kv.y); dst[2]=f2tf(kv.z); dst[3]=f2tf(kv.w);
        }
#pragma unroll
        for (int i = 0; i < 8; i++) {
            int e = i*128 + tid;
            int row = e >> 4, c4 = (e & 15) * 4;
            float4 kv = *(const float4*)&kr[(tk+row)*(size_t)DR_ + c4];
            unsigned* dst = &Ks[row*132 + 64 + c4];
            dst[0]=f2tf(kv.x); dst[1]=f2tf(kv.y); dst[2]=f2tf(kv.z); dst[3]=f2tf(kv.w);
        }
#pragma unroll
        for (int i = 0; i < 8; i++) {
            int e = i*128 + tid;
            int row = e >> 4, c4 = (e & 15) * 4;
            float4 vv = *(const float4*)&v[(tk+row)*(size_t)(H_*DH_) + h*DH_ + c4];
            unsigned* dst = &Vs[row*68 + c4];
            dst[0]=f2tf(vv.x); dst[1]=f2tf(vv.y); dst[2]=f2tf(vv.z); dst[3]=f2tf(vv.w);
        }
        __syncthreads();

        float s[8][4];
#pragma unroll
        for (int j = 0; j < 8; j++)
#pragma unroll
            for (int k = 0; k < 4; k++) s[j][k] = 0.f;

#pragma unroll
        for (int kk = 0; kk < 128; kk += 8) {
            int m0r = (warp*16 + r)*132;
            unsigned a0 = Qs[m0r + kk + cq];
            unsigned a1 = Qs[m0r + 8*132 + kk + cq];
            unsigned a2 = Qs[m0r + kk + cq + 4];
            unsigned a3 = Qs[m0r + 8*132 + kk + cq + 4];
#pragma unroll
            for (int j = 0; j < 8; j++) {
                unsigned b0 = Ks[(j*8 + r)*132 + kk + cq];
                unsigned b1 = Ks[(j*8 + r)*132 + kk + cq + 4];
                asm volatile(
                    "mma.sync.aligned.m16n8k8.row.col.f32.tf32.tf32.f32 "
                    "{%0,%1,%2,%3},{%4,%5,%6,%7},{%8,%9},{%0,%1,%2,%3};"
                    : "+f"(s[j][0]), "+f"(s[j][1]), "+f"(s[j][2]), "+f"(s[j][3])
                    : "r"(a0), "r"(a1), "r"(a2), "r"(a3), "r"(b0), "r"(b1));
            }
        }

        bool diag = (kb == qb);
        int lq0 = warp*16 + r;
        int lq1 = lq0 + 8;
#pragma unroll
        for (int j = 0; j < 8; j++) {
            int c0 = j*8 + cq*2, c1 = c0 + 1;
            s[j][0] *= scale; s[j][1] *= scale;
            s[j][2] *= scale; s[j][3] *= scale;
            if (diag) {
                if (c0 > lq0) s[j][0] = -1e9f;
                if (c1 > lq0) s[j][1] = -1e9f;
                if (c0 > lq1) s[j][2] = -1e9f;
                if (c1 > lq1) s[j][3] = -1e9f;
            }
        }

        float mt0 = -1e30f, mt1 = -1e30f;
#pragma unroll
        for (int j = 0; j < 8; j++) {
            mt0 = fmaxf(mt0, fmaxf(s[j][0], s[j][1]));
            mt1 = fmaxf(mt1, fmaxf(s[j][2], s[j][3]));
        }
        mt0 = fmaxf(mt0, __shfl_xor_sync(0xffffffffu, mt0, 1));
        mt0 = fmaxf(mt0, __shfl_xor_sync(0xffffffffu, mt0, 2));
        mt1 = fmaxf(mt1, __shfl_xor_sync(0xffffffffu, mt1, 1));
        mt1 = fmaxf(mt1, __shfl_xor_sync(0xffffffffu, mt1, 2));

        float mn0 = fmaxf(m0, mt0), mn1 = fmaxf(m1, mt1);
        float al0 = __expf(m0 - mn0), al1 = __expf(m1 - mn1);
        m0 = mn0; m1 = mn1;

        float ps0 = 0.f, ps1 = 0.f;
#pragma unroll
        for (int j = 0; j < 8; j++) {
            s[j][0] = __expf(s[j][0] - mn0);
            s[j][1] = __expf(s[j][1] - mn0);
            s[j][2] = __expf(s[j][2] - mn1);
            s[j][3] = __expf(s[j][3] - mn1);
            ps0 += s[j][0] + s[j][1];
            ps1 += s[j][2] + s[j][3];
        }
        ps0 += __shfl_xor_sync(0xffffffffu, ps0, 1);
        ps0 += __shfl_xor_sync(0xffffffffu, ps0, 2);
        ps1 += __shfl_xor_sync(0xffffffffu, ps1, 1);
        ps1 += __shfl_xor_sync(0xffffffffu, ps1, 2);
        l0 = l0 * al0 + ps0;
        l1 = l1 * al1 + ps1;

#pragma unroll
        for (int j = 0; j < 8; j++) {
            o[j][0] *= al0; o[j][1] *= al0;
            o[j][2] *= al1; o[j][3] *= al1;
        }

#pragma unroll
        for (int j = 0; j < 8; j++) {
            int c0 = j*8 + cq*2;
            Pw[r*68 + c0]       = f2tf(s[j][0]);
            Pw[r*68 + c0 + 1]   = f2tf(s[j][1]);
            Pw[(r+8)*68 + c0]     = f2tf(s[j][2]);
            Pw[(r+8)*68 + c0 + 1] = f2tf(s[j][3]);
        }
        __syncwarp();

#pragma unroll
        for (int kk = 0; kk < 64; kk += 8) {
            unsigned a0 = Pw[r*68 + kk + cq];
            unsigned a1 = Pw[(r+8)*68 + kk + cq];
            unsigned a2 = Pw[r*68 + kk + cq + 4];
            unsigned a3 = Pw[(r+8)*68 + kk + cq + 4];
#pragma unroll
            for (int j = 0; j < 8; j++) {
                unsigned b0 = Vs[(kk+cq)*68 + j*8 + r];
                unsigned b1 = Vs[(kk+cq+4)*68 + j*8 + r];
                asm volatile(
                    "mma.sync.aligned.m16n8k8.row.col.f32.tf32.tf32.f32 "
                    "{%0,%1,%2,%3},{%4,%5,%6,%7},{%8,%9},{%0,%1,%2,%3};"
                    : "+f"(o[j][0]), "+f"(o[j][1]), "+f"(o[j][2]), "+f"(o[j][3])
                    : "r"(a0), "r"(a1), "r"(a2), "r"(a3), "r"(b0), "r"(b1));
            }
        }
        __syncwarp();
    }

    float inv0 = 1.f / l0, inv1 = 1.f / l1;
    size_t row0 = (tq + warp*16 + r) * (size_t)(H_*DH_) + h*DH_;
    size_t row1 = row0 + (size_t)8 * (H_*DH_);
#pragma unroll
    for (int j = 0; j < 8; j++) {
        int c0 = j*8 + cq*2;
        float2 v0; v0.x = o[j][0]*inv0; v0.y = o[j][1]*inv0;
        float2 v1; v1.x = o[j][2]*inv1; v1.y = o[j][3]*inv1;
        *(float2*)&ctx[row0 + c0] = v0;
        *(float2*)&ctx[row1 + c0] = v1;
    }
}

// ---------------- misc elementwise ----------------------------------------
__global__ void zero_cnt_k(int* c) {
    if (threadIdx.x < NR_) c[threadIdx.x] = 0;
}

__global__ void silu_mul_k(const float* __restrict__ g, const float* __restrict__ u,
                           float* __restrict__ o, const int* __restrict__ cntPtr,
                           int fixedCnt) {
    int cnt = cntPtr ? *cntPtr : fixedCnt;
    long total = (long)cnt * DHID_;
    long i = (long)blockIdx.x * blockDim.x + threadIdx.x;
    if (i >= total) return;
    float gv = g[i], uv = u[i];
    o[i] = (gv / (1.f + __expf(-gv))) * uv;
}

// ---------------- gating: logits + softmax + top2 + routing lists ----------
__global__ void gate_topk_k(const float* __restrict__ h2, const float* __restrict__ gw,
                            int* __restrict__ cnt, int* __restrict__ elist,
                            float* __restrict__ ew) {
    int t = blockIdx.x * 8 + (threadIdx.x >> 5);
    int lane = threadIdx.x & 31;
    if (t >= T_) return;
    float acc[NR_];
#pragma unroll
    for (int e = 0; e < NR_; e++) acc[e] = 0.f;
    const float* hr = h2 + (size_t)t * D_;
    for (int d = lane; d < D_; d += 32) {
        float xv = hr[d];
        const float* g = gw + (size_t)d * NR_;
#pragma unroll
        for (int e = 0; e < NR_; e++) acc[e] += xv * g[e];
    }
#pragma unroll
    for (int e = 0; e < NR_; e++)
#pragma unroll
        for (int off = 16; off; off >>= 1)
            acc[e] += __shfl_xor_sync(0xffffffffu, acc[e], off);
    if (lane == 0) {
        int i1 = 0;
#pragma unroll
        for (int e = 1; e < NR_; e++) if (acc[e] > acc[i1]) i1 = e;
        int i2 = (i1 == 0) ? 1 : 0;
#pragma unroll
        for (int e = 0; e < NR_; e++) {
            if (e == i1 || e == i2) continue;
            if (acc[e] > acc[i2]) i2 = e;
        }
        float p2 = __expf(acc[i2] - acc[i1]);
        float inv = 1.f / (1.f + p2);
        float w1 = inv, w2 = p2 * inv;
        int pos = atomicAdd(&cnt[i1], 1);
        elist[i1*T_ + pos] = t; ew[i1*T_ + pos] = w1;
        pos = atomicAdd(&cnt[i2], 1);
        elist[i2*T_ + pos] = t; ew[i2*T_ + pos] = w2;
    }
}

// ---------------- launch ---------------------------------------------------
extern "C" void kernel_launch(void* const* d_in, const int* in_sizes, int n_in,
                              void* d_out, int out_size) {
    const float* x         = (const float*)d_in[0];
    const float* w_q       = (const float*)d_in[2];
    const float* w_dkv     = (const float*)d_in[3];
    const float* w_uk      = (const float*)d_in[4];
    const float* w_uv      = (const float*)d_in[5];
    const float* w_kr      = (const float*)d_in[6];
    const float* w_o       = (const float*)d_in[7];
    const float* attn_nw   = (const float*)d_in[8];
    const float* mlp_nw    = (const float*)d_in[9];
    const float* gate_w    = (const float*)d_in[10];
    const float* wr_gate   = (const float*)d_in[11];
    const float* wr_up     = (const float*)d_in[12];
    const float* wr_down   = (const float*)d_in[13];
    const float* ws_gate   = (const float*)d_in[14];
    const float* ws_up     = (const float*)d_in[15];
    const float* ws_down   = (const float*)d_in[16];
    float* out = (float*)d_out;

    float *ph, *pq, *plat, *pkc, *pv, *pkr, *pctx, *ph2, *pgb, *pub, *pew;
    int *pcnt, *pel;
    cudaGetSymbolAddress((void**)&ph,   g_h);
    cudaGetSymbolAddress((void**)&pq,   g_q);
    cudaGetSymbolAddress((void**)&plat, g_lat);
    cudaGetSymbolAddress((void**)&pkc,  g_kc);
    cudaGetSymbolAddress((void**)&pv,   g_v);
    cudaGetSymbolAddress((void**)&pkr,  g_kr);
    cudaGetSymbolAddress((void**)&pctx, g_ctx);
    cudaGetSymbolAddress((void**)&ph2,  g_h2);
    cudaGetSymbolAddress((void**)&pgb,  g_gb);
    cudaGetSymbolAddress((void**)&pub,  g_ub);
    cudaGetSymbolAddress((void**)&pcnt, g_cnt);
    cudaGetSymbolAddress((void**)&pel,  g_elist);
    cudaGetSymbolAddress((void**)&pew,  g_ew);

    cudaFuncSetAttribute(flash_mma_k,
                         cudaFuncAttributeMaxDynamicSharedMemorySize, FA_SMEM_BYTES);

    // 1) h = rmsnorm(x)
    rmsnorm_k<<<T_, 256>>>(x, attn_nw, ph);

    // 2) projections (tf32 tensor cores, double-buffered)
    mma128<false,false,false><<<dim3((H_*QDIM_)/128, T_/128), 256>>>(ph,   w_q,   pq,  H_*QDIM_, D_,  nullptr, nullptr, nullptr, nullptr);
    mma128<false,false,false><<<dim3(DL_/128,        T_/128), 256>>>(ph,   w_dkv, plat, DL_,     D_,  nullptr, nullptr, nullptr, nullptr);
    mma128<false,false,false><<<dim3((H_*DH_)/128,   T_/128), 256>>>(plat, w_uk,  pkc, H_*DH_,   DL_, nullptr, nullptr, nullptr, nullptr);
    mma128<false,false,false><<<dim3((H_*DH_)/128,   T_/128), 256>>>(plat, w_uv,  pv,  H_*DH_,   DL_, nullptr, nullptr, nullptr, nullptr);
    sgemm64<false><<<dim3(DR_/64, T_/64), 256>>>(ph, w_kr, pkr, DR_, D_);

    // 3) RoPE on q tail + k_r
    {
        int n = T_*H_*32 + T_*32;
        rope_k<<<(n + 255)/256, 256>>>(pq, pkr);
    }

    // 4) attention -> ctx (tensor-core flash)
    flash_mma_k<<<dim3(S_/64, B_*H_), 128, FA_SMEM_BYTES>>>(pq, pkc, pkr, pv, pctx);

    // 5) out = x + ctx @ w_o (residual fused into epilogue)
    mma128<false,false,false><<<dim3(D_/128, T_/128), 256>>>(pctx, w_o, out, D_, D_, nullptr, nullptr, nullptr, x);

    // 6) h2 = rmsnorm(out)
    rmsnorm_k<<<T_, 256>>>(out, mlp_nw, ph2);

    // 7) routing
    zero_cnt_k<<<1, 32>>>(pcnt);
    gate_topk_k<<<T_/8, 256>>>(ph2, gate_w, pcnt, pel, pew);

    // 8) shared experts (dense)
    for (int s = 0; s < NS_; s++) {
        const float* wg = ws_gate + (size_t)s * D_ * DHID_;
        const float* wu = ws_up   + (size_t)s * D_ * DHID_;
        const float* wd = ws_down + (size_t)s * DHID_ * D_;
        mma128<false,false,false><<<dim3(DHID_/128, T_/128), 256>>>(ph2, wg, pgb, DHID_, D_, nullptr, nullptr, nullptr, nullptr);
        mma128<false,false,false><<<dim3(DHID_/128, T_/128), 256>>>(ph2, wu, pub, DHID_, D_, nullptr, nullptr, nullptr, nullptr);
        silu_mul_k<<<(T_*DHID_ + 255)/256, 256>>>(pgb, pub, pgb, nullptr, T_);
        mma128<true,false,false><<<dim3(D_/128, T_/128), 256>>>(pgb, wd, out, D_, DHID_, nullptr, nullptr, nullptr, nullptr);
    }

    // 9) routed experts (sparse top-2, gather/scatter)
    for (int e = 0; e < NR_; e++) {
        const float* wg = wr_gate + (size_t)e * D_ * DHID_;
        const float* wu = wr_up   + (size_t)e * D_ * DHID_;
        const float* wd = wr_down + (size_t)e * DHID_ * D_;
        const int*   idx = pel + e * T_;
        const float* wts = pew + e * T_;
        const int*   cp  = pcnt + e;
        mma128<false,true, false><<<dim3(DHID_/128, T_/128), 256>>>(ph2, wg, pgb, DHID_, D_, idx, nullptr, cp, nullptr);
        mma128<false,true, false><<<dim3(DHID_/128, T_/128), 256>>>(ph2, wu, pub, DHID_, D_, idx, nullptr, cp, nullptr);
        silu_mul_k<<<(T_*DHID_ + 255)/256, 256>>>(pgb, pub, pgb, cp, 0);
        mma128<false,false,true ><<<dim3(D_/128, T_/128), 256>>>(pgb, wd, out, D_, DHID_, idx, wts, cp, nullptr);
    }
}

// round 9
// speedup vs baseline: 4.3784x; 1.7276x over previous
#include <cuda_runtime.h>
#include <math.h>

#define B_ 2
#define S_ 2048
#define D_ 1024
#define H_ 16
#define DH_ 64
#define DR_ 64
#define DL_ 512
#define DHID_ 512
#define NR_ 8
#define NS_ 2
#define T_ (B_*S_)          // 4096 tokens
#define QDIM_ (DH_+DR_)     // 128

// ---------------- scratch (device globals; no allocation allowed) ----------
__device__ float g_h  [T_*D_];
__device__ float g_q  [T_*H_*QDIM_];
__device__ float g_lat[T_*DL_];
__device__ float g_kc [T_*H_*DH_];
__device__ float g_v  [T_*H_*DH_];
__device__ float g_kr [T_*DR_];
__device__ float g_ctx[T_*H_*DH_];
__device__ float g_h2 [T_*D_];
__device__ int   g_cnt[NR_];
__device__ int   g_elist[NR_*T_];
__device__ int   g_rt  [T_*4];        // per-token (e1,pos1,e2,pos2)
__device__ float g_rw  [T_*2];        // per-token (w1,w2)
// shared experts
__device__ float g_gsh[NS_*T_*DHID_];
__device__ float g_ush[NS_*T_*DHID_];
__device__ float g_ysh[NS_*T_*D_];
// routed experts (compact per-expert regions, stride T_ rows)
__device__ float g_gb [NR_*T_*DHID_];
__device__ float g_ub [NR_*T_*DHID_];
__device__ float g_y  [NR_*T_*D_];

__device__ __forceinline__ unsigned f2tf(float x) {
    unsigned r;
    asm("cvt.rna.tf32.f32 %0, %1;" : "=r"(r) : "f"(x));
    return r;
}

// ---------------- rmsnorm --------------------------------------------------
__global__ void rmsnorm_k(const float* __restrict__ x, const float* __restrict__ w,
                          float* __restrict__ o) {
    int row = blockIdx.x;
    const float* xr = x + (size_t)row * D_;
    float ss = 0.f;
    float vloc[4];
#pragma unroll
    for (int i = 0; i < 4; i++) { vloc[i] = xr[threadIdx.x + i*256]; ss += vloc[i]*vloc[i]; }
#pragma unroll
    for (int off = 16; off; off >>= 1) ss += __shfl_xor_sync(0xffffffffu, ss, off);
    __shared__ float sm[8];
    __shared__ float invs;
    if ((threadIdx.x & 31) == 0) sm[threadIdx.x >> 5] = ss;
    __syncthreads();
    if (threadIdx.x == 0) {
        float t = 0.f;
#pragma unroll
        for (int i = 0; i < 8; i++) t += sm[i];
        invs = 1.0f / sqrtf(t / (float)D_ + 1e-6f);
    }
    __syncthreads();
    float inv = invs;
    float* orow = o + (size_t)row * D_;
#pragma unroll
    for (int i = 0; i < 4; i++) {
        int d = threadIdx.x + i*256;
        orow[d] = vloc[i] * inv * w[d];
    }
}

// ---------------- tf32 mma core: 128x128x16, double-buffered ---------------
// cnt < 0 : dense. cnt >= 0: rows bounded by cnt (clamped loads, guarded writes).
// idx != null: A rows gathered via idx. C rows always compact (= global row).
// Dadd != null: C = Dadd + acc (dense use only). N may be < 128 (multiple of 8).
__device__ __forceinline__ void mma_core(
        const float* __restrict__ A, const float* __restrict__ Bm,
        float* __restrict__ C, int N, int K, int bx, int by,
        int cnt, const int* __restrict__ idx, const float* __restrict__ Dadd) {
    __shared__ unsigned As[2][16][136];
    __shared__ unsigned Bs[2][16][136];

    int tid = threadIdx.x;
    int warp = tid >> 5, lane = tid & 31;
    int wm = warp & 3;
    int wn = warp >> 2;
    int r  = lane >> 2;
    int cq = lane & 3;

    float acc[2][8][4];
#pragma unroll
    for (int i = 0; i < 2; i++)
#pragma unroll
        for (int j = 0; j < 8; j++)
#pragma unroll
            for (int k = 0; k < 4; k++) acc[i][j][k] = 0.f;

    int ar = tid >> 1;
    int ac = (tid & 1) * 8;
    int gRowA = by*128 + ar;
    int rowA;
    if (idx) {
        int rs = (cnt >= 0 && gRowA >= cnt) ? (cnt - 1) : gRowA;
        rowA = idx[rs];
    } else if (cnt >= 0) {
        rowA = (gRowA < cnt) ? gRowA : (cnt - 1);
    } else {
        rowA = gRowA;
    }
    const float* Ap = A + (size_t)rowA * K + ac;

    int br = tid >> 4;
    int bc = (tid & 15) * 8;
    int bcc = (bc + 8 <= N) ? bc : (N - 8);     // clamp for N<128 segments
    const float* Bp = Bm + (size_t)br * N + (size_t)bx*128 + bcc;

    int ntiles = K >> 4;

    float4 pa0 = *(const float4*)Ap;
    float4 pa1 = *(const float4*)(Ap + 4);
    float4 pb0 = *(const float4*)Bp;
    float4 pb1 = *(const float4*)(Bp + 4);
    As[0][ac+0][ar] = f2tf(pa0.x); As[0][ac+1][ar] = f2tf(pa0.y);
    As[0][ac+2][ar] = f2tf(pa0.z); As[0][ac+3][ar] = f2tf(pa0.w);
    As[0][ac+4][ar] = f2tf(pa1.x); As[0][ac+5][ar] = f2tf(pa1.y);
    As[0][ac+6][ar] = f2tf(pa1.z); As[0][ac+7][ar] = f2tf(pa1.w);
    {
        uint4 u0 = {f2tf(pb0.x), f2tf(pb0.y), f2tf(pb0.z), f2tf(pb0.w)};
        uint4 u1 = {f2tf(pb1.x), f2tf(pb1.y), f2tf(pb1.z), f2tf(pb1.w)};
        *(uint4*)&Bs[0][br][bc]     = u0;
        *(uint4*)&Bs[0][br][bc + 4] = u1;
    }

    for (int kt = 0; kt < ntiles; kt++) {
        int st = kt & 1;
        __syncthreads();

        bool more = (kt + 1 < ntiles);
        if (more) {
            Ap += 16;
            Bp += (size_t)16 * N;
            pa0 = *(const float4*)Ap;
            pa1 = *(const float4*)(Ap + 4);
            pb0 = *(const float4*)Bp;
            pb1 = *(const float4*)(Bp + 4);
        }

#pragma unroll
        for (int kk = 0; kk < 16; kk += 8) {
            unsigned a[2][4];
#pragma unroll
            for (int i = 0; i < 2; i++) {
                int m0 = wm*32 + i*16 + r;
                a[i][0] = As[st][kk+cq  ][m0];
                a[i][1] = As[st][kk+cq  ][m0 + 8];
                a[i][2] = As[st][kk+cq+4][m0];
                a[i][3] = As[st][kk+cq+4][m0 + 8];
            }
#pragma unroll
            for (int j = 0; j < 8; j++) {
                int n0 = wn*64 + j*8 + r;
                unsigned b0 = Bs[st][kk+cq  ][n0];
                unsigned b1 = Bs[st][kk+cq+4][n0];
#pragma unroll
                for (int i = 0; i < 2; i++) {
                    asm volatile(
                        "mma.sync.aligned.m16n8k8.row.col.f32.tf32.tf32.f32 "
                        "{%0,%1,%2,%3},{%4,%5,%6,%7},{%8,%9},{%0,%1,%2,%3};"
                        : "+f"(acc[i][j][0]), "+f"(acc[i][j][1]),
                          "+f"(acc[i][j][2]), "+f"(acc[i][j][3])
                        : "r"(a[i][0]), "r"(a[i][1]), "r"(a[i][2]), "r"(a[i][3]),
                          "r"(b0), "r"(b1));
                }
            }
        }

        if (more) {
            int ns = st ^ 1;
            As[ns][ac+0][ar] = f2tf(pa0.x); As[ns][ac+1][ar] = f2tf(pa0.y);
            As[ns][ac+2][ar] = f2tf(pa0.z); As[ns][ac+3][ar] = f2tf(pa0.w);
            As[ns][ac+4][ar] = f2tf(pa1.x); As[ns][ac+5][ar] = f2tf(pa1.y);
            As[ns][ac+6][ar] = f2tf(pa1.z); As[ns][ac+7][ar] = f2tf(pa1.w);
            uint4 u0 = {f2tf(pb0.x), f2tf(pb0.y), f2tf(pb0.z), f2tf(pb0.w)};
            uint4 u1 = {f2tf(pb1.x), f2tf(pb1.y), f2tf(pb1.z), f2tf(pb1.w)};
            *(uint4*)&Bs[ns][br][bc]     = u0;
            *(uint4*)&Bs[ns][br][bc + 4] = u1;
        }
    }

#pragma unroll
    for (int i = 0; i < 2; i++) {
        int lrow = wm*32 + i*16 + r;
        int gr0 = by*128 + lrow;
        int gr1 = gr0 + 8;
#pragma unroll
        for (int half = 0; half < 2; half++) {
            int gr = half ? gr1 : gr0;
            if (cnt >= 0 && gr >= cnt) continue;
            float* cbase = C + (size_t)gr * N + (size_t)bx*128 + wn*64;
            const float* dbase = Dadd ? (Dadd + (size_t)gr * N + (size_t)bx*128 + wn*64)
                                      : nullptr;
#pragma unroll
            for (int j = 0; j < 8; j++) {
                int ncol = wn*64 + j*8 + cq*2;
                if (bx*128 + ncol >= N && N < 128) continue;  // N<128 guard
                float v0 = acc[i][j][half*2 + 0];
                float v1 = acc[i][j][half*2 + 1];
                float2* p = (float2*)(cbase + j*8 + cq*2);
                if (dbase) {
                    float2 dv = *(const float2*)(dbase + j*8 + cq*2);
                    float2 nv; nv.x = dv.x + v0; nv.y = dv.y + v1;
                    *p = nv;
                } else {
                    float2 nv; nv.x = v0; nv.y = v1;
                    *p = nv;
                }
            }
        }
    }
}

// ---- dense multi-segment (same A, up to 4 (B,C,N) segments along grid.x) --
__global__ __launch_bounds__(256, 2) void mma_multi4(
        const float* __restrict__ A, int K,
        const float* B0, float* C0, int N0, int X0,
        const float* B1, float* C1, int N1, int X1,
        const float* B2, float* C2, int N2, int X2,
        const float* B3, float* C3, int N3, int X3,
        const float* __restrict__ Dadd) {
    int bx = blockIdx.x;
    const float* Bm; float* C; int N;
    if (bx < X0)                { Bm = B0; C = C0; N = N0; }
    else if (bx < X0+X1)        { bx -= X0; Bm = B1; C = C1; N = N1; }
    else if (bx < X0+X1+X2)     { bx -= X0+X1; Bm = B2; C = C2; N = N2; }
    else                        { bx -= X0+X1+X2; Bm = B3; C = C3; N = N3; }
    mma_core(A, Bm, C, N, K, bx, blockIdx.y, -1, nullptr, Dadd);
}

// ---- routed experts: gate+up batched over z=expert, gathered A ------------
__global__ __launch_bounds__(256, 2) void mma_gu_routed(
        const float* __restrict__ h2, const float* __restrict__ wr_gate,
        const float* __restrict__ wr_up, float* __restrict__ gb,
        float* __restrict__ ub, const int* __restrict__ elist,
        const int* __restrict__ cntArr) {
    int e = blockIdx.z;
    int cnt = cntArr[e];
    if ((int)blockIdx.y * 128 >= cnt) return;
    int bx = blockIdx.x;
    const float* Bm; float* C;
    if (bx < DHID_/128) { Bm = wr_gate + (size_t)e*D_*DHID_; C = gb + (size_t)e*T_*DHID_; }
    else { bx -= DHID_/128; Bm = wr_up + (size_t)e*D_*DHID_; C = ub + (size_t)e*T_*DHID_; }
    mma_core(h2, Bm, C, DHID_, D_, bx, blockIdx.y, cnt, elist + e*T_, nullptr);
}

// ---- routed experts: down batched, compact in -> compact out --------------
__global__ __launch_bounds__(256, 2) void mma_down_routed(
        const float* __restrict__ gb, const float* __restrict__ wr_down,
        float* __restrict__ y, const int* __restrict__ cntArr) {
    int e = blockIdx.z;
    int cnt = cntArr[e];
    if ((int)blockIdx.y * 128 >= cnt) return;
    mma_core(gb + (size_t)e*T_*DHID_, wr_down + (size_t)e*DHID_*D_,
             y + (size_t)e*T_*D_, D_, DHID_, blockIdx.x, blockIdx.y,
             cnt, nullptr, nullptr);
}

// ---- shared experts: down batched over z ----------------------------------
__global__ __launch_bounds__(256, 2) void mma_down_shared(
        const float* __restrict__ gsh, const float* __restrict__ ws_down,
        float* __restrict__ ysh) {
    int s = blockIdx.z;
    mma_core(gsh + (size_t)s*T_*DHID_, ws_down + (size_t)s*DHID_*D_,
             ysh + (size_t)s*T_*D_, D_, DHID_, blockIdx.x, blockIdx.y,
             -1, nullptr, nullptr);
}

// ---------------- RoPE (in-place on q tail + k_r) --------------------------
__global__ void rope_k(float* __restrict__ q, float* __restrict__ kr) {
    int p = blockIdx.x * blockDim.x + threadIdx.x;
    const int NQ = T_ * H_ * 32;
    const int NK = T_ * 32;
    if (p < NQ) {
        int i = p & 31;
        int h = (p >> 5) & (H_ - 1);
        int t = p >> 9;
        int s = t & (S_ - 1);
        float inv = powf(10000.0f, -(float)i / 32.0f);
        float sn, c;
        sincosf((float)s * inv, &sn, &c);
        float* base = q + (size_t)t * (H_*QDIM_) + h * QDIM_ + DH_;
        float t1 = base[i], t2 = base[32 + i];
        base[i]      = t1 * c - t2 * sn;
        base[32 + i] = t2 * c + t1 * sn;
    } else if (p < NQ + NK) {
        int p2 = p - NQ;
        int i = p2 & 31;
        int t = p2 >> 5;
        int s = t & (S_ - 1);
        float inv = powf(10000.0f, -(float)i / 32.0f);
        float sn, c;
        sincosf((float)s * inv, &sn, &c);
        float* base = kr + (size_t)t * DR_;
        float t1 = base[i], t2 = base[32 + i];
        base[i]      = t1 * c - t2 * sn;
        base[32 + i] = t2 * c + t1 * sn;
    }
}

// ---------------- tensor-core flash attention (causal, d=128, dv=64) -------
#define FA_SMEM_FLOATS (64*132 + 64*132 + 64*68 + 4*16*68)
#define FA_SMEM_BYTES  (FA_SMEM_FLOATS*4)

__global__ __launch_bounds__(128) void flash_mma_k(
        const float* __restrict__ q, const float* __restrict__ kc,
        const float* __restrict__ kr, const float* __restrict__ v,
        float* __restrict__ ctx) {
    extern __shared__ unsigned smbuf[];
    unsigned* Qs = smbuf;                 // [64][132]
    unsigned* Ks = Qs + 64*132;           // [64][132]
    unsigned* Vs = Ks + 64*132;           // [64][68]
    unsigned* Ps = Vs + 64*68;            // [4][16][68]

    int qb = blockIdx.x;
    int bh = blockIdx.y;
    int b = bh >> 4, h = bh & 15;
    int tid = threadIdx.x;
    int warp = tid >> 5, lane = tid & 31;
    int r = lane >> 2, cq = lane & 3;
    size_t tq = (size_t)b*S_ + qb*64;
    unsigned* Pw = Ps + warp*16*68;

#pragma unroll
    for (int i = 0; i < 16; i++) {
        int e = i*128 + tid;
        int row = e >> 5, c4 = (e & 31) * 4;
        float4 qv = *(const float4*)&q[(tq+row)*(size_t)(H_*QDIM_) + h*QDIM_ + c4];
        unsigned* dst = &Qs[row*132 + c4];
        dst[0]=f2tf(qv.x); dst[1]=f2tf(qv.y); dst[2]=f2tf(qv.z); dst[3]=f2tf(qv.w);
    }

    float m0 = -1e30f, m1 = -1e30f;
    float l0 = 0.f,  l1 = 0.f;
    float o[8][4];
#pragma unroll
    for (int j = 0; j < 8; j++)
#pragma unroll
        for (int k = 0; k < 4; k++) o[j][k] = 0.f;

    const float scale = 0.088388347648318447f;   // 1/sqrt(128)
    int nkb = qb + 1;

    for (int kb = 0; kb < nkb; kb++) {
        size_t tk = (size_t)b*S_ + kb*64;
        __syncthreads();
#pragma unroll
        for (int i = 0; i < 8; i++) {
            int e = i*128 + tid;
            int row = e >> 4, c4 = (e & 15) * 4;
            float4 kv = *(const float4*)&kc[(tk+row)*(size_t)(H_*DH_) + h*DH_ + c4];
            unsigned* dst = &Ks[row*132 + c4];
            dst[0]=f2tf(kv.x); dst[1]=f2tf(kv.y); dst[2]=f2tf(kv.z); dst[3]=f2tf(kv.w);
        }
#pragma unroll
        for (int i = 0; i < 8; i++) {
            int e = i*128 + tid;
            int row = e >> 4, c4 = (e & 15) * 4;
            float4 kv = *(const float4*)&kr[(tk+row)*(size_t)DR_ + c4];
            unsigned* dst = &Ks[row*132 + 64 + c4];
            dst[0]=f2tf(kv.x); dst[1]=f2tf(kv.y); dst[2]=f2tf(kv.z); dst[3]=f2tf(kv.w);
        }
#pragma unroll
        for (int i = 0; i < 8; i++) {
            int e = i*128 + tid;
            int row = e >> 4, c4 = (e & 15) * 4;
            float4 vv = *(const float4*)&v[(tk+row)*(size_t)(H_*DH_) + h*DH_ + c4];
            unsigned* dst = &Vs[row*68 + c4];
            dst[0]=f2tf(vv.x); dst[1]=f2tf(vv.y); dst[2]=f2tf(vv.z); dst[3]=f2tf(vv.w);
        }
        __syncthreads();

        float s[8][4];
#pragma unroll
        for (int j = 0; j < 8; j++)
#pragma unroll
            for (int k = 0; k < 4; k++) s[j][k] = 0.f;

#pragma unroll
        for (int kk = 0; kk < 128; kk += 8) {
            int m0r = (warp*16 + r)*132;
            unsigned a0 = Qs[m0r + kk + cq];
            unsigned a1 = Qs[m0r + 8*132 + kk + cq];
            unsigned a2 = Qs[m0r + kk + cq + 4];
            unsigned a3 = Qs[m0r + 8*132 + kk + cq + 4];
#pragma unroll
            for (int j = 0; j < 8; j++) {
                unsigned b0 = Ks[(j*8 + r)*132 + kk + cq];
                unsigned b1 = Ks[(j*8 + r)*132 + kk + cq + 4];
                asm volatile(
                    "mma.sync.aligned.m16n8k8.row.col.f32.tf32.tf32.f32 "
                    "{%0,%1,%2,%3},{%4,%5,%6,%7},{%8,%9},{%0,%1,%2,%3};"
                    : "+f"(s[j][0]), "+f"(s[j][1]), "+f"(s[j][2]), "+f"(s[j][3])
                    : "r"(a0), "r"(a1), "r"(a2), "r"(a3), "r"(b0), "r"(b1));
            }
        }

        bool diag = (kb == qb);
        int lq0 = warp*16 + r;
        int lq1 = lq0 + 8;
#pragma unroll
        for (int j = 0; j < 8; j++) {
            int c0 = j*8 + cq*2, c1 = c0 + 1;
            s[j][0] *= scale; s[j][1] *= scale;
            s[j][2] *= scale; s[j][3] *= scale;
            if (diag) {
                if (c0 > lq0) s[j][0] = -1e9f;
                if (c1 > lq0) s[j][1] = -1e9f;
                if (c0 > lq1) s[j][2] = -1e9f;
                if (c1 > lq1) s[j][3] = -1e9f;
            }
        }

        float mt0 = -1e30f, mt1 = -1e30f;
#pragma unroll
        for (int j = 0; j < 8; j++) {
            mt0 = fmaxf(mt0, fmaxf(s[j][0], s[j][1]));
            mt1 = fmaxf(mt1, fmaxf(s[j][2], s[j][3]));
        }
        mt0 = fmaxf(mt0, __shfl_xor_sync(0xffffffffu, mt0, 1));
        mt0 = fmaxf(mt0, __shfl_xor_sync(0xffffffffu, mt0, 2));
        mt1 = fmaxf(mt1, __shfl_xor_sync(0xffffffffu, mt1, 1));
        mt1 = fmaxf(mt1, __shfl_xor_sync(0xffffffffu, mt1, 2));

        float mn0 = fmaxf(m0, mt0), mn1 = fmaxf(m1, mt1);
        float al0 = __expf(m0 - mn0), al1 = __expf(m1 - mn1);
        m0 = mn0; m1 = mn1;

        float ps0 = 0.f, ps1 = 0.f;
#pragma unroll
        for (int j = 0; j < 8; j++) {
            s[j][0] = __expf(s[j][0] - mn0);
            s[j][1] = __expf(s[j][1] - mn0);
            s[j][2] = __expf(s[j][2] - mn1);
            s[j][3] = __expf(s[j][3] - mn1);
            ps0 += s[j][0] + s[j][1];
            ps1 += s[j][2] + s[j][3];
        }
        ps0 += __shfl_xor_sync(0xffffffffu, ps0, 1);
        ps0 += __shfl_xor_sync(0xffffffffu, ps0, 2);
        ps1 += __shfl_xor_sync(0xffffffffu, ps1, 1);
        ps1 += __shfl_xor_sync(0xffffffffu, ps1, 2);
        l0 = l0 * al0 + ps0;
        l1 = l1 * al1 + ps1;

#pragma unroll
        for (int j = 0; j < 8; j++) {
            o[j][0] *= al0; o[j][1] *= al0;
            o[j][2] *= al1; o[j][3] *= al1;
        }

#pragma unroll
        for (int j = 0; j < 8; j++) {
            int c0 = j*8 + cq*2;
            Pw[r*68 + c0]       = f2tf(s[j][0]);
            Pw[r*68 + c0 + 1]   = f2tf(s[j][1]);
            Pw[(r+8)*68 + c0]     = f2tf(s[j][2]);
            Pw[(r+8)*68 + c0 + 1] = f2tf(s[j][3]);
        }
        __syncwarp();

#pragma unroll
        for (int kk = 0; kk < 64; kk += 8) {
            unsigned a0 = Pw[r*68 + kk + cq];
            unsigned a1 = Pw[(r+8)*68 + kk + cq];
            unsigned a2 = Pw[r*68 + kk + cq + 4];
            unsigned a3 = Pw[(r+8)*68 + kk + cq + 4];
#pragma unroll
            for (int j = 0; j < 8; j++) {
                unsigned b0 = Vs[(kk+cq)*68 + j*8 + r];
                unsigned b1 = Vs[(kk+cq+4)*68 + j*8 + r];
                asm volatile(
                    "mma.sync.aligned.m16n8k8.row.col.f32.tf32.tf32.f32 "
                    "{%0,%1,%2,%3},{%4,%5,%6,%7},{%8,%9},{%0,%1,%2,%3};"
                    : "+f"(o[j][0]), "+f"(o[j][1]), "+f"(o[j][2]), "+f"(o[j][3])
                    : "r"(a0), "r"(a1), "r"(a2), "r"(a3), "r"(b0), "r"(b1));
            }
        }
        __syncwarp();
    }

    float inv0 = 1.f / l0, inv1 = 1.f / l1;
    size_t row0 = (tq + warp*16 + r) * (size_t)(H_*DH_) + h*DH_;
    size_t row1 = row0 + (size_t)8 * (H_*DH_);
#pragma unroll
    for (int j = 0; j < 8; j++) {
        int c0 = j*8 + cq*2;
        float2 v0; v0.x = o[j][0]*inv0; v0.y = o[j][1]*inv0;
        float2 v1; v1.x = o[j][2]*inv1; v1.y = o[j][3]*inv1;
        *(float2*)&ctx[row0 + c0] = v0;
        *(float2*)&ctx[row1 + c0] = v1;
    }
}

// ---------------- misc elementwise ----------------------------------------
__global__ void zero_cnt_k(int* c) {
    if (threadIdx.x < NR_) c[threadIdx.x] = 0;
}

// z = blockIdx.y selects slice; cntArr null => dense (cnt = T_)
__global__ void silu_batched_k(const float* __restrict__ g, const float* __restrict__ u,
                               float* __restrict__ o, const int* __restrict__ cntArr) {
    int z = blockIdx.y;
    int cnt = cntArr ? cntArr[z] : T_;
    long i = (long)blockIdx.x * blockDim.x + threadIdx.x;
    if (i >= (long)cnt * DHID_) return;
    size_t base = (size_t)z * T_ * DHID_;
    float gv = g[base + i], uv = u[base + i];
    o[base + i] = (gv / (1.f + __expf(-gv))) * uv;
}

// ---------------- gating: logits + softmax + top2 + routing ----------------
__global__ void gate_topk_k(const float* __restrict__ h2, const float* __restrict__ gw,
                            int* __restrict__ cnt, int* __restrict__ elist,
                            int* __restrict__ rt, float* __restrict__ rw) {
    int t = blockIdx.x * 8 + (threadIdx.x >> 5);
    int lane = threadIdx.x & 31;
    if (t >= T_) return;
    float acc[NR_];
#pragma unroll
    for (int e = 0; e < NR_; e++) acc[e] = 0.f;
    const float* hr = h2 + (size_t)t * D_;
    for (int d = lane; d < D_; d += 32) {
        float xv = hr[d];
        const float* g = gw + (size_t)d * NR_;
#pragma unroll
        for (int e = 0; e < NR_; e++) acc[e] += xv * g[e];
    }
#pragma unroll
    for (int e = 0; e < NR_; e++)
#pragma unroll
        for (int off = 16; off; off >>= 1)
            acc[e] += __shfl_xor_sync(0xffffffffu, acc[e], off);
    if (lane == 0) {
        int i1 = 0;
#pragma unroll
        for (int e = 1; e < NR_; e++) if (acc[e] > acc[i1]) i1 = e;
        int i2 = (i1 == 0) ? 1 : 0;
#pragma unroll
        for (int e = 0; e < NR_; e++) {
            if (e == i1 || e == i2) continue;
            if (acc[e] > acc[i2]) i2 = e;
        }
        float p2 = __expf(acc[i2] - acc[i1]);
        float inv = 1.f / (1.f + p2);
        float w1 = inv, w2 = p2 * inv;
        int pos1 = atomicAdd(&cnt[i1], 1);
        elist[i1*T_ + pos1] = t;
        int pos2 = atomicAdd(&cnt[i2], 1);
        elist[i2*T_ + pos2] = t;
        rt[t*4+0] = i1; rt[t*4+1] = pos1;
        rt[t*4+2] = i2; rt[t*4+3] = pos2;
        rw[t*2+0] = w1; rw[t*2+1] = w2;
    }
}

// ---------------- final reduce: out += shared + routed ---------------------
__global__ void reduce_k(float* __restrict__ out, const float* __restrict__ ysh,
                         const float* __restrict__ y, const int* __restrict__ rt,
                         const float* __restrict__ rw) {
    int t = blockIdx.x;
    int tid = threadIdx.x;
    int e1 = rt[t*4+0], p1 = rt[t*4+1];
    int e2 = rt[t*4+2], p2 = rt[t*4+3];
    float w1 = rw[t*2+0], w2 = rw[t*2+1];
    const float4* s0 = (const float4*)(ysh + (size_t)t * D_);
    const float4* s1 = (const float4*)(ysh + ((size_t)T_ + t) * D_);
    const float4* y1 = (const float4*)(y + ((size_t)e1*T_ + p1) * D_);
    const float4* y2 = (const float4*)(y + ((size_t)e2*T_ + p2) * D_);
    float4* op = (float4*)(out + (size_t)t * D_);
    for (int d = tid; d < D_/4; d += blockDim.x) {
        float4 o = op[d];
        float4 a = s0[d], b = s1[d], c = y1[d], e = y2[d];
        o.x += a.x + b.x + w1*c.x + w2*e.x;
        o.y += a.y + b.y + w1*c.y + w2*e.y;
        o.z += a.z + b.z + w1*c.z + w2*e.z;
        o.w += a.w + b.w + w1*c.w + w2*e.w;
        op[d] = o;
    }
}

// ---------------- launch ---------------------------------------------------
extern "C" void kernel_launch(void* const* d_in, const int* in_sizes, int n_in,
                              void* d_out, int out_size) {
    const float* x         = (const float*)d_in[0];
    const float* w_q       = (const float*)d_in[2];
    const float* w_dkv     = (const float*)d_in[3];
    const float* w_uk      = (const float*)d_in[4];
    const float* w_uv      = (const float*)d_in[5];
    const float* w_kr      = (const float*)d_in[6];
    const float* w_o       = (const float*)d_in[7];
    const float* attn_nw   = (const float*)d_in[8];
    const float* mlp_nw    = (const float*)d_in[9];
    const float* gate_w    = (const float*)d_in[10];
    const float* wr_gate   = (const float*)d_in[11];
    const float* wr_up     = (const float*)d_in[12];
    const float* wr_down   = (const float*)d_in[13];
    const float* ws_gate   = (const float*)d_in[14];
    const float* ws_up     = (const float*)d_in[15];
    const float* ws_down   = (const float*)d_in[16];
    float* out = (float*)d_out;

    float *ph, *pq, *plat, *pkc, *pv, *pkr, *pctx, *ph2;
    float *pgsh, *push, *pysh, *pgb, *pub, *py, *prw;
    int *pcnt, *pel, *prt;
    cudaGetSymbolAddress((void**)&ph,   g_h);
    cudaGetSymbolAddress((void**)&pq,   g_q);
    cudaGetSymbolAddress((void**)&plat, g_lat);
    cudaGetSymbolAddress((void**)&pkc,  g_kc);
    cudaGetSymbolAddress((void**)&pv,   g_v);
    cudaGetSymbolAddress((void**)&pkr,  g_kr);
    cudaGetSymbolAddress((void**)&pctx, g_ctx);
    cudaGetSymbolAddress((void**)&ph2,  g_h2);
    cudaGetSymbolAddress((void**)&pgsh, g_gsh);
    cudaGetSymbolAddress((void**)&push, g_ush);
    cudaGetSymbolAddress((void**)&pysh, g_ysh);
    cudaGetSymbolAddress((void**)&pgb,  g_gb);
    cudaGetSymbolAddress((void**)&pub,  g_ub);
    cudaGetSymbolAddress((void**)&py,   g_y);
    cudaGetSymbolAddress((void**)&pcnt, g_cnt);
    cudaGetSymbolAddress((void**)&pel,  g_elist);
    cudaGetSymbolAddress((void**)&prt,  g_rt);
    cudaGetSymbolAddress((void**)&prw,  g_rw);

    cudaFuncSetAttribute(flash_mma_k,
                         cudaFuncAttributeMaxDynamicSharedMemorySize, FA_SMEM_BYTES);

    // 1) h = rmsnorm(x)
    rmsnorm_k<<<T_, 256>>>(x, attn_nw, ph);

    // 2) fused projections: w_q (16 tiles) + w_dkv (4) + w_kr (1)
    mma_multi4<<<dim3(21, T_/128), 256>>>(ph, D_,
        w_q,   pq,   H_*QDIM_, 16,
        w_dkv, plat, DL_,      4,
        w_kr,  pkr,  DR_,      1,
        nullptr, nullptr, 0, 0, nullptr);

    // 3) RoPE
    {
        int n = T_*H_*32 + T_*32;
        rope_k<<<(n + 255)/256, 256>>>(pq, pkr);
    }

    // 4) fused k_c + v up-projections
    mma_multi4<<<dim3(16, T_/128), 256>>>(plat, DL_,
        w_uk, pkc, H_*DH_, 8,
        w_uv, pv,  H_*DH_, 8,
        nullptr, nullptr, 0, 0,
        nullptr, nullptr, 0, 0, nullptr);

    // 5) attention
    flash_mma_k<<<dim3(S_/64, B_*H_), 128, FA_SMEM_BYTES>>>(pq, pkc, pkr, pv, pctx);

    // 6) out = x + ctx @ w_o
    mma_multi4<<<dim3(8, T_/128), 256>>>(pctx, H_*DH_,
        w_o, out, D_, 8,
        nullptr, nullptr, 0, 0,
        nullptr, nullptr, 0, 0,
        nullptr, nullptr, 0, 0, x);

    // 7) h2 = rmsnorm(out)
    rmsnorm_k<<<T_, 256>>>(out, mlp_nw, ph2);

    // 8) routing
    zero_cnt_k<<<1, 32>>>(pcnt);
    gate_topk_k<<<T_/8, 256>>>(ph2, gate_w, pcnt, pel, prt, prw);

    // 9) shared experts: gate+up (both experts) in one launch
    mma_multi4<<<dim3(16, T_/128), 256>>>(ph2, D_,
        ws_gate,              pgsh,               DHID_, 4,
        ws_up,                push,               DHID_, 4,
        ws_gate + (size_t)D_*DHID_, pgsh + (size_t)T_*DHID_, DHID_, 4,
        ws_up   + (size_t)D_*DHID_, push + (size_t)T_*DHID_, DHID_, 4,
        nullptr);
    silu_batched_k<<<dim3((T_*DHID_ + 255)/256, NS_), 256>>>(pgsh, push, pgsh, nullptr);
    mma_down_shared<<<dim3(D_/128, T_/128, NS_), 256>>>(pgsh, ws_down, pysh);

    // 10) routed experts: batched gate+up, silu, down (compact outputs)
    mma_gu_routed<<<dim3(2*DHID_/128, T_/128, NR_), 256>>>(ph2, wr_gate, wr_up,
                                                           pgb, pub, pel, pcnt);
    silu_batched_k<<<dim3((T_*DHID_ + 255)/256, NR_), 256>>>(pgb, pub, pgb, pcnt);
    mma_down_routed<<<dim3(D_/128, T_/128, NR_), 256>>>(pgb, wr_down, py, pcnt);

    // 11) deterministic combine
    reduce_k<<<T_, 256>>>(out, pysh, py, prt, prw);
}

// round 11
// speedup vs baseline: 5.1355x; 1.1729x over previous
#include <cuda_runtime.h>
#include <math.h>

#define B_ 2
#define S_ 2048
#define D_ 1024
#define H_ 16
#define DH_ 64
#define DR_ 64
#define DL_ 512
#define DHID_ 512
#define NR_ 8
#define NS_ 2
#define T_ (B_*S_)          // 4096 tokens
#define QDIM_ (DH_+DR_)     // 128

// ---------------- scratch (device globals; no allocation allowed) ----------
__device__ float g_h  [T_*D_];
__device__ float g_q  [T_*H_*QDIM_];
__device__ float g_lat[T_*DL_];
__device__ float g_kc [T_*H_*DH_];
__device__ float g_v  [T_*H_*DH_];
__device__ float g_kr [T_*DR_];
__device__ float g_ctx[T_*H_*DH_];
__device__ float g_h2 [T_*D_];
__device__ int   g_cnt[NR_];
__device__ int   g_elist[NR_*T_];
__device__ int   g_rt  [T_*4];        // per-token (e1,pos1,e2,pos2)
__device__ float g_rw  [T_*2];        // per-token (w1,w2)
// shared experts
__device__ float g_gsh[NS_*T_*DHID_];
__device__ float g_ush[NS_*T_*DHID_];
__device__ float g_ysh[NS_*T_*D_];
// routed experts (compact per-expert regions, stride T_ rows)
__device__ float g_gb [NR_*T_*DHID_];
__device__ float g_ub [NR_*T_*DHID_];
__device__ float g_y  [NR_*T_*D_];

__device__ __forceinline__ unsigned f2tf(float x) {
    unsigned r;
    asm("cvt.rna.tf32.f32 %0, %1;" : "=r"(r) : "f"(x));
    return r;
}

__device__ __forceinline__ void cp16(float* dst, const float* src) {
    unsigned d = (unsigned)__cvta_generic_to_shared(dst);
    asm volatile("cp.async.cg.shared.global [%0], [%1], 16;" :: "r"(d), "l"(src));
}

// ---------------- rmsnorm --------------------------------------------------
__global__ void rmsnorm_k(const float* __restrict__ x, const float* __restrict__ w,
                          float* __restrict__ o) {
    int row = blockIdx.x;
    const float* xr = x + (size_t)row * D_;
    float ss = 0.f;
    float vloc[4];
#pragma unroll
    for (int i = 0; i < 4; i++) { vloc[i] = xr[threadIdx.x + i*256]; ss += vloc[i]*vloc[i]; }
#pragma unroll
    for (int off = 16; off; off >>= 1) ss += __shfl_xor_sync(0xffffffffu, ss, off);
    __shared__ float sm[8];
    __shared__ float invs;
    if ((threadIdx.x & 31) == 0) sm[threadIdx.x >> 5] = ss;
    __syncthreads();
    if (threadIdx.x == 0) {
        float t = 0.f;
#pragma unroll
        for (int i = 0; i < 8; i++) t += sm[i];
        invs = 1.0f / sqrtf(t / (float)D_ + 1e-6f);
    }
    __syncthreads();
    float inv = invs;
    float* orow = o + (size_t)row * D_;
#pragma unroll
    for (int i = 0; i < 4; i++) {
        int d = threadIdx.x + i*256;
        orow[d] = vloc[i] * inv * w[d];
    }
}

// ---------------- tf32 mma core: 128x128x16, 4-stage cp.async --------------
#define STG_ 4
#define SA_STRIDE 20                 // 16 k + 4 pad (banks (20r+cq)%32 distinct)
#define SB_STRIDE 136                // 128 n + 8 pad
#define SA_SZ (128*SA_STRIDE)        // floats per stage (A)
#define SB_SZ (16*SB_STRIDE)         // floats per stage (B)
#define STG_SZ (SA_SZ + SB_SZ)
#define MM_SMEM_BYTES (STG_*STG_SZ*4)   // 75,776 B

// cnt < 0 : dense. cnt >= 0: rows bounded by cnt (clamped loads, guarded writes).
// idx != null: A rows gathered via idx. C rows always compact (= global row).
// Dadd != null: C = Dadd + acc. N may be < 128 (multiple of 8).
__device__ __forceinline__ void mma_core(
        const float* __restrict__ A, const float* __restrict__ Bm,
        float* __restrict__ C, int N, int K, int bx, int by,
        int cnt, const int* __restrict__ idx, const float* __restrict__ Dadd) {
    extern __shared__ float smdyn[];

    int tid = threadIdx.x;
    int warp = tid >> 5, lane = tid & 31;
    int wm = warp & 3;
    int wn = warp >> 2;
    int r  = lane >> 2;
    int cq = lane & 3;

    float acc[2][8][4];
#pragma unroll
    for (int i = 0; i < 2; i++)
#pragma unroll
        for (int j = 0; j < 8; j++)
#pragma unroll
            for (int k = 0; k < 4; k++) acc[i][j][k] = 0.f;

    // A loader: thread -> row ar (0..127), k-offset ak (0 or 8)
    int ar = tid >> 1;
    int ak = (tid & 1) * 8;
    int gRowA = by*128 + ar;
    int rowA;
    if (idx) {
        int rs = (cnt >= 0 && gRowA >= cnt) ? (cnt - 1) : gRowA;
        rowA = idx[rs];
    } else if (cnt >= 0) {
        rowA = (gRowA < cnt) ? gRowA : (cnt - 1);
    } else {
        rowA = gRowA;
    }
    const float* Arow = A + (size_t)rowA * K + ak;
    int aDstOff = ar*SA_STRIDE + ak;

    // B loader: thread -> k-row br (0..15), n-offset bc
    int br = tid >> 4;
    int bc = (tid & 15) * 8;
    int bcc = (bc + 8 <= N) ? bc : (N - 8);     // src clamp for N<128
    const float* Bsrc0 = Bm + (size_t)br * N + (size_t)bx*128 + bcc;
    int bDstOff = SA_SZ + br*SB_STRIDE + bc;

    int ntiles = K >> 4;

    // prologue: stages 0..STG_-2
#pragma unroll
    for (int p = 0; p < STG_-1; p++) {
        float* st = smdyn + p*STG_SZ;
        const float* as = Arow + p*16;
        cp16(st + aDstOff,     as);
        cp16(st + aDstOff + 4, as + 4);
        const float* bs = Bsrc0 + (size_t)p * 16 * N;
        cp16(st + bDstOff,     bs);
        cp16(st + bDstOff + 4, bs + 4);
        asm volatile("cp.async.commit_group;");
    }

    for (int kt = 0; kt < ntiles; kt++) {
        asm volatile("cp.async.wait_group %0;" :: "n"(STG_-2));
        __syncthreads();

        const unsigned* As = (const unsigned*)(smdyn + (kt & (STG_-1))*STG_SZ);
        const unsigned* Bs = As + SA_SZ;

#pragma unroll
        for (int kk = 0; kk < 16; kk += 8) {
            unsigned a[2][4];
#pragma unroll
            for (int i = 0; i < 2; i++) {
                int m0 = (wm*32 + i*16 + r) * SA_STRIDE;
                a[i][0] = As[m0                + kk + cq];
                a[i][1] = As[m0 + 8*SA_STRIDE  + kk + cq];
                a[i][2] = As[m0                + kk + cq + 4];
                a[i][3] = As[m0 + 8*SA_STRIDE  + kk + cq + 4];
            }
#pragma unroll
            for (int j = 0; j < 8; j++) {
                int n0 = wn*64 + j*8 + r;
                unsigned b0 = Bs[(kk+cq  )*SB_STRIDE + n0];
                unsigned b1 = Bs[(kk+cq+4)*SB_STRIDE + n0];
#pragma unroll
                for (int i = 0; i < 2; i++) {
                    asm volatile(
                        "mma.sync.aligned.m16n8k8.row.col.f32.tf32.tf32.f32 "
                        "{%0,%1,%2,%3},{%4,%5,%6,%7},{%8,%9},{%0,%1,%2,%3};"
                        : "+f"(acc[i][j][0]), "+f"(acc[i][j][1]),
                          "+f"(acc[i][j][2]), "+f"(acc[i][j][3])
                        : "r"(a[i][0]), "r"(a[i][1]), "r"(a[i][2]), "r"(a[i][3]),
                          "r"(b0), "r"(b1));
                }
            }
        }

        int kn = kt + STG_ - 1;
        if (kn < ntiles) {
            float* st = smdyn + (kn & (STG_-1))*STG_SZ;
            const float* as = Arow + kn*16;
            cp16(st + aDstOff,     as);
            cp16(st + aDstOff + 4, as + 4);
            const float* bs = Bsrc0 + (size_t)kn * 16 * N;
            cp16(st + bDstOff,     bs);
            cp16(st + bDstOff + 4, bs + 4);
        }
        asm volatile("cp.async.commit_group;");
    }

#pragma unroll
    for (int i = 0; i < 2; i++) {
        int lrow = wm*32 + i*16 + r;
        int gr0 = by*128 + lrow;
        int gr1 = gr0 + 8;
#pragma unroll
        for (int half = 0; half < 2; half++) {
            int gr = half ? gr1 : gr0;
            if (cnt >= 0 && gr >= cnt) continue;
            float* cbase = C + (size_t)gr * N + (size_t)bx*128 + wn*64;
            const float* dbase = Dadd ? (Dadd + (size_t)gr * N + (size_t)bx*128 + wn*64)
                                      : nullptr;
#pragma unroll
            for (int j = 0; j < 8; j++) {
                int ncol = wn*64 + j*8 + cq*2;
                if (bx*128 + ncol >= N && N < 128) continue;  // N<128 guard
                float v0 = acc[i][j][half*2 + 0];
                float v1 = acc[i][j][half*2 + 1];
                float2* p = (float2*)(cbase + j*8 + cq*2);
                if (dbase) {
                    float2 dv = *(const float2*)(dbase + j*8 + cq*2);
                    float2 nv; nv.x = dv.x + v0; nv.y = dv.y + v1;
                    *p = nv;
                } else {
                    float2 nv; nv.x = v0; nv.y = v1;
                    *p = nv;
                }
            }
        }
    }
}

// ---- dense multi-segment (same A, up to 4 (B,C,N) segments along grid.x) --
__global__ __launch_bounds__(256, 2) void mma_multi4(
        const float* __restrict__ A, int K,
        const float* B0, float* C0, int N0, int X0,
        const float* B1, float* C1, int N1, int X1,
        const float* B2, float* C2, int N2, int X2,
        const float* B3, float* C3, int N3, int X3,
        const float* __restrict__ Dadd) {
    int bx = blockIdx.x;
    const float* Bm; float* C; int N;
    if (bx < X0)                { Bm = B0; C = C0; N = N0; }
    else if (bx < X0+X1)        { bx -= X0; Bm = B1; C = C1; N = N1; }
    else if (bx < X0+X1+X2)     { bx -= X0+X1; Bm = B2; C = C2; N = N2; }
    else                        { bx -= X0+X1+X2; Bm = B3; C = C3; N = N3; }
    mma_core(A, Bm, C, N, K, bx, blockIdx.y, -1, nullptr, Dadd);
}

// ---- routed experts: gate+up batched over z=expert, gathered A ------------
__global__ __launch_bounds__(256, 2) void mma_gu_routed(
        const float* __restrict__ h2, const float* __restrict__ wr_gate,
        const float* __restrict__ wr_up, float* __restrict__ gb,
        float* __restrict__ ub, const int* __restrict__ elist,
        const int* __restrict__ cntArr) {
    int e = blockIdx.z;
    int cnt = cntArr[e];
    if ((int)blockIdx.y * 128 >= cnt) return;
    int bx = blockIdx.x;
    const float* Bm; float* C;
    if (bx < DHID_/128) { Bm = wr_gate + (size_t)e*D_*DHID_; C = gb + (size_t)e*T_*DHID_; }
    else { bx -= DHID_/128; Bm = wr_up + (size_t)e*D_*DHID_; C = ub + (size_t)e*T_*DHID_; }
    mma_core(h2, Bm, C, DHID_, D_, bx, blockIdx.y, cnt, elist + e*T_, nullptr);
}

// ---- routed experts: down batched, compact in -> compact out --------------
__global__ __launch_bounds__(256, 2) void mma_down_routed(
        const float* __restrict__ gb, const float* __restrict__ wr_down,
        float* __restrict__ y, const int* __restrict__ cntArr) {
    int e = blockIdx.z;
    int cnt = cntArr[e];
    if ((int)blockIdx.y * 128 >= cnt) return;
    mma_core(gb + (size_t)e*T_*DHID_, wr_down + (size_t)e*DHID_*D_,
             y + (size_t)e*T_*D_, D_, DHID_, blockIdx.x, blockIdx.y,
             cnt, nullptr, nullptr);
}

// ---- shared experts: down batched over z ----------------------------------
__global__ __launch_bounds__(256, 2) void mma_down_shared(
        const float* __restrict__ gsh, const float* __restrict__ ws_down,
        float* __restrict__ ysh) {
    int s = blockIdx.z;
    mma_core(gsh + (size_t)s*T_*DHID_, ws_down + (size_t)s*DHID_*D_,
             ysh + (size_t)s*T_*D_, D_, DHID_, blockIdx.x, blockIdx.y,
             -1, nullptr, nullptr);
}

// ---------------- RoPE (in-place on q tail + k_r) --------------------------
__global__ void rope_k(float* __restrict__ q, float* __restrict__ kr) {
    int p = blockIdx.x * blockDim.x + threadIdx.x;
    const int NQ = T_ * H_ * 32;
    const int NK = T_ * 32;
    if (p < NQ) {
        int i = p & 31;
        int h = (p >> 5) & (H_ - 1);
        int t = p >> 9;
        int s = t & (S_ - 1);
        float inv = powf(10000.0f, -(float)i / 32.0f);
        float sn, c;
        sincosf((float)s * inv, &sn, &c);
        float* base = q + (size_t)t * (H_*QDIM_) + h * QDIM_ + DH_;
        float t1 = base[i], t2 = base[32 + i];
        base[i]      = t1 * c - t2 * sn;
        base[32 + i] = t2 * c + t1 * sn;
    } else if (p < NQ + NK) {
        int p2 = p - NQ;
        int i = p2 & 31;
        int t = p2 >> 5;
        int s = t & (S_ - 1);
        float inv = powf(10000.0f, -(float)i / 32.0f);
        float sn, c;
        sincosf((float)s * inv, &sn, &c);
        float* base = kr + (size_t)t * DR_;
        float t1 = base[i], t2 = base[32 + i];
        base[i]      = t1 * c - t2 * sn;
        base[32 + i] = t2 * c + t1 * sn;
    }
}

// ---------------- tensor-core flash attention (causal, d=128, dv=64) -------
#define FA_SMEM_FLOATS (64*132 + 64*132 + 64*68 + 4*16*68)
#define FA_SMEM_BYTES  (FA_SMEM_FLOATS*4)

__global__ __launch_bounds__(128) void flash_mma_k(
        const float* __restrict__ q, const float* __restrict__ kc,
        const float* __restrict__ kr, const float* __restrict__ v,
        float* __restrict__ ctx) {
    extern __shared__ unsigned smbuf[];
    unsigned* Qs = smbuf;                 // [64][132]
    unsigned* Ks = Qs + 64*132;           // [64][132]
    unsigned* Vs = Ks + 64*132;           // [64][68]
    unsigned* Ps = Vs + 64*68;            // [4][16][68]

    int qb = blockIdx.x;
    int bh = blockIdx.y;
    int b = bh >> 4, h = bh & 15;
    int tid = threadIdx.x;
    int warp = tid >> 5, lane = tid & 31;
    int r = lane >> 2, cq = lane & 3;
    size_t tq = (size_t)b*S_ + qb*64;
    unsigned* Pw = Ps + warp*16*68;

#pragma unroll
    for (int i = 0; i < 16; i++) {
        int e = i*128 + tid;
        int row = e >> 5, c4 = (e & 31) * 4;
        float4 qv = *(const float4*)&q[(tq+row)*(size_t)(H_*QDIM_) + h*QDIM_ + c4];
        unsigned* dst = &Qs[row*132 + c4];
        dst[0]=f2tf(qv.x); dst[1]=f2tf(qv.y); dst[2]=f2tf(qv.z); dst[3]=f2tf(qv.w);
    }

    float m0 = -1e30f, m1 = -1e30f;
    float l0 = 0.f,  l1 = 0.f;
    float o[8][4];
#pragma unroll
    for (int j = 0; j < 8; j++)
#pragma unroll
        for (int k = 0; k < 4; k++) o[j][k] = 0.f;

    const float scale = 0.088388347648318447f;   // 1/sqrt(128)
    int nkb = qb + 1;

    for (int kb = 0; kb < nkb; kb++) {
        size_t tk = (size_t)b*S_ + kb*64;
        __syncthreads();
#pragma unroll
        for (int i = 0; i < 8; i++) {
            int e = i*128 + tid;
            int row = e >> 4, c4 = (e & 15) * 4;
            float4 kv = *(const float4*)&kc[(tk+row)*(size_t)(H_*DH_) + h*DH_ + c4];
            unsigned* dst = &Ks[row*132 + c4];
            dst[0]=f2tf(kv.x); dst[1]=f2tf(kv.y); dst[2]=f2tf(kv.z); dst[3]=f2tf(kv.w);
        }
#pragma unroll
        for (int i = 0; i < 8; i++) {
            int e = i*128 + tid;
            int row = e >> 4, c4 = (e & 15) * 4;
            float4 kv = *(const float4*)&kr[(tk+row)*(size_t)DR_ + c4];
            unsigned* dst = &Ks[row*132 + 64 + c4];
            dst[0]=f2tf(kv.x); dst[1]=f2tf(kv.y); dst[2]=f2tf(kv.z); dst[3]=f2tf(kv.w);
        }
#pragma unroll
        for (int i = 0; i < 8; i++) {
            int e = i*128 + tid;
            int row = e >> 4, c4 = (e & 15) * 4;
            float4 vv = *(const float4*)&v[(tk+row)*(size_t)(H_*DH_) + h*DH_ + c4];
            unsigned* dst = &Vs[row*68 + c4];
            dst[0]=f2tf(vv.x); dst[1]=f2tf(vv.y); dst[2]=f2tf(vv.z); dst[3]=f2tf(vv.w);
        }
        __syncthreads();

        float s[8][4];
#pragma unroll
        for (int j = 0; j < 8; j++)
#pragma unroll
            for (int k = 0; k < 4; k++) s[j][k] = 0.f;

#pragma unroll
        for (int kk = 0; kk < 128; kk += 8) {
            int m0r = (warp*16 + r)*132;
            unsigned a0 = Qs[m0r + kk + cq];
            unsigned a1 = Qs[m0r + 8*132 + kk + cq];
            unsigned a2 = Qs[m0r + kk + cq + 4];
            unsigned a3 = Qs[m0r + 8*132 + kk + cq + 4];
#pragma unroll
            for (int j = 0; j < 8; j++) {
                unsigned b0 = Ks[(j*8 + r)*132 + kk + cq];
                unsigned b1 = Ks[(j*8 + r)*132 + kk + cq + 4];
                asm volatile(
                    "mma.sync.aligned.m16n8k8.row.col.f32.tf32.tf32.f32 "
                    "{%0,%1,%2,%3},{%4,%5,%6,%7},{%8,%9},{%0,%1,%2,%3};"
                    : "+f"(s[j][0]), "+f"(s[j][1]), "+f"(s[j][2]), "+f"(s[j][3])
                    : "r"(a0), "r"(a1), "r"(a2), "r"(a3), "r"(b0), "r"(b1));
            }
        }

        bool diag = (kb == qb);
        int lq0 = warp*16 + r;
        int lq1 = lq0 + 8;
#pragma unroll
        for (int j = 0; j < 8; j++) {
            int c0 = j*8 + cq*2, c1 = c0 + 1;
            s[j][0] *= scale; s[j][1] *= scale;
            s[j][2] *= scale; s[j][3] *= scale;
            if (diag) {
                if (c0 > lq0) s[j][0] = -1e9f;
                if (c1 > lq0) s[j][1] = -1e9f;
                if (c0 > lq1) s[j][2] = -1e9f;
                if (c1 > lq1) s[j][3] = -1e9f;
            }
        }

        float mt0 = -1e30f, mt1 = -1e30f;
#pragma unroll
        for (int j = 0; j < 8; j++) {
            mt0 = fmaxf(mt0, fmaxf(s[j][0], s[j][1]));
            mt1 = fmaxf(mt1, fmaxf(s[j][2], s[j][3]));
        }
        mt0 = fmaxf(mt0, __shfl_xor_sync(0xffffffffu, mt0, 1));
        mt0 = fmaxf(mt0, __shfl_xor_sync(0xffffffffu, mt0, 2));
        mt1 = fmaxf(mt1, __shfl_xor_sync(0xffffffffu, mt1, 1));
        mt1 = fmaxf(mt1, __shfl_xor_sync(0xffffffffu, mt1, 2));

        float mn0 = fmaxf(m0, mt0), mn1 = fmaxf(m1, mt1);
        float al0 = __expf(m0 - mn0), al1 = __expf(m1 - mn1);
        m0 = mn0; m1 = mn1;

        float ps0 = 0.f, ps1 = 0.f;
#pragma unroll
        for (int j = 0; j < 8; j++) {
            s[j][0] = __expf(s[j][0] - mn0);
            s[j][1] = __expf(s[j][1] - mn0);
            s[j][2] = __expf(s[j][2] - mn1);
            s[j][3] = __expf(s[j][3] - mn1);
            ps0 += s[j][0] + s[j][1];
            ps1 += s[j][2] + s[j][3];
        }
        ps0 += __shfl_xor_sync(0xffffffffu, ps0, 1);
        ps0 += __shfl_xor_sync(0xffffffffu, ps0, 2);
        ps1 += __shfl_xor_sync(0xffffffffu, ps1, 1);
        ps1 += __shfl_xor_sync(0xffffffffu, ps1, 2);
        l0 = l0 * al0 + ps0;
        l1 = l1 * al1 + ps1;

#pragma unroll
        for (int j = 0; j < 8; j++) {
            o[j][0] *= al0; o[j][1] *= al0;
            o[j][2] *= al1; o[j][3] *= al1;
        }

#pragma unroll
        for (int j = 0; j < 8; j++) {
            int c0 = j*8 + cq*2;
            Pw[r*68 + c0]       = f2tf(s[j][0]);
            Pw[r*68 + c0 + 1]   = f2tf(s[j][1]);
            Pw[(r+8)*68 + c0]     = f2tf(s[j][2]);
            Pw[(r+8)*68 + c0 + 1] = f2tf(s[j][3]);
        }
        __syncwarp();

#pragma unroll
        for (int kk = 0; kk < 64; kk += 8) {
            unsigned a0 = Pw[r*68 + kk + cq];
            unsigned a1 = Pw[(r+8)*68 + kk + cq];
            unsigned a2 = Pw[r*68 + kk + cq + 4];
            unsigned a3 = Pw[(r+8)*68 + kk + cq + 4];
#pragma unroll
            for (int j = 0; j < 8; j++) {
                unsigned b0 = Vs[(kk+cq)*68 + j*8 + r];
                unsigned b1 = Vs[(kk+cq+4)*68 + j*8 + r];
                asm volatile(
                    "mma.sync.aligned.m16n8k8.row.col.f32.tf32.tf32.f32 "
                    "{%0,%1,%2,%3},{%4,%5,%6,%7},{%8,%9},{%0,%1,%2,%3};"
                    : "+f"(o[j][0]), "+f"(o[j][1]), "+f"(o[j][2]), "+f"(o[j][3])
                    : "r"(a0), "r"(a1), "r"(a2), "r"(a3), "r"(b0), "r"(b1));
            }
        }
        __syncwarp();
    }

    float inv0 = 1.f / l0, inv1 = 1.f / l1;
    size_t row0 = (tq + warp*16 + r) * (size_t)(H_*DH_) + h*DH_;
    size_t row1 = row0 + (size_t)8 * (H_*DH_);
#pragma unroll
    for (int j = 0; j < 8; j++) {
        int c0 = j*8 + cq*2;
        float2 v0; v0.x = o[j][0]*inv0; v0.y = o[j][1]*inv0;
        float2 v1; v1.x = o[j][2]*inv1; v1.y = o[j][3]*inv1;
        *(float2*)&ctx[row0 + c0] = v0;
        *(float2*)&ctx[row1 + c0] = v1;
    }
}

// ---------------- misc elementwise ----------------------------------------
__global__ void zero_cnt_k(int* c) {
    if (threadIdx.x < NR_) c[threadIdx.x] = 0;
}

// z = blockIdx.y selects slice; cntArr null => dense (cnt = T_)
__global__ void silu_batched_k(const float* __restrict__ g, const float* __restrict__ u,
                               float* __restrict__ o, const int* __restrict__ cntArr) {
    int z = blockIdx.y;
    int cnt = cntArr ? cntArr[z] : T_;
    long i = (long)blockIdx.x * blockDim.x + threadIdx.x;
    if (i >= (long)cnt * DHID_) return;
    size_t base = (size_t)z * T_ * DHID_;
    float gv = g[base + i], uv = u[base + i];
    o[base + i] = (gv / (1.f + __expf(-gv))) * uv;
}

// ---------------- gating: logits + softmax + top2 + routing ----------------
__global__ void gate_topk_k(const float* __restrict__ h2, const float* __restrict__ gw,
                            int* __restrict__ cnt, int* __restrict__ elist,
                            int* __restrict__ rt, float* __restrict__ rw) {
    int t = blockIdx.x * 8 + (threadIdx.x >> 5);
    int lane = threadIdx.x & 31;
    if (t >= T_) return;
    float acc[NR_];
#pragma unroll
    for (int e = 0; e < NR_; e++) acc[e] = 0.f;
    const float* hr = h2 + (size_t)t * D_;
    for (int d = lane; d < D_; d += 32) {
        float xv = hr[d];
        const float* g = gw + (size_t)d * NR_;
#pragma unroll
        for (int e = 0; e < NR_; e++) acc[e] += xv * g[e];
    }
#pragma unroll
    for (int e = 0; e < NR_; e++)
#pragma unroll
        for (int off = 16; off; off >>= 1)
            acc[e] += __shfl_xor_sync(0xffffffffu, acc[e], off);
    if (lane == 0) {
        int i1 = 0;
#pragma unroll
        for (int e = 1; e < NR_; e++) if (acc[e] > acc[i1]) i1 = e;
        int i2 = (i1 == 0) ? 1 : 0;
#pragma unroll
        for (int e = 0; e < NR_; e++) {
            if (e == i1 || e == i2) continue;
            if (acc[e] > acc[i2]) i2 = e;
        }
        float p2 = __expf(acc[i2] - acc[i1]);
        float inv = 1.f / (1.f + p2);
        float w1 = inv, w2 = p2 * inv;
        int pos1 = atomicAdd(&cnt[i1], 1);
        elist[i1*T_ + pos1] = t;
        int pos2 = atomicAdd(&cnt[i2], 1);
        elist[i2*T_ + pos2] = t;
        rt[t*4+0] = i1; rt[t*4+1] = pos1;
        rt[t*4+2] = i2; rt[t*4+3] = pos2;
        rw[t*2+0] = w1; rw[t*2+1] = w2;
    }
}

// ---------------- final reduce: out += shared + routed ---------------------
__global__ void reduce_k(float* __restrict__ out, const float* __restrict__ ysh,
                         const float* __restrict__ y, const int* __restrict__ rt,
                         const float* __restrict__ rw) {
    int t = blockIdx.x;
    int tid = threadIdx.x;
    int e1 = rt[t*4+0], p1 = rt[t*4+1];
    int e2 = rt[t*4+2], p2 = rt[t*4+3];
    float w1 = rw[t*2+0], w2 = rw[t*2+1];
    const float4* s0 = (const float4*)(ysh + (size_t)t * D_);
    const float4* s1 = (const float4*)(ysh + ((size_t)T_ + t) * D_);
    const float4* y1 = (const float4*)(y + ((size_t)e1*T_ + p1) * D_);
    const float4* y2 = (const float4*)(y + ((size_t)e2*T_ + p2) * D_);
    float4* op = (float4*)(out + (size_t)t * D_);
    for (int d = tid; d < D_/4; d += blockDim.x) {
        float4 o = op[d];
        float4 a = s0[d], b = s1[d], c = y1[d], e = y2[d];
        o.x += a.x + b.x + w1*c.x + w2*e.x;
        o.y += a.y + b.y + w1*c.y + w2*e.y;
        o.z += a.z + b.z + w1*c.z + w2*e.z;
        o.w += a.w + b.w + w1*c.w + w2*e.w;
        op[d] = o;
    }
}

// ---------------- launch ---------------------------------------------------
extern "C" void kernel_launch(void* const* d_in, const int* in_sizes, int n_in,
                              void* d_out, int out_size) {
    const float* x         = (const float*)d_in[0];
    const float* w_q       = (const float*)d_in[2];
    const float* w_dkv     = (const float*)d_in[3];
    const float* w_uk      = (const float*)d_in[4];
    const float* w_uv      = (const float*)d_in[5];
    const float* w_kr      = (const float*)d_in[6];
    const float* w_o       = (const float*)d_in[7];
    const float* attn_nw   = (const float*)d_in[8];
    const float* mlp_nw    = (const float*)d_in[9];
    const float* gate_w    = (const float*)d_in[10];
    const float* wr_gate   = (const float*)d_in[11];
    const float* wr_up     = (const float*)d_in[12];
    const float* wr_down   = (const float*)d_in[13];
    const float* ws_gate   = (const float*)d_in[14];
    const float* ws_up     = (const float*)d_in[15];
    const float* ws_down   = (const float*)d_in[16];
    float* out = (float*)d_out;

    float *ph, *pq, *plat, *pkc, *pv, *pkr, *pctx, *ph2;
    float *pgsh, *push, *pysh, *pgb, *pub, *py, *prw;
    int *pcnt, *pel, *prt;
    cudaGetSymbolAddress((void**)&ph,   g_h);
    cudaGetSymbolAddress((void**)&pq,   g_q);
    cudaGetSymbolAddress((void**)&plat, g_lat);
    cudaGetSymbolAddress((void**)&pkc,  g_kc);
    cudaGetSymbolAddress((void**)&pv,   g_v);
    cudaGetSymbolAddress((void**)&pkr,  g_kr);
    cudaGetSymbolAddress((void**)&pctx, g_ctx);
    cudaGetSymbolAddress((void**)&ph2,  g_h2);
    cudaGetSymbolAddress((void**)&pgsh, g_gsh);
    cudaGetSymbolAddress((void**)&push, g_ush);
    cudaGetSymbolAddress((void**)&pysh, g_ysh);
    cudaGetSymbolAddress((void**)&pgb,  g_gb);
    cudaGetSymbolAddress((void**)&pub,  g_ub);
    cudaGetSymbolAddress((void**)&py,   g_y);
    cudaGetSymbolAddress((void**)&pcnt, g_cnt);
    cudaGetSymbolAddress((void**)&pel,  g_elist);
    cudaGetSymbolAddress((void**)&prt,  g_rt);
    cudaGetSymbolAddress((void**)&prw,  g_rw);

    cudaFuncSetAttribute(flash_mma_k,
                         cudaFuncAttributeMaxDynamicSharedMemorySize, FA_SMEM_BYTES);
    cudaFuncSetAttribute(mma_multi4,
                         cudaFuncAttributeMaxDynamicSharedMemorySize, MM_SMEM_BYTES);
    cudaFuncSetAttribute(mma_gu_routed,
                         cudaFuncAttributeMaxDynamicSharedMemorySize, MM_SMEM_BYTES);
    cudaFuncSetAttribute(mma_down_routed,
                         cudaFuncAttributeMaxDynamicSharedMemorySize, MM_SMEM_BYTES);
    cudaFuncSetAttribute(mma_down_shared,
                         cudaFuncAttributeMaxDynamicSharedMemorySize, MM_SMEM_BYTES);

    // 1) h = rmsnorm(x)
    rmsnorm_k<<<T_, 256>>>(x, attn_nw, ph);

    // 2) fused projections: w_q (16 tiles) + w_dkv (4) + w_kr (1)
    mma_multi4<<<dim3(21, T_/128), 256, MM_SMEM_BYTES>>>(ph, D_,
        w_q,   pq,   H_*QDIM_, 16,
        w_dkv, plat, DL_,      4,
        w_kr,  pkr,  DR_,      1,
        nullptr, nullptr, 0, 0, nullptr);

    // 3) RoPE
    {
        int n = T_*H_*32 + T_*32;
        rope_k<<<(n + 255)/256, 256>>>(pq, pkr);
    }

    // 4) fused k_c + v up-projections
    mma_multi4<<<dim3(16, T_/128), 256, MM_SMEM_BYTES>>>(plat, DL_,
        w_uk, pkc, H_*DH_, 8,
        w_uv, pv,  H_*DH_, 8,
        nullptr, nullptr, 0, 0,
        nullptr, nullptr, 0, 0, nullptr);

    // 5) attention
    flash_mma_k<<<dim3(S_/64, B_*H_), 128, FA_SMEM_BYTES>>>(pq, pkc, pkr, pv, pctx);

    // 6) out = x + ctx @ w_o
    mma_multi4<<<dim3(8, T_/128), 256, MM_SMEM_BYTES>>>(pctx, H_*DH_,
        w_o, out, D_, 8,
        nullptr, nullptr, 0, 0,
        nullptr, nullptr, 0, 0,
        nullptr, nullptr, 0, 0, x);

    // 7) h2 = rmsnorm(out)
    rmsnorm_k<<<T_, 256>>>(out, mlp_nw, ph2);

    // 8) routing
    zero_cnt_k<<<1, 32>>>(pcnt);
    gate_topk_k<<<T_/8, 256>>>(ph2, gate_w, pcnt, pel, prt, prw);

    // 9) shared experts: gate+up (both experts) in one launch
    mma_multi4<<<dim3(16, T_/128), 256, MM_SMEM_BYTES>>>(ph2, D_,
        ws_gate,              pgsh,               DHID_, 4,
        ws_up,                push,               DHID_, 4,
        ws_gate + (size_t)D_*DHID_, pgsh + (size_t)T_*DHID_, DHID_, 4,
        ws_up   + (size_t)D_*DHID_, push + (size_t)T_*DHID_, DHID_, 4,
        nullptr);
    silu_batched_k<<<dim3((T_*DHID_ + 255)/256, NS_), 256>>>(pgsh, push, pgsh, nullptr);
    mma_down_shared<<<dim3(D_/128, T_/128, NS_), 256, MM_SMEM_BYTES>>>(pgsh, ws_down, pysh);

    // 10) routed experts: batched gate+up, silu, down (compact outputs)
    mma_gu_routed<<<dim3(2*DHID_/128, T_/128, NR_), 256, MM_SMEM_BYTES>>>(ph2, wr_gate, wr_up,
                                                           pgb, pub, pel, pcnt);
    silu_batched_k<<<dim3((T_*DHID_ + 255)/256, NR_), 256>>>(pgb, pub, pgb, pcnt);
    mma_down_routed<<<dim3(D_/128, T_/128, NR_), 256, MM_SMEM_BYTES>>>(pgb, wr_down, py, pcnt);

    // 11) deterministic combine
    reduce_k<<<T_, 256>>>(out, pysh, py, prt, prw);
}